// round 4
// baseline (speedup 1.0000x reference)
#include <cuda_runtime.h>
#include <stdint.h>

#define R_TOT 524288
#define NE    33554432
#define NTILE 16384          // R_TOT / 32 rows per macro-tile

struct Params {
    float s_x, zp_x, s_h, zp_h, s_c, zp_c, s_cat, zp_cat;
    float alpha[4];
    float bdq[256];
    int   zpw_i[4], zpc_i;
    float sG[4], zpG[4], sA[4], zpA[4];
    float s_fc, zp_fc, s_ic, zp_ic, s_cn, zp_cn, s_t, zp_t, s_hn, zp_hn;
};

__device__ Params   g_p;
__device__ unsigned g_mm[22];            // 11 (min,max) encoded-float slots
__device__ int8_t   g_wq[256 * 128];     // quantized weight codes
__device__ int      g_const[256];        // per-output zero-point correction
__device__ uint32_t g_catf[16777216];    // cat codes as raw MMA A-fragments (64 MB)
__device__ int8_t   g_act[4][NE];        // i,f,o,cg activation codes
__device__ int8_t   g_cq[NE];            // c_prev codes
__device__ int8_t   g_tq[NE];            // tanh(c_next) codes

// ---------- helpers ----------
__device__ __forceinline__ unsigned fenc(float f) {
    unsigned u = __float_as_uint(f);
    return (u & 0x80000000u) ? ~u : (u | 0x80000000u);
}
__device__ __forceinline__ float fdec(unsigned u) {
    return __uint_as_float((u & 0x80000000u) ? (u & 0x7fffffffu) : ~u);
}
__device__ __forceinline__ float quant_q(float v, float s, float zp) {
    float q = rintf(__fdiv_rn(v, s)) + zp;
    return fminf(fmaxf(q, -128.f), 127.f);
}
__device__ __forceinline__ float fqv(float v, float s, float zp) {
    return __fmul_rn(quant_q(v, s, zp) - zp, s);
}
__device__ __forceinline__ void mkparams(float mnr, float mxr, float* s, float* zp) {
    float mn = fminf(mnr, 0.f), mx = fmaxf(mxr, 0.f);
    float sc = fmaxf(__fdiv_rn(mx - mn, 255.f), 1e-8f);
    float z  = rintf(-128.f - __fdiv_rn(mn, sc));
    *s = sc; *zp = fminf(fmaxf(z, -128.f), 127.f);
}
__device__ __forceinline__ float hsig(float v) {
    return fminf(fmaxf(__fadd_rn(__fdiv_rn(v, 6.f), 0.5f), 0.f), 1.f);
}
__device__ __forceinline__ float htanh(float v) { return fminf(fmaxf(v, -1.f), 1.f); }

__device__ __forceinline__ void block_minmax(float mn, float mx, unsigned* gmin, unsigned* gmax) {
    #pragma unroll
    for (int o = 16; o; o >>= 1) {
        mn = fminf(mn, __shfl_xor_sync(0xffffffffu, mn, o));
        mx = fmaxf(mx, __shfl_xor_sync(0xffffffffu, mx, o));
    }
    __shared__ float smn[8], smx[8];
    int w = threadIdx.x >> 5, nw = blockDim.x >> 5;
    __syncthreads();
    if ((threadIdx.x & 31) == 0) { smn[w] = mn; smx[w] = mx; }
    __syncthreads();
    if (threadIdx.x == 0) {
        for (int i = 1; i < nw; i++) { mn = fminf(mn, smn[i]); mx = fmaxf(mx, smx[i]); }
        atomicMin(gmin, fenc(mn));
        atomicMax(gmax, fenc(mx));
    }
    __syncthreads();
}

__device__ __forceinline__ float2 block_reduce_pair(float mn, float mx) {
    #pragma unroll
    for (int o = 16; o; o >>= 1) {
        mn = fminf(mn, __shfl_xor_sync(0xffffffffu, mn, o));
        mx = fmaxf(mx, __shfl_xor_sync(0xffffffffu, mx, o));
    }
    __shared__ float smn[8], smx[8];
    __shared__ float2 res;
    int w = threadIdx.x >> 5, nw = blockDim.x >> 5;
    __syncthreads();
    if ((threadIdx.x & 31) == 0) { smn[w] = mn; smx[w] = mx; }
    __syncthreads();
    if (threadIdx.x == 0) {
        for (int i = 1; i < nw; i++) { mn = fminf(mn, smn[i]); mx = fmaxf(mx, smx[i]); }
        res = make_float2(mn, mx);
    }
    __syncthreads();
    return res;
}

__device__ __forceinline__ void mma_s8(int* c, uint32_t a0, uint32_t a1, uint32_t a2,
                                       uint32_t a3, uint32_t b0, uint32_t b1) {
    asm volatile(
        "mma.sync.aligned.m16n8k32.row.col.s32.s8.s8.s32 "
        "{%0,%1,%2,%3}, {%4,%5,%6,%7}, {%8,%9}, {%0,%1,%2,%3};\n"
        : "+r"(c[0]), "+r"(c[1]), "+r"(c[2]), "+r"(c[3])
        : "r"(a0), "r"(a1), "r"(a2), "r"(a3), "r"(b0), "r"(b1));
}

// ---------- K0: reset reduction slots ----------
__global__ void k_init() {
    int t = threadIdx.x;
    if (t < 11) { g_mm[2 * t] = fenc(1e30f); g_mm[2 * t + 1] = fenc(-1e30f); }
}

// ---------- K1: minmax of x, h, c ----------
__global__ void k_minmax3(const float* __restrict__ x, const float* __restrict__ h,
                          const float* __restrict__ c) {
    const float* arrs[3] = {x, h, c};
    for (int a = 0; a < 3; a++) {
        float mn = 1e30f, mx = -1e30f;
        const float4* p = (const float4*)arrs[a];
        for (long i = blockIdx.x * blockDim.x + threadIdx.x; i < NE / 4;
             i += (long)gridDim.x * blockDim.x) {
            float4 v = p[i];
            mn = fminf(fminf(fminf(mn, v.x), v.y), fminf(v.z, v.w));
            mx = fmaxf(fmaxf(fmaxf(mx, v.x), v.y), fmaxf(v.z, v.w));
        }
        block_minmax(mn, mx, &g_mm[2 * a], &g_mm[2 * a + 1]);
    }
}

// ---------- K2: scalar params + weight/bias quantization (1 block) ----------
__global__ void k_params(const float* __restrict__ Wi, const float* __restrict__ bi,
                         const float* __restrict__ Wf, const float* __restrict__ bf,
                         const float* __restrict__ Wo, const float* __restrict__ bo,
                         const float* __restrict__ Wc, const float* __restrict__ bc) {
    __shared__ float sw, zw, sb, zb;
    int t = threadIdx.x;
    if (t == 0) {
        mkparams(fdec(g_mm[0]), fdec(g_mm[1]), &g_p.s_x, &g_p.zp_x);
        mkparams(fdec(g_mm[2]), fdec(g_mm[3]), &g_p.s_h, &g_p.zp_h);
        mkparams(fdec(g_mm[4]), fdec(g_mm[5]), &g_p.s_c, &g_p.zp_c);
        float xlo = fqv(fdec(g_mm[0]), g_p.s_x, g_p.zp_x);
        float xhi = fqv(fdec(g_mm[1]), g_p.s_x, g_p.zp_x);
        float hlo = fqv(fdec(g_mm[2]), g_p.s_h, g_p.zp_h);
        float hhi = fqv(fdec(g_mm[3]), g_p.s_h, g_p.zp_h);
        mkparams(fminf(xlo, hlo), fmaxf(xhi, hhi), &g_p.s_cat, &g_p.zp_cat);
        g_p.zpc_i = (int)g_p.zp_cat;
    }
    __syncthreads();
    const float* Wg[4] = {Wi, Wf, Wo, Wc};
    const float* bg[4] = {bi, bf, bo, bc};
    for (int g = 0; g < 4; g++) {
        float mn = 1e30f, mx = -1e30f;
        for (int i = t; i < 8192; i += 256) {
            float v = Wg[g][i];
            mn = fminf(mn, v); mx = fmaxf(mx, v);
        }
        float2 m = block_reduce_pair(mn, mx);
        if (t == 0) {
            mkparams(m.x, m.y, &sw, &zw);
            g_p.alpha[g] = __fmul_rn(g_p.s_cat, sw);
            g_p.zpw_i[g] = (int)zw;
        }
        __syncthreads();
        for (int i = t; i < 8192; i += 256)
            g_wq[g * 8192 + i] = (int8_t)(int)quant_q(Wg[g][i], sw, zw);
        mn = (t < 64) ? bg[g][t] : 1e30f;
        mx = (t < 64) ? bg[g][t] : -1e30f;
        m = block_reduce_pair(mn, mx);
        if (t == 0) mkparams(m.x, m.y, &sb, &zb);
        __syncthreads();
        if (t < 64) g_p.bdq[g * 64 + t] = fqv(bg[g][t], sb, zb);
        __syncthreads();
    }
    {
        int s = 0;
        const int8_t* wr = &g_wq[t * 128];
        for (int k = 0; k < 128; k++) s += wr[k];
        int g = t >> 6;
        g_const[t] = -g_p.zpc_i * s + 128 * g_p.zpc_i * g_p.zpw_i[g];
    }
}

// ---------- K2b: quantize c_prev to codes ----------
__global__ void k_quantc(const float* __restrict__ c) {
    float s = g_p.s_c, z = g_p.zp_c;
    for (long i = blockIdx.x * blockDim.x + threadIdx.x; i < NE / 4;
         i += (long)gridDim.x * blockDim.x) {
        float4 v = ((const float4*)c)[i];
        char4 q;
        q.x = (int8_t)(int)quant_q(v.x, s, z);
        q.y = (int8_t)(int)quant_q(v.y, s, z);
        q.z = (int8_t)(int)quant_q(v.z, s, z);
        q.w = (int8_t)(int)quant_q(v.w, s, z);
        ((char4*)g_cq)[i] = q;
    }
}

// Quantize one float4 of cat at (row, col..col+3) to packed codes
__device__ __forceinline__ uint32_t packq(const float4* __restrict__ X4,
                                          const float4* __restrict__ H4,
                                          long row, int col,
                                          float sx, float zx, float sh, float zh,
                                          float sc, float zc) {
    float4 v; float s0, z0;
    if (col < 64) { v = X4[row * 16 + (col >> 2)]; s0 = sx; z0 = zx; }
    else          { v = H4[row * 16 + ((col - 64) >> 2)]; s0 = sh; z0 = zh; }
    int q0 = (int)quant_q(fqv(v.x, s0, z0), sc, zc);
    int q1 = (int)quant_q(fqv(v.y, s0, z0), sc, zc);
    int q2 = (int)quant_q(fqv(v.z, s0, z0), sc, zc);
    int q3 = (int)quant_q(fqv(v.w, s0, z0), sc, zc);
    return (uint32_t)(q0 & 255) | ((uint32_t)(q1 & 255) << 8) |
           ((uint32_t)(q2 & 255) << 16) | ((uint32_t)(q3 & 255) << 24);
}

#define ONEB 0x01010101

// ---------- K3a: pass A — quantize cat, store fragments, MMA, gate minmax ----------
__global__ void __launch_bounds__(256) k_gemmA(const float* __restrict__ X,
                                               const float* __restrict__ H) {
    __shared__ uint32_t asm_[2][16][32];
    int t = threadIdx.x, lane = t & 31, w = t >> 5;
    int rg = w & 1, cg = w >> 1;            // cg = gate
    int colbase = cg * 64;
    // B fragments: 8 n-tiles x 4 k-chunks x 2 regs
    uint32_t B[8][4][2];
    #pragma unroll
    for (int nt = 0; nt < 8; nt++)
        #pragma unroll
        for (int kc = 0; kc < 4; kc++) {
            int col = colbase + nt * 8 + (lane >> 2);
            B[nt][kc][0] = *(const uint32_t*)&g_wq[col * 128 + kc * 32 + 4 * (lane & 3)];
            B[nt][kc][1] = *(const uint32_t*)&g_wq[col * 128 + kc * 32 + 4 * (lane & 3) + 16];
        }
    int   gco0[8], gco1[8];
    float gb0[8], gb1[8];
    #pragma unroll
    for (int nt = 0; nt < 8; nt++) {
        int cA = colbase + nt * 8 + 2 * (lane & 3);
        gco0[nt] = g_const[cA];     gco1[nt] = g_const[cA + 1];
        gb0[nt]  = g_p.bdq[cA];     gb1[nt]  = g_p.bdq[cA + 1];
    }
    float al = g_p.alpha[cg];
    int   zw = g_p.zpw_i[cg];
    float sx = g_p.s_x, zx = g_p.zp_x, sh = g_p.s_h, zh = g_p.zp_h;
    float sc = g_p.s_cat, zc = g_p.zp_cat;
    const float4* X4 = (const float4*)X;
    const float4* H4 = (const float4*)H;
    float mn = 1e30f, mx = -1e30f;

    for (int tile = blockIdx.x; tile < NTILE; tile += gridDim.x) {
        long r0 = (long)tile * 32;
        uint32_t A[16];
        if (w < 2) {
            long rb = r0 + w * 16 + (lane >> 2);
            #pragma unroll
            for (int kc = 0; kc < 4; kc++) {
                int k0 = kc * 32 + 4 * (lane & 3);
                A[kc * 4 + 0] = packq(X4, H4, rb,     k0,      sx, zx, sh, zh, sc, zc);
                A[kc * 4 + 1] = packq(X4, H4, rb + 8, k0,      sx, zx, sh, zh, sc, zc);
                A[kc * 4 + 2] = packq(X4, H4, rb,     k0 + 16, sx, zx, sh, zh, sc, zc);
                A[kc * 4 + 3] = packq(X4, H4, rb + 8, k0 + 16, sx, zx, sh, zh, sc, zc);
            }
            size_t gbase = ((size_t)tile * 2 + w) * 512 + lane;
            #pragma unroll
            for (int r = 0; r < 16; r++) {
                asm_[w][r][lane] = A[r];
                g_catf[gbase + r * 32] = A[r];
            }
        }
        __syncthreads();
        if (w >= 2) {
            #pragma unroll
            for (int r = 0; r < 16; r++) A[r] = asm_[rg][r][lane];
        }
        int rs_lo = 0, rs_hi = 0;
        #pragma unroll
        for (int kc = 0; kc < 4; kc++) {
            rs_lo = __dp4a((int)A[kc * 4 + 0], ONEB, rs_lo);
            rs_lo = __dp4a((int)A[kc * 4 + 2], ONEB, rs_lo);
            rs_hi = __dp4a((int)A[kc * 4 + 1], ONEB, rs_hi);
            rs_hi = __dp4a((int)A[kc * 4 + 3], ONEB, rs_hi);
        }
        rs_lo += __shfl_xor_sync(0xffffffffu, rs_lo, 1);
        rs_lo += __shfl_xor_sync(0xffffffffu, rs_lo, 2);
        rs_hi += __shfl_xor_sync(0xffffffffu, rs_hi, 1);
        rs_hi += __shfl_xor_sync(0xffffffffu, rs_hi, 2);

        #pragma unroll
        for (int nt = 0; nt < 8; nt++) {
            int acc[4] = {0, 0, 0, 0};
            #pragma unroll
            for (int kc = 0; kc < 4; kc++)
                mma_s8(acc, A[kc * 4 + 0], A[kc * 4 + 1], A[kc * 4 + 2], A[kc * 4 + 3],
                       B[nt][kc][0], B[nt][kc][1]);
            float G00 = __fadd_rn(__fmul_rn((float)(acc[0] - zw * rs_lo + gco0[nt]), al), gb0[nt]);
            float G01 = __fadd_rn(__fmul_rn((float)(acc[1] - zw * rs_lo + gco1[nt]), al), gb1[nt]);
            float G10 = __fadd_rn(__fmul_rn((float)(acc[2] - zw * rs_hi + gco0[nt]), al), gb0[nt]);
            float G11 = __fadd_rn(__fmul_rn((float)(acc[3] - zw * rs_hi + gco1[nt]), al), gb1[nt]);
            mn = fminf(mn, fminf(fminf(G00, G01), fminf(G10, G11)));
            mx = fmaxf(mx, fmaxf(fmaxf(G00, G01), fmaxf(G10, G11)));
        }
        __syncthreads();
    }
    #pragma unroll
    for (int o = 16; o; o >>= 1) {
        mn = fminf(mn, __shfl_xor_sync(0xffffffffu, mn, o));
        mx = fmaxf(mx, __shfl_xor_sync(0xffffffffu, mx, o));
    }
    if (lane == 0) {
        atomicMin(&g_mm[6 + 2 * cg], fenc(mn));
        atomicMax(&g_mm[7 + 2 * cg], fenc(mx));
    }
}

// ---------- K4: gate + activation params ----------
__global__ void k_p2() {
    for (int g = 0; g < 4; g++) {
        float mn = fdec(g_mm[6 + 2 * g]), mx = fdec(g_mm[7 + 2 * g]);
        mkparams(mn, mx, &g_p.sG[g], &g_p.zpG[g]);
        float lo = fqv(mn, g_p.sG[g], g_p.zpG[g]);
        float hi = fqv(mx, g_p.sG[g], g_p.zpG[g]);
        float amin, amax;
        if (g < 3) { amin = hsig(lo); amax = hsig(hi); }
        else       { amin = htanh(lo); amax = htanh(hi); }
        mkparams(amin, amax, &g_p.sA[g], &g_p.zpA[g]);
    }
}

// ---------- K3b: pass B — MMA from stored fragments, activations, fc/ic minmax ----------
#define APAD 264
__global__ void __launch_bounds__(256) k_gemmB() {
    __shared__ int8_t acts[32][APAD];
    int t = threadIdx.x, lane = t & 31, w = t >> 5;
    int rg = w & 1, cg = w >> 1;
    int colbase = cg * 64;
    uint32_t B[8][4][2];
    #pragma unroll
    for (int nt = 0; nt < 8; nt++)
        #pragma unroll
        for (int kc = 0; kc < 4; kc++) {
            int col = colbase + nt * 8 + (lane >> 2);
            B[nt][kc][0] = *(const uint32_t*)&g_wq[col * 128 + kc * 32 + 4 * (lane & 3)];
            B[nt][kc][1] = *(const uint32_t*)&g_wq[col * 128 + kc * 32 + 4 * (lane & 3) + 16];
        }
    int   gco0[8], gco1[8];
    float gb0[8], gb1[8];
    #pragma unroll
    for (int nt = 0; nt < 8; nt++) {
        int cA = colbase + nt * 8 + 2 * (lane & 3);
        gco0[nt] = g_const[cA];     gco1[nt] = g_const[cA + 1];
        gb0[nt]  = g_p.bdq[cA];     gb1[nt]  = g_p.bdq[cA + 1];
    }
    float al = g_p.alpha[cg];
    int   zw = g_p.zpw_i[cg];
    float sGg = g_p.sG[cg], zGg = g_p.zpG[cg], sAg = g_p.sA[cg], zAg = g_p.zpA[cg];
    float sAi = g_p.sA[0], zAi = g_p.zpA[0], sAf = g_p.sA[1], zAf = g_p.zpA[1];
    float sAc = g_p.sA[3], zAc = g_p.zpA[3];
    float scc = g_p.s_c, zcc = g_p.zp_c;
    int rlo = rg * 16 + (lane >> 2);        // local row of C frag (lo half)
    float mn1 = 1e30f, mx1 = -1e30f, mn2 = 1e30f, mx2 = -1e30f;

    for (int tile = blockIdx.x; tile < NTILE; tile += gridDim.x) {
        uint32_t A[16];
        size_t gbase = ((size_t)tile * 2 + rg) * 512 + lane;
        #pragma unroll
        for (int r = 0; r < 16; r++) A[r] = g_catf[gbase + r * 32];

        int rs_lo = 0, rs_hi = 0;
        #pragma unroll
        for (int kc = 0; kc < 4; kc++) {
            rs_lo = __dp4a((int)A[kc * 4 + 0], ONEB, rs_lo);
            rs_lo = __dp4a((int)A[kc * 4 + 2], ONEB, rs_lo);
            rs_hi = __dp4a((int)A[kc * 4 + 1], ONEB, rs_hi);
            rs_hi = __dp4a((int)A[kc * 4 + 3], ONEB, rs_hi);
        }
        rs_lo += __shfl_xor_sync(0xffffffffu, rs_lo, 1);
        rs_lo += __shfl_xor_sync(0xffffffffu, rs_lo, 2);
        rs_hi += __shfl_xor_sync(0xffffffffu, rs_hi, 1);
        rs_hi += __shfl_xor_sync(0xffffffffu, rs_hi, 2);

        #pragma unroll
        for (int nt = 0; nt < 8; nt++) {
            int acc[4] = {0, 0, 0, 0};
            #pragma unroll
            for (int kc = 0; kc < 4; kc++)
                mma_s8(acc, A[kc * 4 + 0], A[kc * 4 + 1], A[kc * 4 + 2], A[kc * 4 + 3],
                       B[nt][kc][0], B[nt][kc][1]);
            int cA = colbase + nt * 8 + 2 * (lane & 3);
            float G00 = __fadd_rn(__fmul_rn((float)(acc[0] - zw * rs_lo + gco0[nt]), al), gb0[nt]);
            float G01 = __fadd_rn(__fmul_rn((float)(acc[1] - zw * rs_lo + gco1[nt]), al), gb1[nt]);
            float G10 = __fadd_rn(__fmul_rn((float)(acc[2] - zw * rs_hi + gco0[nt]), al), gb0[nt]);
            float G11 = __fadd_rn(__fmul_rn((float)(acc[3] - zw * rs_hi + gco1[nt]), al), gb1[nt]);
            float v00 = fqv(G00, sGg, zGg), v01 = fqv(G01, sGg, zGg);
            float v10 = fqv(G10, sGg, zGg), v11 = fqv(G11, sGg, zGg);
            float a00, a01, a10, a11;
            if (cg < 3) { a00 = hsig(v00); a01 = hsig(v01); a10 = hsig(v10); a11 = hsig(v11); }
            else        { a00 = htanh(v00); a01 = htanh(v01); a10 = htanh(v10); a11 = htanh(v11); }
            char2 lo2, hi2;
            lo2.x = (int8_t)(int)quant_q(a00, sAg, zAg);
            lo2.y = (int8_t)(int)quant_q(a01, sAg, zAg);
            hi2.x = (int8_t)(int)quant_q(a10, sAg, zAg);
            hi2.y = (int8_t)(int)quant_q(a11, sAg, zAg);
            *(char2*)&acts[rlo][cA]     = lo2;
            *(char2*)&acts[rlo + 8][cA] = hi2;
        }
        __syncthreads();

        // store act codes to global (coalesced), 2048 words / 256 threads = 8 each
        #pragma unroll
        for (int q = 0; q < 8; q++) {
            int w_ = t + q * 256;
            int g  = w_ >> 9, rem = w_ & 511, row = rem >> 4, wo = rem & 15;
            uint32_t val = *(const uint32_t*)&acts[row][g * 64 + wo * 4];
            *(uint32_t*)&g_act[g][((size_t)tile * 32 + row) * 64 + wo * 4] = val;
        }
        // fc / ic minmax: thread handles row = t>>3, 8 cols at h0 = (t&7)*8
        {
            int row = t >> 3, h0 = (t & 7) * 8;
            uint2 ci = *(const uint2*)&acts[row][0 * 64 + h0];
            uint2 cf = *(const uint2*)&acts[row][1 * 64 + h0];
            uint2 cgc = *(const uint2*)&acts[row][3 * 64 + h0];
            uint2 ccq = *(const uint2*)&g_cq[((size_t)tile * 32 + row) * 64 + h0];
            #pragma unroll
            for (int half = 0; half < 2; half++) {
                uint32_t wi = half ? ci.y : ci.x;
                uint32_t wf = half ? cf.y : cf.x;
                uint32_t wg = half ? cgc.y : cgc.x;
                uint32_t wc = half ? ccq.y : ccq.x;
                #pragma unroll
                for (int b = 0; b < 4; b++) {
                    int qi = (int)(int8_t)(wi >> (8 * b));
                    int qf = (int)(int8_t)(wf >> (8 * b));
                    int qg = (int)(int8_t)(wg >> (8 * b));
                    int qc = (int)(int8_t)(wc >> (8 * b));
                    float fv = __fmul_rn((float)qf - zAf, sAf);
                    float iv = __fmul_rn((float)qi - zAi, sAi);
                    float gv = __fmul_rn((float)qg - zAc, sAc);
                    float cd = __fmul_rn((float)qc - zcc, scc);
                    float fc = __fmul_rn(fv, cd);
                    float ic = __fmul_rn(iv, gv);
                    mn1 = fminf(mn1, fc); mx1 = fmaxf(mx1, fc);
                    mn2 = fminf(mn2, ic); mx2 = fmaxf(mx2, ic);
                }
            }
        }
        __syncthreads();
    }
    block_minmax(mn1, mx1, &g_mm[14], &g_mm[15]);
    block_minmax(mn2, mx2, &g_mm[16], &g_mm[17]);
}

// ---------- K6 ----------
__global__ void k_p3() {
    mkparams(fdec(g_mm[14]), fdec(g_mm[15]), &g_p.s_fc, &g_p.zp_fc);
    mkparams(fdec(g_mm[16]), fdec(g_mm[17]), &g_p.s_ic, &g_p.zp_ic);
}

// ---------- K7: minmax of fq(fc)+fq(ic) ----------
__global__ void k_pre() {
    float sAi = g_p.sA[0], zAi = g_p.zpA[0], sAf = g_p.sA[1], zAf = g_p.zpA[1];
    float sAg = g_p.sA[3], zAg = g_p.zpA[3], scc = g_p.s_c, zcc = g_p.zp_c;
    float sfc = g_p.s_fc, zfc = g_p.zp_fc, sic = g_p.s_ic, zic = g_p.zp_ic;
    float mn = 1e30f, mx = -1e30f;
    for (long i = blockIdx.x * blockDim.x + threadIdx.x; i < NE / 4;
         i += (long)gridDim.x * blockDim.x) {
        char4 qi = ((const char4*)g_act[0])[i];
        char4 qf = ((const char4*)g_act[1])[i];
        char4 qg = ((const char4*)g_act[3])[i];
        char4 qc = ((const char4*)g_cq)[i];
        int ii[4] = {qi.x, qi.y, qi.z, qi.w}, ff[4] = {qf.x, qf.y, qf.z, qf.w};
        int gg[4] = {qg.x, qg.y, qg.z, qg.w}, cc[4] = {qc.x, qc.y, qc.z, qc.w};
        #pragma unroll
        for (int j = 0; j < 4; j++) {
            float fv = __fmul_rn((float)ff[j] - zAf, sAf);
            float iv = __fmul_rn((float)ii[j] - zAi, sAi);
            float gv = __fmul_rn((float)gg[j] - zAg, sAg);
            float cd = __fmul_rn((float)cc[j] - zcc, scc);
            float fcv = fqv(__fmul_rn(fv, cd), sfc, zfc);
            float icv = fqv(__fmul_rn(iv, gv), sic, zic);
            float pre = __fadd_rn(fcv, icv);
            mn = fminf(mn, pre); mx = fmaxf(mx, pre);
        }
    }
    block_minmax(mn, mx, &g_mm[18], &g_mm[19]);
}

// ---------- K8 ----------
__global__ void k_p4() {
    float mn = fdec(g_mm[18]), mx = fdec(g_mm[19]);
    mkparams(mn, mx, &g_p.s_cn, &g_p.zp_cn);
    float lo = htanh(fqv(mn, g_p.s_cn, g_p.zp_cn));
    float hi = htanh(fqv(mx, g_p.s_cn, g_p.zp_cn));
    mkparams(lo, hi, &g_p.s_t, &g_p.zp_t);
}

// ---------- K9: write c_next, store t codes, minmax(o*t) ----------
__global__ void k_cnext(float* __restrict__ out_c) {
    float sAi = g_p.sA[0], zAi = g_p.zpA[0], sAf = g_p.sA[1], zAf = g_p.zpA[1];
    float sAo = g_p.sA[2], zAo = g_p.zpA[2], sAg = g_p.sA[3], zAg = g_p.zpA[3];
    float scc = g_p.s_c, zcc = g_p.zp_c;
    float sfc = g_p.s_fc, zfc = g_p.zp_fc, sic = g_p.s_ic, zic = g_p.zp_ic;
    float scn = g_p.s_cn, zcn = g_p.zp_cn, st = g_p.s_t, zt = g_p.zp_t;
    float mn = 1e30f, mx = -1e30f;
    for (long i = blockIdx.x * blockDim.x + threadIdx.x; i < NE / 4;
         i += (long)gridDim.x * blockDim.x) {
        char4 qi = ((const char4*)g_act[0])[i];
        char4 qf = ((const char4*)g_act[1])[i];
        char4 qo = ((const char4*)g_act[2])[i];
        char4 qg = ((const char4*)g_act[3])[i];
        char4 qc = ((const char4*)g_cq)[i];
        int ii[4] = {qi.x, qi.y, qi.z, qi.w}, ff[4] = {qf.x, qf.y, qf.z, qf.w};
        int oo[4] = {qo.x, qo.y, qo.z, qo.w}, gg[4] = {qg.x, qg.y, qg.z, qg.w};
        int cc[4] = {qc.x, qc.y, qc.z, qc.w};
        float4 outc;
        float* oc = (float*)&outc;
        char4 tq4;
        int8_t* tqq = (int8_t*)&tq4;
        #pragma unroll
        for (int j = 0; j < 4; j++) {
            float fv = __fmul_rn((float)ff[j] - zAf, sAf);
            float iv = __fmul_rn((float)ii[j] - zAi, sAi);
            float gv = __fmul_rn((float)gg[j] - zAg, sAg);
            float cd = __fmul_rn((float)cc[j] - zcc, scc);
            float fcv = fqv(__fmul_rn(fv, cd), sfc, zfc);
            float icv = fqv(__fmul_rn(iv, gv), sic, zic);
            float pre = __fadd_rn(fcv, icv);
            float cn = fqv(pre, scn, zcn);
            oc[j] = cn;
            int tcode = (int)quant_q(htanh(cn), st, zt);
            tqq[j] = (int8_t)tcode;
            float tv = __fmul_rn((float)tcode - zt, st);
            float ov = __fmul_rn((float)oo[j] - zAo, sAo);
            float hp = __fmul_rn(ov, tv);
            mn = fminf(mn, hp); mx = fmaxf(mx, hp);
        }
        ((float4*)out_c)[i] = outc;
        ((char4*)g_tq)[i] = tq4;
    }
    block_minmax(mn, mx, &g_mm[20], &g_mm[21]);
}

// ---------- K10 ----------
__global__ void k_p5() {
    mkparams(fdec(g_mm[20]), fdec(g_mm[21]), &g_p.s_hn, &g_p.zp_hn);
}

// ---------- K11: h_next ----------
__global__ void k_hnext(float* __restrict__ out_h) {
    float sAo = g_p.sA[2], zAo = g_p.zpA[2], st = g_p.s_t, zt = g_p.zp_t;
    float shn = g_p.s_hn, zhn = g_p.zp_hn;
    for (long i = blockIdx.x * blockDim.x + threadIdx.x; i < NE / 4;
         i += (long)gridDim.x * blockDim.x) {
        char4 qo = ((const char4*)g_act[2])[i];
        char4 qt = ((const char4*)g_tq)[i];
        int oo[4] = {qo.x, qo.y, qo.z, qo.w}, tt[4] = {qt.x, qt.y, qt.z, qt.w};
        float4 outh;
        float* oh = (float*)&outh;
        #pragma unroll
        for (int j = 0; j < 4; j++) {
            float ov = __fmul_rn((float)oo[j] - zAo, sAo);
            float tv = __fmul_rn((float)tt[j] - zt, st);
            oh[j] = fqv(__fmul_rn(ov, tv), shn, zhn);
        }
        ((float4*)out_h)[i] = outh;
    }
}

extern "C" void kernel_launch(void* const* d_in, const int* in_sizes, int n_in,
                              void* d_out, int out_size) {
    const float* x  = (const float*)d_in[0];
    const float* h  = (const float*)d_in[1];
    const float* c  = (const float*)d_in[2];
    const float* Wi = (const float*)d_in[3];
    const float* bi = (const float*)d_in[4];
    const float* Wf = (const float*)d_in[5];
    const float* bf = (const float*)d_in[6];
    const float* Wo = (const float*)d_in[7];
    const float* bo = (const float*)d_in[8];
    const float* Wc = (const float*)d_in[9];
    const float* bc = (const float*)d_in[10];
    float* out_h = (float*)d_out;
    float* out_c = (float*)d_out + NE;

    k_init<<<1, 32>>>();
    k_minmax3<<<2048, 256>>>(x, h, c);
    k_params<<<1, 256>>>(Wi, bi, Wf, bf, Wo, bo, Wc, bc);
    k_quantc<<<4096, 256>>>(c);
    k_gemmA<<<2048, 256>>>(x, h);
    k_p2<<<1, 1>>>();
    k_gemmB<<<2048, 256>>>();
    k_p3<<<1, 1>>>();
    k_pre<<<8192, 256>>>();
    k_p4<<<1, 1>>>();
    k_cnext<<<8192, 256>>>(out_c);
    k_p5<<<1, 1>>>();
    k_hnext<<<8192, 256>>>(out_h);
}

// round 5
// speedup vs baseline: 3.2361x; 3.2361x over previous
#include <cuda_runtime.h>
#include <stdint.h>

#define R_TOT 524288
#define NE    33554432

struct Params {
    float s_x, zp_x, s_h, zp_h, s_c, zp_c, s_cat, zp_cat;
    float alpha[4];
    float bdq[256];
    int   zpw_i[4], zpc_i;
    float sG[4], zpG[4], sA[4], zpA[4];
    float s_fc, zp_fc, s_ic, zp_ic, s_cn, zp_cn, s_t, zp_t, s_hn, zp_hn;
};

__device__ Params   g_p;
__device__ unsigned g_mm[22];            // 11 (min,max) encoded-float slots
__device__ int8_t   g_wq[256 * 128];     // quantized weight codes
__device__ int      g_const[256];        // per-output zero-point correction
__device__ uint32_t g_catq[R_TOT * 32];  // packed cat codes (64 MB)
__device__ int      g_rowsum[R_TOT];     // per-row code sums (2 MB)
__device__ int8_t   g_act[4][NE];        // i,f,o,cg activation codes
__device__ int8_t   g_cq[NE];            // c_prev codes
__device__ int8_t   g_tq[NE];            // tanh(c_next) codes

// ---------- helpers ----------
__device__ __forceinline__ unsigned fenc(float f) {
    unsigned u = __float_as_uint(f);
    return (u & 0x80000000u) ? ~u : (u | 0x80000000u);
}
__device__ __forceinline__ float fdec(unsigned u) {
    return __uint_as_float((u & 0x80000000u) ? (u & 0x7fffffffu) : ~u);
}
__device__ __forceinline__ float quant_q(float v, float s, float zp) {
    float q = rintf(__fdiv_rn(v, s)) + zp;
    return fminf(fmaxf(q, -128.f), 127.f);
}
__device__ __forceinline__ float fqv(float v, float s, float zp) {
    return __fmul_rn(quant_q(v, s, zp) - zp, s);
}
__device__ __forceinline__ void mkparams(float mnr, float mxr, float* s, float* zp) {
    float mn = fminf(mnr, 0.f), mx = fmaxf(mxr, 0.f);
    float sc = fmaxf(__fdiv_rn(mx - mn, 255.f), 1e-8f);
    float z  = rintf(-128.f - __fdiv_rn(mn, sc));
    *s = sc; *zp = fminf(fmaxf(z, -128.f), 127.f);
}
__device__ __forceinline__ float hsig(float v) {
    return fminf(fmaxf(__fadd_rn(__fdiv_rn(v, 6.f), 0.5f), 0.f), 1.f);
}
__device__ __forceinline__ float htanh(float v) { return fminf(fmaxf(v, -1.f), 1.f); }

__device__ __forceinline__ void block_minmax(float mn, float mx, unsigned* gmin, unsigned* gmax) {
    #pragma unroll
    for (int o = 16; o; o >>= 1) {
        mn = fminf(mn, __shfl_xor_sync(0xffffffffu, mn, o));
        mx = fmaxf(mx, __shfl_xor_sync(0xffffffffu, mx, o));
    }
    __shared__ float smn[8], smx[8];
    int w = threadIdx.x >> 5, nw = blockDim.x >> 5;
    __syncthreads();
    if ((threadIdx.x & 31) == 0) { smn[w] = mn; smx[w] = mx; }
    __syncthreads();
    if (threadIdx.x == 0) {
        for (int i = 1; i < nw; i++) { mn = fminf(mn, smn[i]); mx = fmaxf(mx, smx[i]); }
        atomicMin(gmin, fenc(mn));
        atomicMax(gmax, fenc(mx));
    }
    __syncthreads();
}

__device__ __forceinline__ float2 block_reduce_pair(float mn, float mx) {
    #pragma unroll
    for (int o = 16; o; o >>= 1) {
        mn = fminf(mn, __shfl_xor_sync(0xffffffffu, mn, o));
        mx = fmaxf(mx, __shfl_xor_sync(0xffffffffu, mx, o));
    }
    __shared__ float smn[8], smx[8];
    __shared__ float2 res;
    int w = threadIdx.x >> 5, nw = blockDim.x >> 5;
    __syncthreads();
    if ((threadIdx.x & 31) == 0) { smn[w] = mn; smx[w] = mx; }
    __syncthreads();
    if (threadIdx.x == 0) {
        for (int i = 1; i < nw; i++) { mn = fminf(mn, smn[i]); mx = fmaxf(mx, smx[i]); }
        res = make_float2(mn, mx);
    }
    __syncthreads();
    return res;
}

// ---------- K0: reset reduction slots ----------
__global__ void k_init() {
    int t = threadIdx.x;
    if (t < 11) { g_mm[2 * t] = fenc(1e30f); g_mm[2 * t + 1] = fenc(-1e30f); }
}

// ---------- K1: minmax of x, h, c ----------
__global__ void k_minmax3(const float* __restrict__ x, const float* __restrict__ h,
                          const float* __restrict__ c) {
    const float* arrs[3] = {x, h, c};
    for (int a = 0; a < 3; a++) {
        float mn = 1e30f, mx = -1e30f;
        const float4* p = (const float4*)arrs[a];
        for (long i = blockIdx.x * blockDim.x + threadIdx.x; i < NE / 4;
             i += (long)gridDim.x * blockDim.x) {
            float4 v = p[i];
            mn = fminf(fminf(fminf(mn, v.x), v.y), fminf(v.z, v.w));
            mx = fmaxf(fmaxf(fmaxf(mx, v.x), v.y), fmaxf(v.z, v.w));
        }
        block_minmax(mn, mx, &g_mm[2 * a], &g_mm[2 * a + 1]);
    }
}

// ---------- K2: scalar params + weight/bias quantization (1 block) ----------
__global__ void k_params(const float* __restrict__ Wi, const float* __restrict__ bi,
                         const float* __restrict__ Wf, const float* __restrict__ bf,
                         const float* __restrict__ Wo, const float* __restrict__ bo,
                         const float* __restrict__ Wc, const float* __restrict__ bc) {
    __shared__ float sw, zw, sb, zb;
    int t = threadIdx.x;
    if (t == 0) {
        mkparams(fdec(g_mm[0]), fdec(g_mm[1]), &g_p.s_x, &g_p.zp_x);
        mkparams(fdec(g_mm[2]), fdec(g_mm[3]), &g_p.s_h, &g_p.zp_h);
        mkparams(fdec(g_mm[4]), fdec(g_mm[5]), &g_p.s_c, &g_p.zp_c);
        float xlo = fqv(fdec(g_mm[0]), g_p.s_x, g_p.zp_x);
        float xhi = fqv(fdec(g_mm[1]), g_p.s_x, g_p.zp_x);
        float hlo = fqv(fdec(g_mm[2]), g_p.s_h, g_p.zp_h);
        float hhi = fqv(fdec(g_mm[3]), g_p.s_h, g_p.zp_h);
        mkparams(fminf(xlo, hlo), fmaxf(xhi, hhi), &g_p.s_cat, &g_p.zp_cat);
        g_p.zpc_i = (int)g_p.zp_cat;
    }
    __syncthreads();
    const float* Wg[4] = {Wi, Wf, Wo, Wc};
    const float* bg[4] = {bi, bf, bo, bc};
    for (int g = 0; g < 4; g++) {
        float mn = 1e30f, mx = -1e30f;
        for (int i = t; i < 8192; i += 256) {
            float v = Wg[g][i];
            mn = fminf(mn, v); mx = fmaxf(mx, v);
        }
        float2 m = block_reduce_pair(mn, mx);
        if (t == 0) {
            mkparams(m.x, m.y, &sw, &zw);
            g_p.alpha[g] = __fmul_rn(g_p.s_cat, sw);
            g_p.zpw_i[g] = (int)zw;
        }
        __syncthreads();
        for (int i = t; i < 8192; i += 256)
            g_wq[g * 8192 + i] = (int8_t)(int)quant_q(Wg[g][i], sw, zw);
        mn = (t < 64) ? bg[g][t] : 1e30f;
        mx = (t < 64) ? bg[g][t] : -1e30f;
        m = block_reduce_pair(mn, mx);
        if (t == 0) mkparams(m.x, m.y, &sb, &zb);
        __syncthreads();
        if (t < 64) g_p.bdq[g * 64 + t] = fqv(bg[g][t], sb, zb);
        __syncthreads();
    }
    {
        int s = 0;
        const int8_t* wr = &g_wq[t * 128];
        for (int k = 0; k < 128; k++) s += wr[k];
        int g = t >> 6;
        g_const[t] = -g_p.zpc_i * s + 128 * g_p.zpc_i * g_p.zpw_i[g];
    }
}

// ---------- K2b: quantize c_prev to codes ----------
__global__ void k_quantc(const float* __restrict__ c) {
    float s = g_p.s_c, z = g_p.zp_c;
    for (long i = blockIdx.x * blockDim.x + threadIdx.x; i < NE / 4;
         i += (long)gridDim.x * blockDim.x) {
        float4 v = ((const float4*)c)[i];
        char4 q;
        q.x = (int8_t)(int)quant_q(v.x, s, z);
        q.y = (int8_t)(int)quant_q(v.y, s, z);
        q.z = (int8_t)(int)quant_q(v.z, s, z);
        q.w = (int8_t)(int)quant_q(v.w, s, z);
        ((char4*)g_cq)[i] = q;
    }
}

// ---------- K3a: pass A — quantize cat, store codes+rowsum, dp4a, gate minmax ----------
__global__ void __launch_bounds__(256) k_gemmA(const float* __restrict__ X,
                                               const float* __restrict__ H) {
    __shared__ __align__(16) uint32_t rsm[8][36];
    __shared__ int rowsum[8];
    int t = threadIdx.x, lane = t & 31, wrp = t >> 5;
    int g = t >> 6;
    int wv[32];
    const int* wq32 = (const int*)g_wq;
    #pragma unroll
    for (int w = 0; w < 32; w++) wv[w] = wq32[t * 32 + w];
    float al = g_p.alpha[g], bo = g_p.bdq[t];
    int   zw = g_p.zpw_i[g], co = g_const[t];
    float sx = g_p.s_x, zx = g_p.zp_x, sh = g_p.s_h, zh = g_p.zp_h;
    float sc = g_p.s_cat, zc = g_p.zp_cat;
    float mn = 1e30f, mx = -1e30f;

    for (long tile = blockIdx.x; tile < R_TOT / 8; tile += gridDim.x) {
        long r0 = tile * 8;
        {
            long r = r0 + wrp;
            float4 v = (lane < 16) ? ((const float4*)X)[r * 16 + lane]
                                   : ((const float4*)H)[r * 16 + lane - 16];
            float s0 = (lane < 16) ? sx : sh, z0 = (lane < 16) ? zx : zh;
            int q0 = (int)quant_q(fqv(v.x, s0, z0), sc, zc);
            int q1 = (int)quant_q(fqv(v.y, s0, z0), sc, zc);
            int q2 = (int)quant_q(fqv(v.z, s0, z0), sc, zc);
            int q3 = (int)quant_q(fqv(v.w, s0, z0), sc, zc);
            uint32_t pk = (uint32_t)(q0 & 255) | ((uint32_t)(q1 & 255) << 8) |
                          ((uint32_t)(q2 & 255) << 16) | ((uint32_t)(q3 & 255) << 24);
            int sum = q0 + q1 + q2 + q3;
            #pragma unroll
            for (int o = 16; o; o >>= 1) sum += __shfl_xor_sync(0xffffffffu, sum, o);
            rsm[wrp][lane] = pk;
            g_catq[r * 32 + lane] = pk;
            if (lane == 0) { rowsum[wrp] = sum; g_rowsum[r] = sum; }
        }
        __syncthreads();
        #pragma unroll
        for (int rr = 0; rr < 8; rr++) {
            const uint4* rp = (const uint4*)rsm[rr];
            int acc = 0;
            #pragma unroll
            for (int w4 = 0; w4 < 8; w4++) {
                uint4 vv = rp[w4];
                acc = __dp4a((int)vv.x, wv[w4 * 4 + 0], acc);
                acc = __dp4a((int)vv.y, wv[w4 * 4 + 1], acc);
                acc = __dp4a((int)vv.z, wv[w4 * 4 + 2], acc);
                acc = __dp4a((int)vv.w, wv[w4 * 4 + 3], acc);
            }
            int S = acc - zw * rowsum[rr] + co;
            float G = __fadd_rn(__fmul_rn((float)S, al), bo);
            mn = fminf(mn, G); mx = fmaxf(mx, G);
        }
        __syncthreads();
    }
    #pragma unroll
    for (int o = 16; o; o >>= 1) {
        mn = fminf(mn, __shfl_xor_sync(0xffffffffu, mn, o));
        mx = fmaxf(mx, __shfl_xor_sync(0xffffffffu, mx, o));
    }
    if (lane == 0) {
        atomicMin(&g_mm[6 + 2 * g], fenc(mn));
        atomicMax(&g_mm[7 + 2 * g], fenc(mx));
    }
}

// ---------- K4: gate + activation params ----------
__global__ void k_p2() {
    for (int g = 0; g < 4; g++) {
        float mn = fdec(g_mm[6 + 2 * g]), mx = fdec(g_mm[7 + 2 * g]);
        mkparams(mn, mx, &g_p.sG[g], &g_p.zpG[g]);
        float lo = fqv(mn, g_p.sG[g], g_p.zpG[g]);
        float hi = fqv(mx, g_p.sG[g], g_p.zpG[g]);
        float amin, amax;
        if (g < 3) { amin = hsig(lo); amax = hsig(hi); }
        else       { amin = htanh(lo); amax = htanh(hi); }
        mkparams(amin, amax, &g_p.sA[g], &g_p.zpA[g]);
    }
}

// ---------- K3b: pass B — dp4a from stored codes, activations, fc/ic minmax ----------
__global__ void __launch_bounds__(256) k_gemmB() {
    __shared__ __align__(16) uint32_t rsm[8][36];
    __shared__ int rowsum[8];
    __shared__ int8_t sact[8][264];
    int t = threadIdx.x, lane = t & 31, wrp = t >> 5;
    int g = t >> 6;
    int wv[32];
    const int* wq32 = (const int*)g_wq;
    #pragma unroll
    for (int w = 0; w < 32; w++) wv[w] = wq32[t * 32 + w];
    float al = g_p.alpha[g], bo = g_p.bdq[t];
    int   zw = g_p.zpw_i[g], co = g_const[t];
    float sGg = g_p.sG[g], zGg = g_p.zpG[g], sAg = g_p.sA[g], zAg = g_p.zpA[g];
    float sAi = g_p.sA[0], zAi = g_p.zpA[0], sAf = g_p.sA[1], zAf = g_p.zpA[1];
    float sAc = g_p.sA[3], zAc = g_p.zpA[3];
    float scc = g_p.s_c, zcc = g_p.zp_c;
    bool is_sig = (g < 3);
    float mn1 = 1e30f, mx1 = -1e30f, mn2 = 1e30f, mx2 = -1e30f;

    for (long tile = blockIdx.x; tile < R_TOT / 8; tile += gridDim.x) {
        long r0 = tile * 8;
        {
            long r = r0 + wrp;
            rsm[wrp][lane] = g_catq[r * 32 + lane];
            if (lane == 0) rowsum[wrp] = g_rowsum[r];
        }
        __syncthreads();
        #pragma unroll
        for (int rr = 0; rr < 8; rr++) {
            const uint4* rp = (const uint4*)rsm[rr];
            int acc = 0;
            #pragma unroll
            for (int w4 = 0; w4 < 8; w4++) {
                uint4 vv = rp[w4];
                acc = __dp4a((int)vv.x, wv[w4 * 4 + 0], acc);
                acc = __dp4a((int)vv.y, wv[w4 * 4 + 1], acc);
                acc = __dp4a((int)vv.z, wv[w4 * 4 + 2], acc);
                acc = __dp4a((int)vv.w, wv[w4 * 4 + 3], acc);
            }
            int S = acc - zw * rowsum[rr] + co;
            float G = __fadd_rn(__fmul_rn((float)S, al), bo);
            float v = fqv(G, sGg, zGg);
            float a = is_sig ? hsig(v) : htanh(v);
            sact[rr][t] = (int8_t)(int)quant_q(a, sAg, zAg);
        }
        __syncthreads();
        // coalesced store of act codes: 512 words, 2 per thread
        #pragma unroll
        for (int q = 0; q < 2; q++) {
            int w_ = t + q * 256;
            int gg = w_ >> 7, rem = w_ & 127, row = rem >> 4, wo = rem & 15;
            uint32_t val = *(const uint32_t*)&sact[row][gg * 64 + wo * 4];
            *(uint32_t*)&g_act[gg][(r0 + row) * 64 + wo * 4] = val;
        }
        // fc/ic minmax: thread handles (rows t>>6 and (t>>6)+4, hcol t&63)
        {
            int h0 = t & 63, rb = t >> 6;
            #pragma unroll
            for (int half = 0; half < 2; half++) {
                int row = rb + half * 4;
                int qi = (int)sact[row][0 * 64 + h0];
                int qf = (int)sact[row][1 * 64 + h0];
                int qg = (int)sact[row][3 * 64 + h0];
                int qc = (int)g_cq[(r0 + row) * 64 + h0];
                float fv = __fmul_rn((float)qf - zAf, sAf);
                float iv = __fmul_rn((float)qi - zAi, sAi);
                float gv = __fmul_rn((float)qg - zAc, sAc);
                float cd = __fmul_rn((float)qc - zcc, scc);
                float fc = __fmul_rn(fv, cd);
                float ic = __fmul_rn(iv, gv);
                mn1 = fminf(mn1, fc); mx1 = fmaxf(mx1, fc);
                mn2 = fminf(mn2, ic); mx2 = fmaxf(mx2, ic);
            }
        }
        __syncthreads();
    }
    block_minmax(mn1, mx1, &g_mm[14], &g_mm[15]);
    block_minmax(mn2, mx2, &g_mm[16], &g_mm[17]);
}

// ---------- K6 ----------
__global__ void k_p3() {
    mkparams(fdec(g_mm[14]), fdec(g_mm[15]), &g_p.s_fc, &g_p.zp_fc);
    mkparams(fdec(g_mm[16]), fdec(g_mm[17]), &g_p.s_ic, &g_p.zp_ic);
}

// ---------- K7: minmax of fq(fc)+fq(ic) ----------
__global__ void k_pre() {
    float sAi = g_p.sA[0], zAi = g_p.zpA[0], sAf = g_p.sA[1], zAf = g_p.zpA[1];
    float sAg = g_p.sA[3], zAg = g_p.zpA[3], scc = g_p.s_c, zcc = g_p.zp_c;
    float sfc = g_p.s_fc, zfc = g_p.zp_fc, sic = g_p.s_ic, zic = g_p.zp_ic;
    float mn = 1e30f, mx = -1e30f;
    for (long i = blockIdx.x * blockDim.x + threadIdx.x; i < NE / 4;
         i += (long)gridDim.x * blockDim.x) {
        char4 qi = ((const char4*)g_act[0])[i];
        char4 qf = ((const char4*)g_act[1])[i];
        char4 qg = ((const char4*)g_act[3])[i];
        char4 qc = ((const char4*)g_cq)[i];
        int ii[4] = {qi.x, qi.y, qi.z, qi.w}, ff[4] = {qf.x, qf.y, qf.z, qf.w};
        int gg[4] = {qg.x, qg.y, qg.z, qg.w}, cc[4] = {qc.x, qc.y, qc.z, qc.w};
        #pragma unroll
        for (int j = 0; j < 4; j++) {
            float fv = __fmul_rn((float)ff[j] - zAf, sAf);
            float iv = __fmul_rn((float)ii[j] - zAi, sAi);
            float gv = __fmul_rn((float)gg[j] - zAg, sAg);
            float cd = __fmul_rn((float)cc[j] - zcc, scc);
            float fcv = fqv(__fmul_rn(fv, cd), sfc, zfc);
            float icv = fqv(__fmul_rn(iv, gv), sic, zic);
            float pre = __fadd_rn(fcv, icv);
            mn = fminf(mn, pre); mx = fmaxf(mx, pre);
        }
    }
    block_minmax(mn, mx, &g_mm[18], &g_mm[19]);
}

// ---------- K8 ----------
__global__ void k_p4() {
    float mn = fdec(g_mm[18]), mx = fdec(g_mm[19]);
    mkparams(mn, mx, &g_p.s_cn, &g_p.zp_cn);
    float lo = htanh(fqv(mn, g_p.s_cn, g_p.zp_cn));
    float hi = htanh(fqv(mx, g_p.s_cn, g_p.zp_cn));
    mkparams(lo, hi, &g_p.s_t, &g_p.zp_t);
}

// ---------- K9: write c_next, store t codes, minmax(o*t) ----------
__global__ void k_cnext(float* __restrict__ out_c) {
    float sAi = g_p.sA[0], zAi = g_p.zpA[0], sAf = g_p.sA[1], zAf = g_p.zpA[1];
    float sAo = g_p.sA[2], zAo = g_p.zpA[2], sAg = g_p.sA[3], zAg = g_p.zpA[3];
    float scc = g_p.s_c, zcc = g_p.zp_c;
    float sfc = g_p.s_fc, zfc = g_p.zp_fc, sic = g_p.s_ic, zic = g_p.zp_ic;
    float scn = g_p.s_cn, zcn = g_p.zp_cn, st = g_p.s_t, zt = g_p.zp_t;
    float mn = 1e30f, mx = -1e30f;
    for (long i = blockIdx.x * blockDim.x + threadIdx.x; i < NE / 4;
         i += (long)gridDim.x * blockDim.x) {
        char4 qi = ((const char4*)g_act[0])[i];
        char4 qf = ((const char4*)g_act[1])[i];
        char4 qo = ((const char4*)g_act[2])[i];
        char4 qg = ((const char4*)g_act[3])[i];
        char4 qc = ((const char4*)g_cq)[i];
        int ii[4] = {qi.x, qi.y, qi.z, qi.w}, ff[4] = {qf.x, qf.y, qf.z, qf.w};
        int oo[4] = {qo.x, qo.y, qo.z, qo.w}, gg[4] = {qg.x, qg.y, qg.z, qg.w};
        int cc[4] = {qc.x, qc.y, qc.z, qc.w};
        float4 outc;
        float* oc = (float*)&outc;
        char4 tq4;
        int8_t* tqq = (int8_t*)&tq4;
        #pragma unroll
        for (int j = 0; j < 4; j++) {
            float fv = __fmul_rn((float)ff[j] - zAf, sAf);
            float iv = __fmul_rn((float)ii[j] - zAi, sAi);
            float gv = __fmul_rn((float)gg[j] - zAg, sAg);
            float cd = __fmul_rn((float)cc[j] - zcc, scc);
            float fcv = fqv(__fmul_rn(fv, cd), sfc, zfc);
            float icv = fqv(__fmul_rn(iv, gv), sic, zic);
            float pre = __fadd_rn(fcv, icv);
            float cn = fqv(pre, scn, zcn);
            oc[j] = cn;
            int tcode = (int)quant_q(htanh(cn), st, zt);
            tqq[j] = (int8_t)tcode;
            float tv = __fmul_rn((float)tcode - zt, st);
            float ov = __fmul_rn((float)oo[j] - zAo, sAo);
            float hp = __fmul_rn(ov, tv);
            mn = fminf(mn, hp); mx = fmaxf(mx, hp);
        }
        ((float4*)out_c)[i] = outc;
        ((char4*)g_tq)[i] = tq4;
    }
    block_minmax(mn, mx, &g_mm[20], &g_mm[21]);
}

// ---------- K10 ----------
__global__ void k_p5() {
    mkparams(fdec(g_mm[20]), fdec(g_mm[21]), &g_p.s_hn, &g_p.zp_hn);
}

// ---------- K11: h_next ----------
__global__ void k_hnext(float* __restrict__ out_h) {
    float sAo = g_p.sA[2], zAo = g_p.zpA[2], st = g_p.s_t, zt = g_p.zp_t;
    float shn = g_p.s_hn, zhn = g_p.zp_hn;
    for (long i = blockIdx.x * blockDim.x + threadIdx.x; i < NE / 4;
         i += (long)gridDim.x * blockDim.x) {
        char4 qo = ((const char4*)g_act[2])[i];
        char4 qt = ((const char4*)g_tq)[i];
        int oo[4] = {qo.x, qo.y, qo.z, qo.w}, tt[4] = {qt.x, qt.y, qt.z, qt.w};
        float4 outh;
        float* oh = (float*)&outh;
        #pragma unroll
        for (int j = 0; j < 4; j++) {
            float ov = __fmul_rn((float)oo[j] - zAo, sAo);
            float tv = __fmul_rn((float)tt[j] - zt, st);
            oh[j] = fqv(__fmul_rn(ov, tv), shn, zhn);
        }
        ((float4*)out_h)[i] = outh;
    }
}

extern "C" void kernel_launch(void* const* d_in, const int* in_sizes, int n_in,
                              void* d_out, int out_size) {
    const float* x  = (const float*)d_in[0];
    const float* h  = (const float*)d_in[1];
    const float* c  = (const float*)d_in[2];
    const float* Wi = (const float*)d_in[3];
    const float* bi = (const float*)d_in[4];
    const float* Wf = (const float*)d_in[5];
    const float* bf = (const float*)d_in[6];
    const float* Wo = (const float*)d_in[7];
    const float* bo = (const float*)d_in[8];
    const float* Wc = (const float*)d_in[9];
    const float* bc = (const float*)d_in[10];
    float* out_h = (float*)d_out;
    float* out_c = (float*)d_out + NE;

    k_init<<<1, 32>>>();
    k_minmax3<<<2048, 256>>>(x, h, c);
    k_params<<<1, 256>>>(Wi, bi, Wf, bf, Wo, bo, Wc, bc);
    k_quantc<<<4096, 256>>>(c);
    k_gemmA<<<2048, 256>>>(x, h);
    k_p2<<<1, 1>>>();
    k_gemmB<<<2048, 256>>>();
    k_p3<<<1, 1>>>();
    k_pre<<<8192, 256>>>();
    k_p4<<<1, 1>>>();
    k_cnext<<<8192, 256>>>(out_c);
    k_p5<<<1, 1>>>();
    k_hnext<<<8192, 256>>>(out_h);
}

// round 6
// speedup vs baseline: 4.0749x; 1.2592x over previous
#include <cuda_runtime.h>
#include <stdint.h>

#define R_TOT 524288
#define NE    33554432
#define NT128 4096            // R_TOT / 128 rows per macro-tile
#define ONEB  0x01010101

struct Params {
    float s_x, zp_x, s_h, zp_h, s_c, zp_c, s_cat, zp_cat;
    float alpha[4];
    float bdq[256];
    int   zpw_i[4], zpc_i;
    float sG[4], zpG[4], sA[4], zpA[4];
    float s_fc, zp_fc, s_ic, zp_ic, s_cn, zp_cn, s_t, zp_t, s_hn, zp_hn;
};

__device__ Params   g_p;
__device__ unsigned g_mm[22];            // 11 (min,max) encoded-float slots
__device__ int8_t   g_wq[256 * 128];     // quantized weight codes [col][k]
__device__ int      g_const[256];        // per-output zero-point correction
__device__ uint32_t g_catq[R_TOT * 32];  // packed cat codes (64 MB)
__device__ int      g_rowsum[R_TOT];     // per-row code sums (2 MB)
__device__ int8_t   g_act[4][NE];        // i,f,o,cg activation codes
__device__ int8_t   g_cq[NE];            // c_prev codes
__device__ int8_t   g_tq[NE];            // tanh(c_next) codes

// ---------- helpers ----------
__device__ __forceinline__ unsigned fenc(float f) {
    unsigned u = __float_as_uint(f);
    return (u & 0x80000000u) ? ~u : (u | 0x80000000u);
}
__device__ __forceinline__ float fdec(unsigned u) {
    return __uint_as_float((u & 0x80000000u) ? (u & 0x7fffffffu) : ~u);
}
__device__ __forceinline__ float quant_q(float v, float s, float zp) {
    float q = rintf(__fdiv_rn(v, s)) + zp;
    return fminf(fmaxf(q, -128.f), 127.f);
}
__device__ __forceinline__ float fqv(float v, float s, float zp) {
    return __fmul_rn(quant_q(v, s, zp) - zp, s);
}
__device__ __forceinline__ void mkparams(float mnr, float mxr, float* s, float* zp) {
    float mn = fminf(mnr, 0.f), mx = fmaxf(mxr, 0.f);
    float sc = fmaxf(__fdiv_rn(mx - mn, 255.f), 1e-8f);
    float z  = rintf(-128.f - __fdiv_rn(mn, sc));
    *s = sc; *zp = fminf(fmaxf(z, -128.f), 127.f);
}
__device__ __forceinline__ float hsig(float v) {
    return fminf(fmaxf(__fadd_rn(__fdiv_rn(v, 6.f), 0.5f), 0.f), 1.f);
}
__device__ __forceinline__ float htanh(float v) { return fminf(fmaxf(v, -1.f), 1.f); }

__device__ __forceinline__ void block_minmax(float mn, float mx, unsigned* gmin, unsigned* gmax) {
    #pragma unroll
    for (int o = 16; o; o >>= 1) {
        mn = fminf(mn, __shfl_xor_sync(0xffffffffu, mn, o));
        mx = fmaxf(mx, __shfl_xor_sync(0xffffffffu, mx, o));
    }
    __shared__ float smn[8], smx[8];
    int w = threadIdx.x >> 5, nw = blockDim.x >> 5;
    __syncthreads();
    if ((threadIdx.x & 31) == 0) { smn[w] = mn; smx[w] = mx; }
    __syncthreads();
    if (threadIdx.x == 0) {
        for (int i = 1; i < nw; i++) { mn = fminf(mn, smn[i]); mx = fmaxf(mx, smx[i]); }
        atomicMin(gmin, fenc(mn));
        atomicMax(gmax, fenc(mx));
    }
    __syncthreads();
}

__device__ __forceinline__ float2 block_reduce_pair(float mn, float mx) {
    #pragma unroll
    for (int o = 16; o; o >>= 1) {
        mn = fminf(mn, __shfl_xor_sync(0xffffffffu, mn, o));
        mx = fmaxf(mx, __shfl_xor_sync(0xffffffffu, mx, o));
    }
    __shared__ float smn[8], smx[8];
    __shared__ float2 res;
    int w = threadIdx.x >> 5, nw = blockDim.x >> 5;
    __syncthreads();
    if ((threadIdx.x & 31) == 0) { smn[w] = mn; smx[w] = mx; }
    __syncthreads();
    if (threadIdx.x == 0) {
        for (int i = 1; i < nw; i++) { mn = fminf(mn, smn[i]); mx = fmaxf(mx, smx[i]); }
        res = make_float2(mn, mx);
    }
    __syncthreads();
    return res;
}

__device__ __forceinline__ void mma_s8(int* c, uint32_t a0, uint32_t a1, uint32_t a2,
                                       uint32_t a3, uint32_t b0, uint32_t b1) {
    asm volatile(
        "mma.sync.aligned.m16n8k32.row.col.s32.s8.s8.s32 "
        "{%0,%1,%2,%3}, {%4,%5,%6,%7}, {%8,%9}, {%0,%1,%2,%3};\n"
        : "+r"(c[0]), "+r"(c[1]), "+r"(c[2]), "+r"(c[3])
        : "r"(a0), "r"(a1), "r"(a2), "r"(a3), "r"(b0), "r"(b1));
}
__device__ __forceinline__ void ldsm_x4(uint32_t& r0, uint32_t& r1, uint32_t& r2,
                                        uint32_t& r3, uint32_t addr) {
    asm volatile("ldmatrix.sync.aligned.m8n8.x4.shared.b16 {%0,%1,%2,%3}, [%4];"
                 : "=r"(r0), "=r"(r1), "=r"(r2), "=r"(r3) : "r"(addr));
}
__device__ __forceinline__ void ldsm_x2(uint32_t& r0, uint32_t& r1, uint32_t addr) {
    asm volatile("ldmatrix.sync.aligned.m8n8.x2.shared.b16 {%0,%1}, [%2];"
                 : "=r"(r0), "=r"(r1) : "r"(addr));
}

// ---------- K0: reset reduction slots ----------
__global__ void k_init() {
    int t = threadIdx.x;
    if (t < 11) { g_mm[2 * t] = fenc(1e30f); g_mm[2 * t + 1] = fenc(-1e30f); }
}

// ---------- K1: minmax of x, h, c ----------
__global__ void k_minmax3(const float* __restrict__ x, const float* __restrict__ h,
                          const float* __restrict__ c) {
    const float* arrs[3] = {x, h, c};
    for (int a = 0; a < 3; a++) {
        float mn = 1e30f, mx = -1e30f;
        const float4* p = (const float4*)arrs[a];
        for (long i = blockIdx.x * blockDim.x + threadIdx.x; i < NE / 4;
             i += (long)gridDim.x * blockDim.x) {
            float4 v = p[i];
            mn = fminf(fminf(fminf(mn, v.x), v.y), fminf(v.z, v.w));
            mx = fmaxf(fmaxf(fmaxf(mx, v.x), v.y), fmaxf(v.z, v.w));
        }
        block_minmax(mn, mx, &g_mm[2 * a], &g_mm[2 * a + 1]);
    }
}

// ---------- K2: scalar params + weight/bias quantization (1 block) ----------
__global__ void k_params(const float* __restrict__ Wi, const float* __restrict__ bi,
                         const float* __restrict__ Wf, const float* __restrict__ bf,
                         const float* __restrict__ Wo, const float* __restrict__ bo,
                         const float* __restrict__ Wc, const float* __restrict__ bc) {
    __shared__ float sw, zw, sb, zb;
    int t = threadIdx.x;
    if (t == 0) {
        mkparams(fdec(g_mm[0]), fdec(g_mm[1]), &g_p.s_x, &g_p.zp_x);
        mkparams(fdec(g_mm[2]), fdec(g_mm[3]), &g_p.s_h, &g_p.zp_h);
        mkparams(fdec(g_mm[4]), fdec(g_mm[5]), &g_p.s_c, &g_p.zp_c);
        float xlo = fqv(fdec(g_mm[0]), g_p.s_x, g_p.zp_x);
        float xhi = fqv(fdec(g_mm[1]), g_p.s_x, g_p.zp_x);
        float hlo = fqv(fdec(g_mm[2]), g_p.s_h, g_p.zp_h);
        float hhi = fqv(fdec(g_mm[3]), g_p.s_h, g_p.zp_h);
        mkparams(fminf(xlo, hlo), fmaxf(xhi, hhi), &g_p.s_cat, &g_p.zp_cat);
        g_p.zpc_i = (int)g_p.zp_cat;
    }
    __syncthreads();
    const float* Wg[4] = {Wi, Wf, Wo, Wc};
    const float* bg[4] = {bi, bf, bo, bc};
    for (int g = 0; g < 4; g++) {
        float mn = 1e30f, mx = -1e30f;
        for (int i = t; i < 8192; i += 256) {
            float v = Wg[g][i];
            mn = fminf(mn, v); mx = fmaxf(mx, v);
        }
        float2 m = block_reduce_pair(mn, mx);
        if (t == 0) {
            mkparams(m.x, m.y, &sw, &zw);
            g_p.alpha[g] = __fmul_rn(g_p.s_cat, sw);
            g_p.zpw_i[g] = (int)zw;
        }
        __syncthreads();
        for (int i = t; i < 8192; i += 256)
            g_wq[g * 8192 + i] = (int8_t)(int)quant_q(Wg[g][i], sw, zw);
        mn = (t < 64) ? bg[g][t] : 1e30f;
        mx = (t < 64) ? bg[g][t] : -1e30f;
        m = block_reduce_pair(mn, mx);
        if (t == 0) mkparams(m.x, m.y, &sb, &zb);
        __syncthreads();
        if (t < 64) g_p.bdq[g * 64 + t] = fqv(bg[g][t], sb, zb);
        __syncthreads();
    }
    {
        int s = 0;
        const int8_t* wr = &g_wq[t * 128];
        for (int k = 0; k < 128; k++) s += wr[k];
        int g = t >> 6;
        g_const[t] = -g_p.zpc_i * s + 128 * g_p.zpc_i * g_p.zpw_i[g];
    }
}

// ---------- K2b: quantize c_prev to codes ----------
__global__ void k_quantc(const float* __restrict__ c) {
    float s = g_p.s_c, z = g_p.zp_c;
    for (long i = blockIdx.x * blockDim.x + threadIdx.x; i < NE / 4;
         i += (long)gridDim.x * blockDim.x) {
        float4 v = ((const float4*)c)[i];
        char4 q;
        q.x = (int8_t)(int)quant_q(v.x, s, z);
        q.y = (int8_t)(int)quant_q(v.y, s, z);
        q.z = (int8_t)(int)quant_q(v.z, s, z);
        q.w = (int8_t)(int)quant_q(v.w, s, z);
        ((char4*)g_cq)[i] = q;
    }
}

// dyn smem layout (both gemm kernels):
//   [0, 32768)          W codes, [col][k], 256 cols x 128 bytes
//   [32768, ...)        codes staging: 128 rows x 36 words (144B stride, 16B aligned)
//                       word 32 of each row = rowsum.  (k_gemmB: unioned with sact)
#define W_BYTES   32768
#define CODE_STRW 36
#define SACT_STR  264
#define DYN_A     (W_BYTES + 128 * CODE_STRW * 4)              // 51200
#define DYN_B     (W_BYTES + 128 * SACT_STR)                   // 66560

// ---------- K3a: pass A — quantize cat, store codes+rowsum, MMA, gate minmax ----------
__global__ void __launch_bounds__(256) k_gemmA(const float* __restrict__ X,
                                               const float* __restrict__ H) {
    extern __shared__ uint8_t dyn[];
    uint32_t* Wsm32  = (uint32_t*)dyn;
    uint32_t* codes  = (uint32_t*)(dyn + W_BYTES);
    __shared__ int   cosm[256];
    __shared__ float bosm[256];
    __shared__ float alsm[4];
    __shared__ int   zwsm[4];
    int t = threadIdx.x, lane = t & 31, w = t >> 5;

    const uint32_t* wq32 = (const uint32_t*)g_wq;
    #pragma unroll
    for (int i = 0; i < 32; i++) Wsm32[t + i * 256] = wq32[t + i * 256];
    cosm[t] = g_const[t];
    bosm[t] = g_p.bdq[t];
    if (t < 4) { alsm[t] = g_p.alpha[t]; zwsm[t] = g_p.zpw_i[t]; }

    float sx = g_p.s_x, zx = g_p.zp_x, sh = g_p.s_h, zh = g_p.zp_h;
    float sc = g_p.s_cat, zc = g_p.zp_cat;
    const float4* X4 = (const float4*)X;
    const float4* H4 = (const float4*)H;

    uint32_t Waddr = (uint32_t)__cvta_generic_to_shared(Wsm32);
    uint32_t Caddr = (uint32_t)__cvta_generic_to_shared(codes);
    uint32_t ldB_base = Waddr + (lane & 7) * 128 + ((lane >> 3) & 1) * 16;
    uint32_t ldA_base = Caddr + (w * 16 + (lane & 15)) * 144 + (lane >> 4) * 16;

    float mnG[4], mxG[4];
    #pragma unroll
    for (int g = 0; g < 4; g++) { mnG[g] = 1e30f; mxG[g] = -1e30f; }
    __syncthreads();

    for (int tile = blockIdx.x; tile < NT128; tile += gridDim.x) {
        long r0 = (long)tile * 128;
        // quantize 16 rows per warp, 1 row per iteration (lane<16: X, else H)
        #pragma unroll 4
        for (int rr = 0; rr < 16; rr++) {
            int lrow = w * 16 + rr;
            long row = r0 + lrow;
            float4 v = (lane < 16) ? X4[row * 16 + lane] : H4[row * 16 + lane - 16];
            float s0 = (lane < 16) ? sx : sh, z0 = (lane < 16) ? zx : zh;
            int q0 = (int)quant_q(fqv(v.x, s0, z0), sc, zc);
            int q1 = (int)quant_q(fqv(v.y, s0, z0), sc, zc);
            int q2 = (int)quant_q(fqv(v.z, s0, z0), sc, zc);
            int q3 = (int)quant_q(fqv(v.w, s0, z0), sc, zc);
            uint32_t pk = (uint32_t)(q0 & 255) | ((uint32_t)(q1 & 255) << 8) |
                          ((uint32_t)(q2 & 255) << 16) | ((uint32_t)(q3 & 255) << 24);
            codes[lrow * CODE_STRW + lane] = pk;
            g_catq[row * 32 + lane] = pk;
        }
        __syncthreads();
        if (t < 128) {
            const uint32_t* cr = &codes[t * CODE_STRW];
            int sum = 0;
            #pragma unroll
            for (int k = 0; k < 32; k++) sum = __dp4a((int)cr[k], ONEB, sum);
            codes[t * CODE_STRW + 32] = (uint32_t)sum;
            g_rowsum[r0 + t] = sum;
        }
        __syncthreads();

        uint32_t a[16];
        #pragma unroll
        for (int kc = 0; kc < 4; kc++)
            ldsm_x4(a[kc * 4], a[kc * 4 + 1], a[kc * 4 + 2], a[kc * 4 + 3],
                    ldA_base + kc * 32);
        int rs_lo = (int)codes[(w * 16 + (lane >> 2)) * CODE_STRW + 32];
        int rs_hi = (int)codes[(w * 16 + (lane >> 2) + 8) * CODE_STRW + 32];

        #pragma unroll
        for (int g = 0; g < 4; g++) {
            float al = alsm[g];
            int   zw = zwsm[g];
            float mn = 1e30f, mx = -1e30f;
            #pragma unroll 2
            for (int ntg = 0; ntg < 8; ntg++) {
                int nt = g * 8 + ntg;
                int C[4] = {0, 0, 0, 0};
                #pragma unroll
                for (int kc = 0; kc < 4; kc++) {
                    uint32_t b0, b1;
                    ldsm_x2(b0, b1, ldB_base + nt * 1024 + kc * 32);
                    mma_s8(C, a[kc * 4], a[kc * 4 + 1], a[kc * 4 + 2], a[kc * 4 + 3],
                           b0, b1);
                }
                int col0 = nt * 8 + 2 * (lane & 3);
                int co0 = cosm[col0], co1 = cosm[col0 + 1];
                float bo0 = bosm[col0], bo1 = bosm[col0 + 1];
                float G0 = __fadd_rn(__fmul_rn((float)(C[0] - zw * rs_lo + co0), al), bo0);
                float G1 = __fadd_rn(__fmul_rn((float)(C[1] - zw * rs_lo + co1), al), bo1);
                float G2 = __fadd_rn(__fmul_rn((float)(C[2] - zw * rs_hi + co0), al), bo0);
                float G3 = __fadd_rn(__fmul_rn((float)(C[3] - zw * rs_hi + co1), al), bo1);
                mn = fminf(mn, fminf(fminf(G0, G1), fminf(G2, G3)));
                mx = fmaxf(mx, fmaxf(fmaxf(G0, G1), fmaxf(G2, G3)));
            }
            mnG[g] = fminf(mnG[g], mn);
            mxG[g] = fmaxf(mxG[g], mx);
        }
        __syncthreads();
    }
    #pragma unroll
    for (int g = 0; g < 4; g++) {
        float mn = mnG[g], mx = mxG[g];
        #pragma unroll
        for (int o = 16; o; o >>= 1) {
            mn = fminf(mn, __shfl_xor_sync(0xffffffffu, mn, o));
            mx = fmaxf(mx, __shfl_xor_sync(0xffffffffu, mx, o));
        }
        if (lane == 0) {
            atomicMin(&g_mm[6 + 2 * g], fenc(mn));
            atomicMax(&g_mm[7 + 2 * g], fenc(mx));
        }
    }
}

// ---------- K4: gate + activation params ----------
__global__ void k_p2() {
    for (int g = 0; g < 4; g++) {
        float mn = fdec(g_mm[6 + 2 * g]), mx = fdec(g_mm[7 + 2 * g]);
        mkparams(mn, mx, &g_p.sG[g], &g_p.zpG[g]);
        float lo = fqv(mn, g_p.sG[g], g_p.zpG[g]);
        float hi = fqv(mx, g_p.sG[g], g_p.zpG[g]);
        float amin, amax;
        if (g < 3) { amin = hsig(lo); amax = hsig(hi); }
        else       { amin = htanh(lo); amax = htanh(hi); }
        mkparams(amin, amax, &g_p.sA[g], &g_p.zpA[g]);
    }
}

// ---------- K3b: pass B — MMA from stored codes, activations, fc/ic minmax ----------
__global__ void __launch_bounds__(256) k_gemmB() {
    extern __shared__ uint8_t dyn[];
    uint32_t* Wsm32 = (uint32_t*)dyn;
    uint32_t* codes = (uint32_t*)(dyn + W_BYTES);   // union with sact (disjoint lifetime)
    int8_t*   sact  = (int8_t*)(dyn + W_BYTES);
    __shared__ int   cosm[256];
    __shared__ float bosm[256];
    __shared__ float alsm[4], sGsm[4], zGsm[4], sAsm[4], zAsm[4];
    __shared__ int   zwsm[4];
    int t = threadIdx.x, lane = t & 31, w = t >> 5;

    const uint32_t* wq32 = (const uint32_t*)g_wq;
    #pragma unroll
    for (int i = 0; i < 32; i++) Wsm32[t + i * 256] = wq32[t + i * 256];
    cosm[t] = g_const[t];
    bosm[t] = g_p.bdq[t];
    if (t < 4) {
        alsm[t] = g_p.alpha[t]; zwsm[t] = g_p.zpw_i[t];
        sGsm[t] = g_p.sG[t];    zGsm[t] = g_p.zpG[t];
        sAsm[t] = g_p.sA[t];    zAsm[t] = g_p.zpA[t];
    }
    float sAi = g_p.sA[0], zAi = g_p.zpA[0], sAf = g_p.sA[1], zAf = g_p.zpA[1];
    float sAc = g_p.sA[3], zAc = g_p.zpA[3];
    float scc = g_p.s_c, zcc = g_p.zp_c;

    uint32_t Waddr = (uint32_t)__cvta_generic_to_shared(Wsm32);
    uint32_t Caddr = (uint32_t)__cvta_generic_to_shared(codes);
    uint32_t ldB_base = Waddr + (lane & 7) * 128 + ((lane >> 3) & 1) * 16;
    uint32_t ldA_base = Caddr + (w * 16 + (lane & 15)) * 144 + (lane >> 4) * 16;
    int rlo = w * 16 + (lane >> 2);
    const uint32_t* cq32 = (const uint32_t*)g_cq;

    float mn1 = 1e30f, mx1 = -1e30f, mn2 = 1e30f, mx2 = -1e30f;
    __syncthreads();

    for (int tile = blockIdx.x; tile < NT128; tile += gridDim.x) {
        long r0 = (long)tile * 128;
        // load codes + rowsums into smem
        #pragma unroll
        for (int i = 0; i < 16; i++) {
            int idx = t + i * 256;                 // 4096 words
            codes[(idx >> 5) * CODE_STRW + (idx & 31)] = g_catq[r0 * 32 + idx];
        }
        if (t < 128) codes[t * CODE_STRW + 32] = (uint32_t)g_rowsum[r0 + t];
        __syncthreads();

        uint32_t a[16];
        #pragma unroll
        for (int kc = 0; kc < 4; kc++)
            ldsm_x4(a[kc * 4], a[kc * 4 + 1], a[kc * 4 + 2], a[kc * 4 + 3],
                    ldA_base + kc * 32);
        int rs_lo = (int)codes[(w * 16 + (lane >> 2)) * CODE_STRW + 32];
        int rs_hi = (int)codes[(w * 16 + (lane >> 2) + 8) * CODE_STRW + 32];
        __syncthreads();   // codes region now reused as sact

        #pragma unroll
        for (int g = 0; g < 4; g++) {
            float al = alsm[g];
            int   zw = zwsm[g];
            float sGg = sGsm[g], zGg = zGsm[g], sAg = sAsm[g], zAg = zAsm[g];
            #pragma unroll 2
            for (int ntg = 0; ntg < 8; ntg++) {
                int nt = g * 8 + ntg;
                int C[4] = {0, 0, 0, 0};
                #pragma unroll
                for (int kc = 0; kc < 4; kc++) {
                    uint32_t b0, b1;
                    ldsm_x2(b0, b1, ldB_base + nt * 1024 + kc * 32);
                    mma_s8(C, a[kc * 4], a[kc * 4 + 1], a[kc * 4 + 2], a[kc * 4 + 3],
                           b0, b1);
                }
                int col0 = nt * 8 + 2 * (lane & 3);
                int co0 = cosm[col0], co1 = cosm[col0 + 1];
                float bo0 = bosm[col0], bo1 = bosm[col0 + 1];
                float G0 = __fadd_rn(__fmul_rn((float)(C[0] - zw * rs_lo + co0), al), bo0);
                float G1 = __fadd_rn(__fmul_rn((float)(C[1] - zw * rs_lo + co1), al), bo1);
                float G2 = __fadd_rn(__fmul_rn((float)(C[2] - zw * rs_hi + co0), al), bo0);
                float G3 = __fadd_rn(__fmul_rn((float)(C[3] - zw * rs_hi + co1), al), bo1);
                float v0 = fqv(G0, sGg, zGg), v1 = fqv(G1, sGg, zGg);
                float v2 = fqv(G2, sGg, zGg), v3 = fqv(G3, sGg, zGg);
                float a0, a1, a2, a3;
                if (g < 3) { a0 = hsig(v0); a1 = hsig(v1); a2 = hsig(v2); a3 = hsig(v3); }
                else       { a0 = htanh(v0); a1 = htanh(v1); a2 = htanh(v2); a3 = htanh(v3); }
                char2 lo2, hi2;
                lo2.x = (int8_t)(int)quant_q(a0, sAg, zAg);
                lo2.y = (int8_t)(int)quant_q(a1, sAg, zAg);
                hi2.x = (int8_t)(int)quant_q(a2, sAg, zAg);
                hi2.y = (int8_t)(int)quant_q(a3, sAg, zAg);
                *(char2*)&sact[rlo * SACT_STR + col0]       = lo2;
                *(char2*)&sact[(rlo + 8) * SACT_STR + col0] = hi2;
            }
        }
        __syncthreads();

        // coalesced store of act codes: 8192 words total
        #pragma unroll
        for (int i = 0; i < 32; i++) {
            int idx = t + i * 256;
            int g = idx >> 11, rem = idx & 2047, row = rem >> 4, w4 = rem & 15;
            uint32_t val = *(const uint32_t*)&sact[row * SACT_STR + g * 64 + w4 * 4];
            *(uint32_t*)&g_act[g][(r0 + row) * 64 + w4 * 4] = val;
        }
        // fc/ic minmax: 2048 word-groups of 4 elements
        #pragma unroll
        for (int i = 0; i < 8; i++) {
            int idx = t + i * 256;
            int row = idx >> 4, w4 = idx & 15;
            uint32_t wi = *(const uint32_t*)&sact[row * SACT_STR + 0 * 64 + w4 * 4];
            uint32_t wf = *(const uint32_t*)&sact[row * SACT_STR + 1 * 64 + w4 * 4];
            uint32_t wg = *(const uint32_t*)&sact[row * SACT_STR + 3 * 64 + w4 * 4];
            uint32_t wc = cq32[r0 * 16 + idx];
            #pragma unroll
            for (int b = 0; b < 4; b++) {
                int qi = (int)(int8_t)(wi >> (8 * b));
                int qf = (int)(int8_t)(wf >> (8 * b));
                int qg = (int)(int8_t)(wg >> (8 * b));
                int qc = (int)(int8_t)(wc >> (8 * b));
                float fv = __fmul_rn((float)qf - zAf, sAf);
                float iv = __fmul_rn((float)qi - zAi, sAi);
                float gv = __fmul_rn((float)qg - zAc, sAc);
                float cd = __fmul_rn((float)qc - zcc, scc);
                float fc = __fmul_rn(fv, cd);
                float ic = __fmul_rn(iv, gv);
                mn1 = fminf(mn1, fc); mx1 = fmaxf(mx1, fc);
                mn2 = fminf(mn2, ic); mx2 = fmaxf(mx2, ic);
            }
        }
        __syncthreads();
    }
    block_minmax(mn1, mx1, &g_mm[14], &g_mm[15]);
    block_minmax(mn2, mx2, &g_mm[16], &g_mm[17]);
}

// ---------- K6 ----------
__global__ void k_p3() {
    mkparams(fdec(g_mm[14]), fdec(g_mm[15]), &g_p.s_fc, &g_p.zp_fc);
    mkparams(fdec(g_mm[16]), fdec(g_mm[17]), &g_p.s_ic, &g_p.zp_ic);
}

// ---------- K7: minmax of fq(fc)+fq(ic) ----------
__global__ void k_pre() {
    float sAi = g_p.sA[0], zAi = g_p.zpA[0], sAf = g_p.sA[1], zAf = g_p.zpA[1];
    float sAg = g_p.sA[3], zAg = g_p.zpA[3], scc = g_p.s_c, zcc = g_p.zp_c;
    float sfc = g_p.s_fc, zfc = g_p.zp_fc, sic = g_p.s_ic, zic = g_p.zp_ic;
    float mn = 1e30f, mx = -1e30f;
    for (long i = blockIdx.x * blockDim.x + threadIdx.x; i < NE / 4;
         i += (long)gridDim.x * blockDim.x) {
        char4 qi = ((const char4*)g_act[0])[i];
        char4 qf = ((const char4*)g_act[1])[i];
        char4 qg = ((const char4*)g_act[3])[i];
        char4 qc = ((const char4*)g_cq)[i];
        int ii[4] = {qi.x, qi.y, qi.z, qi.w}, ff[4] = {qf.x, qf.y, qf.z, qf.w};
        int gg[4] = {qg.x, qg.y, qg.z, qg.w}, cc[4] = {qc.x, qc.y, qc.z, qc.w};
        #pragma unroll
        for (int j = 0; j < 4; j++) {
            float fv = __fmul_rn((float)ff[j] - zAf, sAf);
            float iv = __fmul_rn((float)ii[j] - zAi, sAi);
            float gv = __fmul_rn((float)gg[j] - zAg, sAg);
            float cd = __fmul_rn((float)cc[j] - zcc, scc);
            float fcv = fqv(__fmul_rn(fv, cd), sfc, zfc);
            float icv = fqv(__fmul_rn(iv, gv), sic, zic);
            float pre = __fadd_rn(fcv, icv);
            mn = fminf(mn, pre); mx = fmaxf(mx, pre);
        }
    }
    block_minmax(mn, mx, &g_mm[18], &g_mm[19]);
}

// ---------- K8 ----------
__global__ void k_p4() {
    float mn = fdec(g_mm[18]), mx = fdec(g_mm[19]);
    mkparams(mn, mx, &g_p.s_cn, &g_p.zp_cn);
    float lo = htanh(fqv(mn, g_p.s_cn, g_p.zp_cn));
    float hi = htanh(fqv(mx, g_p.s_cn, g_p.zp_cn));
    mkparams(lo, hi, &g_p.s_t, &g_p.zp_t);
}

// ---------- K9: write c_next, store t codes, minmax(o*t) ----------
__global__ void k_cnext(float* __restrict__ out_c) {
    float sAi = g_p.sA[0], zAi = g_p.zpA[0], sAf = g_p.sA[1], zAf = g_p.zpA[1];
    float sAo = g_p.sA[2], zAo = g_p.zpA[2], sAg = g_p.sA[3], zAg = g_p.zpA[3];
    float scc = g_p.s_c, zcc = g_p.zp_c;
    float sfc = g_p.s_fc, zfc = g_p.zp_fc, sic = g_p.s_ic, zic = g_p.zp_ic;
    float scn = g_p.s_cn, zcn = g_p.zp_cn, st = g_p.s_t, zt = g_p.zp_t;
    float mn = 1e30f, mx = -1e30f;
    for (long i = blockIdx.x * blockDim.x + threadIdx.x; i < NE / 4;
         i += (long)gridDim.x * blockDim.x) {
        char4 qi = ((const char4*)g_act[0])[i];
        char4 qf = ((const char4*)g_act[1])[i];
        char4 qo = ((const char4*)g_act[2])[i];
        char4 qg = ((const char4*)g_act[3])[i];
        char4 qc = ((const char4*)g_cq)[i];
        int ii[4] = {qi.x, qi.y, qi.z, qi.w}, ff[4] = {qf.x, qf.y, qf.z, qf.w};
        int oo[4] = {qo.x, qo.y, qo.z, qo.w}, gg[4] = {qg.x, qg.y, qg.z, qg.w};
        int cc[4] = {qc.x, qc.y, qc.z, qc.w};
        float4 outc;
        float* oc = (float*)&outc;
        char4 tq4;
        int8_t* tqq = (int8_t*)&tq4;
        #pragma unroll
        for (int j = 0; j < 4; j++) {
            float fv = __fmul_rn((float)ff[j] - zAf, sAf);
            float iv = __fmul_rn((float)ii[j] - zAi, sAi);
            float gv = __fmul_rn((float)gg[j] - zAg, sAg);
            float cd = __fmul_rn((float)cc[j] - zcc, scc);
            float fcv = fqv(__fmul_rn(fv, cd), sfc, zfc);
            float icv = fqv(__fmul_rn(iv, gv), sic, zic);
            float pre = __fadd_rn(fcv, icv);
            float cn = fqv(pre, scn, zcn);
            oc[j] = cn;
            int tcode = (int)quant_q(htanh(cn), st, zt);
            tqq[j] = (int8_t)tcode;
            float tv = __fmul_rn((float)tcode - zt, st);
            float ov = __fmul_rn((float)oo[j] - zAo, sAo);
            float hp = __fmul_rn(ov, tv);
            mn = fminf(mn, hp); mx = fmaxf(mx, hp);
        }
        ((float4*)out_c)[i] = outc;
        ((char4*)g_tq)[i] = tq4;
    }
    block_minmax(mn, mx, &g_mm[20], &g_mm[21]);
}

// ---------- K10 ----------
__global__ void k_p5() {
    mkparams(fdec(g_mm[20]), fdec(g_mm[21]), &g_p.s_hn, &g_p.zp_hn);
}

// ---------- K11: h_next ----------
__global__ void k_hnext(float* __restrict__ out_h) {
    float sAo = g_p.sA[2], zAo = g_p.zpA[2], st = g_p.s_t, zt = g_p.zp_t;
    float shn = g_p.s_hn, zhn = g_p.zp_hn;
    for (long i = blockIdx.x * blockDim.x + threadIdx.x; i < NE / 4;
         i += (long)gridDim.x * blockDim.x) {
        char4 qo = ((const char4*)g_act[2])[i];
        char4 qt = ((const char4*)g_tq)[i];
        int oo[4] = {qo.x, qo.y, qo.z, qo.w}, tt[4] = {qt.x, qt.y, qt.z, qt.w};
        float4 outh;
        float* oh = (float*)&outh;
        #pragma unroll
        for (int j = 0; j < 4; j++) {
            float ov = __fmul_rn((float)oo[j] - zAo, sAo);
            float tv = __fmul_rn((float)tt[j] - zt, st);
            oh[j] = fqv(__fmul_rn(ov, tv), shn, zhn);
        }
        ((float4*)out_h)[i] = outh;
    }
}

extern "C" void kernel_launch(void* const* d_in, const int* in_sizes, int n_in,
                              void* d_out, int out_size) {
    const float* x  = (const float*)d_in[0];
    const float* h  = (const float*)d_in[1];
    const float* c  = (const float*)d_in[2];
    const float* Wi = (const float*)d_in[3];
    const float* bi = (const float*)d_in[4];
    const float* Wf = (const float*)d_in[5];
    const float* bf = (const float*)d_in[6];
    const float* Wo = (const float*)d_in[7];
    const float* bo = (const float*)d_in[8];
    const float* Wc = (const float*)d_in[9];
    const float* bc = (const float*)d_in[10];
    float* out_h = (float*)d_out;
    float* out_c = (float*)d_out + NE;

    static int attr_done = 0;
    if (!attr_done) {
        cudaFuncSetAttribute(k_gemmA, cudaFuncAttributeMaxDynamicSharedMemorySize, DYN_A);
        cudaFuncSetAttribute(k_gemmB, cudaFuncAttributeMaxDynamicSharedMemorySize, DYN_B);
        attr_done = 1;
    }

    k_init<<<1, 32>>>();
    k_minmax3<<<2048, 256>>>(x, h, c);
    k_params<<<1, 256>>>(Wi, bi, Wf, bf, Wo, bo, Wc, bc);
    k_quantc<<<4096, 256>>>(c);
    k_gemmA<<<2048, 256, DYN_A>>>(x, h);
    k_p2<<<1, 1>>>();
    k_gemmB<<<2048, 256, DYN_B>>>();
    k_p3<<<1, 1>>>();
    k_pre<<<8192, 256>>>();
    k_p4<<<1, 1>>>();
    k_cnext<<<8192, 256>>>(out_c);
    k_p5<<<1, 1>>>();
    k_hnext<<<8192, 256>>>(out_h);
}

// round 7
// speedup vs baseline: 6.0514x; 1.4851x over previous
#include <cuda_runtime.h>
#include <stdint.h>

#define R_TOT 524288
#define NE    33554432
#define NT128 4096            // R_TOT / 128 rows per macro-tile
#define ONEB  0x01010101

struct Params {
    float s_x, zp_x, s_h, zp_h, s_c, zp_c, s_cat, zp_cat;
    float r_x, r_h, r_c, r_cat;
    float alpha[4];
    float bdq[256];
    int   zpw_i[4], zpc_i;
    float sG[4], zpG[4], sA[4], zpA[4];
    float rG[4], rA[4];
    float s_fc, zp_fc, s_ic, zp_ic, s_cn, zp_cn, s_t, zp_t, s_hn, zp_hn;
    float r_fc, r_ic, r_cn, r_t, r_hn;
};

__device__ Params   g_p;
__device__ unsigned g_mm[22];            // 11 (min,max) encoded-float slots
__device__ int8_t   g_wq[256 * 128];     // quantized weight codes [col][k]
__device__ int      g_const[256];        // per-output zero-point correction
__device__ uint32_t g_catq[R_TOT * 32];  // packed cat codes (64 MB)
__device__ int      g_rowsum[R_TOT];     // per-row code sums (2 MB)
__device__ int8_t   g_act[4][NE];        // i,f,o,cg activation codes
__device__ int8_t   g_cq[NE];            // c_prev codes
__device__ int8_t   g_tq[NE];            // tanh(c_next) codes

// ---------- helpers ----------
__device__ __forceinline__ unsigned fenc(float f) {
    unsigned u = __float_as_uint(f);
    return (u & 0x80000000u) ? ~u : (u | 0x80000000u);
}
__device__ __forceinline__ float fdec(unsigned u) {
    return __uint_as_float((u & 0x80000000u) ? (u & 0x7fffffffu) : ~u);
}
// reciprocal-multiply quantize: q = clip(rint(v*rs)+zp, -128, 127)
__device__ __forceinline__ float quant_qm(float v, float rs, float zp) {
    float q = rintf(__fmul_rn(v, rs)) + zp;
    return fminf(fmaxf(q, -128.f), 127.f);
}
__device__ __forceinline__ float fqvm(float v, float s, float rs, float zp) {
    return __fmul_rn(quant_qm(v, rs, zp) - zp, s);
}
__device__ __forceinline__ void mkparams(float mnr, float mxr, float* s, float* zp) {
    float mn = fminf(mnr, 0.f), mx = fmaxf(mxr, 0.f);
    float sc = fmaxf(__fdiv_rn(mx - mn, 255.f), 1e-8f);
    float z  = rintf(-128.f - __fdiv_rn(mn, sc));
    *s = sc; *zp = fminf(fmaxf(z, -128.f), 127.f);
}
#define HSIG_C 0.16666667f
__device__ __forceinline__ float hsig(float v) {
    return fminf(fmaxf(__fadd_rn(__fmul_rn(v, HSIG_C), 0.5f), 0.f), 1.f);
}
__device__ __forceinline__ float htanh(float v) { return fminf(fmaxf(v, -1.f), 1.f); }

__device__ __forceinline__ void block_minmax(float mn, float mx, unsigned* gmin, unsigned* gmax) {
    #pragma unroll
    for (int o = 16; o; o >>= 1) {
        mn = fminf(mn, __shfl_xor_sync(0xffffffffu, mn, o));
        mx = fmaxf(mx, __shfl_xor_sync(0xffffffffu, mx, o));
    }
    __shared__ float smn[8], smx[8];
    int w = threadIdx.x >> 5, nw = blockDim.x >> 5;
    __syncthreads();
    if ((threadIdx.x & 31) == 0) { smn[w] = mn; smx[w] = mx; }
    __syncthreads();
    if (threadIdx.x == 0) {
        for (int i = 1; i < nw; i++) { mn = fminf(mn, smn[i]); mx = fmaxf(mx, smx[i]); }
        atomicMin(gmin, fenc(mn));
        atomicMax(gmax, fenc(mx));
    }
    __syncthreads();
}

__device__ __forceinline__ float2 block_reduce_pair(float mn, float mx) {
    #pragma unroll
    for (int o = 16; o; o >>= 1) {
        mn = fminf(mn, __shfl_xor_sync(0xffffffffu, mn, o));
        mx = fmaxf(mx, __shfl_xor_sync(0xffffffffu, mx, o));
    }
    __shared__ float smn[8], smx[8];
    __shared__ float2 res;
    int w = threadIdx.x >> 5, nw = blockDim.x >> 5;
    __syncthreads();
    if ((threadIdx.x & 31) == 0) { smn[w] = mn; smx[w] = mx; }
    __syncthreads();
    if (threadIdx.x == 0) {
        for (int i = 1; i < nw; i++) { mn = fminf(mn, smn[i]); mx = fmaxf(mx, smx[i]); }
        res = make_float2(mn, mx);
    }
    __syncthreads();
    return res;
}

__device__ __forceinline__ void mma_s8(int* c, uint32_t a0, uint32_t a1, uint32_t a2,
                                       uint32_t a3, uint32_t b0, uint32_t b1) {
    asm volatile(
        "mma.sync.aligned.m16n8k32.row.col.s32.s8.s8.s32 "
        "{%0,%1,%2,%3}, {%4,%5,%6,%7}, {%8,%9}, {%0,%1,%2,%3};\n"
        : "+r"(c[0]), "+r"(c[1]), "+r"(c[2]), "+r"(c[3])
        : "r"(a0), "r"(a1), "r"(a2), "r"(a3), "r"(b0), "r"(b1));
}
__device__ __forceinline__ void ldsm_x4(uint32_t& r0, uint32_t& r1, uint32_t& r2,
                                        uint32_t& r3, uint32_t addr) {
    asm volatile("ldmatrix.sync.aligned.m8n8.x4.shared.b16 {%0,%1,%2,%3}, [%4];"
                 : "=r"(r0), "=r"(r1), "=r"(r2), "=r"(r3) : "r"(addr));
}
__device__ __forceinline__ void ldsm_x2(uint32_t& r0, uint32_t& r1, uint32_t addr) {
    asm volatile("ldmatrix.sync.aligned.m8n8.x2.shared.b16 {%0,%1}, [%2];"
                 : "=r"(r0), "=r"(r1) : "r"(addr));
}

// ---------- K0 ----------
__global__ void k_init() {
    int t = threadIdx.x;
    if (t < 11) { g_mm[2 * t] = fenc(1e30f); g_mm[2 * t + 1] = fenc(-1e30f); }
}

// ---------- K1: minmax of x, h, c ----------
__global__ void k_minmax3(const float* __restrict__ x, const float* __restrict__ h,
                          const float* __restrict__ c) {
    const float* arrs[3] = {x, h, c};
    for (int a = 0; a < 3; a++) {
        float mn = 1e30f, mx = -1e30f;
        const float4* p = (const float4*)arrs[a];
        for (long i = blockIdx.x * blockDim.x + threadIdx.x; i < NE / 4;
             i += (long)gridDim.x * blockDim.x) {
            float4 v = p[i];
            mn = fminf(fminf(fminf(mn, v.x), v.y), fminf(v.z, v.w));
            mx = fmaxf(fmaxf(fmaxf(mx, v.x), v.y), fmaxf(v.z, v.w));
        }
        block_minmax(mn, mx, &g_mm[2 * a], &g_mm[2 * a + 1]);
    }
}

// ---------- K2: scalar params + weight/bias quantization (1 block) ----------
__global__ void k_params(const float* __restrict__ Wi, const float* __restrict__ bi,
                         const float* __restrict__ Wf, const float* __restrict__ bf,
                         const float* __restrict__ Wo, const float* __restrict__ bo,
                         const float* __restrict__ Wc, const float* __restrict__ bc) {
    __shared__ float sw, zw, rw, sb, zb, rb_;
    int t = threadIdx.x;
    if (t == 0) {
        mkparams(fdec(g_mm[0]), fdec(g_mm[1]), &g_p.s_x, &g_p.zp_x);
        mkparams(fdec(g_mm[2]), fdec(g_mm[3]), &g_p.s_h, &g_p.zp_h);
        mkparams(fdec(g_mm[4]), fdec(g_mm[5]), &g_p.s_c, &g_p.zp_c);
        g_p.r_x = __fdiv_rn(1.f, g_p.s_x);
        g_p.r_h = __fdiv_rn(1.f, g_p.s_h);
        g_p.r_c = __fdiv_rn(1.f, g_p.s_c);
        float xlo = fqvm(fdec(g_mm[0]), g_p.s_x, g_p.r_x, g_p.zp_x);
        float xhi = fqvm(fdec(g_mm[1]), g_p.s_x, g_p.r_x, g_p.zp_x);
        float hlo = fqvm(fdec(g_mm[2]), g_p.s_h, g_p.r_h, g_p.zp_h);
        float hhi = fqvm(fdec(g_mm[3]), g_p.s_h, g_p.r_h, g_p.zp_h);
        mkparams(fminf(xlo, hlo), fmaxf(xhi, hhi), &g_p.s_cat, &g_p.zp_cat);
        g_p.r_cat = __fdiv_rn(1.f, g_p.s_cat);
        g_p.zpc_i = (int)g_p.zp_cat;
    }
    __syncthreads();
    const float* Wg[4] = {Wi, Wf, Wo, Wc};
    const float* bg[4] = {bi, bf, bo, bc};
    for (int g = 0; g < 4; g++) {
        float mn = 1e30f, mx = -1e30f;
        for (int i = t; i < 8192; i += 256) {
            float v = Wg[g][i];
            mn = fminf(mn, v); mx = fmaxf(mx, v);
        }
        float2 m = block_reduce_pair(mn, mx);
        if (t == 0) {
            mkparams(m.x, m.y, &sw, &zw);
            rw = __fdiv_rn(1.f, sw);
            g_p.alpha[g] = __fmul_rn(g_p.s_cat, sw);
            g_p.zpw_i[g] = (int)zw;
        }
        __syncthreads();
        for (int i = t; i < 8192; i += 256)
            g_wq[g * 8192 + i] = (int8_t)(int)quant_qm(Wg[g][i], rw, zw);
        mn = (t < 64) ? bg[g][t] : 1e30f;
        mx = (t < 64) ? bg[g][t] : -1e30f;
        m = block_reduce_pair(mn, mx);
        if (t == 0) { mkparams(m.x, m.y, &sb, &zb); rb_ = __fdiv_rn(1.f, sb); }
        __syncthreads();
        if (t < 64) g_p.bdq[g * 64 + t] = fqvm(bg[g][t], sb, rb_, zb);
        __syncthreads();
    }
    {
        int s = 0;
        const int8_t* wr = &g_wq[t * 128];
        for (int k = 0; k < 128; k++) s += wr[k];
        int g = t >> 6;
        g_const[t] = -g_p.zpc_i * s + 128 * g_p.zpc_i * g_p.zpw_i[g];
    }
}

// ---------- K2b: quantize c_prev to codes ----------
__global__ void k_quantc(const float* __restrict__ c) {
    float rc = g_p.r_c, z = g_p.zp_c;
    for (long i = blockIdx.x * blockDim.x + threadIdx.x; i < NE / 4;
         i += (long)gridDim.x * blockDim.x) {
        float4 v = ((const float4*)c)[i];
        char4 q;
        q.x = (int8_t)(int)quant_qm(v.x, rc, z);
        q.y = (int8_t)(int)quant_qm(v.y, rc, z);
        q.z = (int8_t)(int)quant_qm(v.z, rc, z);
        q.w = (int8_t)(int)quant_qm(v.w, rc, z);
        ((char4*)g_cq)[i] = q;
    }
}

// dyn smem layout (both gemm kernels):
//   [0, 36864)   W codes, 256 cols x 144B stride (128B data + 16B pad: conflict-free LDSM)
//   [36864, ...) codes staging: 128 rows x 36 words (144B stride); word 32 = rowsum
#define W_BYTES   36864
#define W_STRB    144
#define CODE_STRW 36
#define SACT_STR  264
#define DYN_A     (W_BYTES + 128 * CODE_STRW * 4)              // 55296
#define DYN_B     (W_BYTES + 128 * SACT_STR)                   // 70656

// ---------- K3a: pass A — quantize cat, store codes+rowsum, MMA, gate minmax ----------
__global__ void __launch_bounds__(256) k_gemmA(const float* __restrict__ X,
                                               const float* __restrict__ H) {
    extern __shared__ uint8_t dyn[];
    uint32_t* codes = (uint32_t*)(dyn + W_BYTES);
    __shared__ int   cosm[256];
    __shared__ float bosm[256];
    __shared__ float alsm[4];
    __shared__ int   zwsm[4];
    int t = threadIdx.x, lane = t & 31, w = t >> 5;

    {   // W fill: one col per thread, uint4, padded stride
        const uint4* wsrc = (const uint4*)&g_wq[t * 128];
        uint4* wdst = (uint4*)(dyn + t * W_STRB);
        #pragma unroll
        for (int i = 0; i < 8; i++) wdst[i] = wsrc[i];
    }
    cosm[t] = g_const[t];
    bosm[t] = g_p.bdq[t];
    if (t < 4) { alsm[t] = g_p.alpha[t]; zwsm[t] = g_p.zpw_i[t]; }

    float sx = g_p.s_x, rx = g_p.r_x, zx = g_p.zp_x;
    float sh = g_p.s_h, rh = g_p.r_h, zh = g_p.zp_h;
    float rc = g_p.r_cat, zc = g_p.zp_cat;
    const float4* X4 = (const float4*)X;
    const float4* H4 = (const float4*)H;

    uint32_t Waddr = (uint32_t)__cvta_generic_to_shared(dyn);
    uint32_t Caddr = (uint32_t)__cvta_generic_to_shared(codes);
    uint32_t ldB_base = Waddr + (lane & 7) * W_STRB + ((lane >> 3) & 1) * 16;
    uint32_t ldA_base = Caddr + (w * 16 + (lane & 15)) * 144 + (lane >> 4) * 16;

    float mnG[4], mxG[4];
    #pragma unroll
    for (int g = 0; g < 4; g++) { mnG[g] = 1e30f; mxG[g] = -1e30f; }
    __syncthreads();

    for (int tile = blockIdx.x; tile < NT128; tile += gridDim.x) {
        long r0 = (long)tile * 128;
        #pragma unroll 4
        for (int rr = 0; rr < 16; rr++) {
            int lrow = w * 16 + rr;
            long row = r0 + lrow;
            float4 v = (lane < 16) ? X4[row * 16 + lane] : H4[row * 16 + lane - 16];
            float s0 = (lane < 16) ? sx : sh;
            float r0s = (lane < 16) ? rx : rh;
            float z0 = (lane < 16) ? zx : zh;
            int q0 = (int)quant_qm(fqvm(v.x, s0, r0s, z0), rc, zc);
            int q1 = (int)quant_qm(fqvm(v.y, s0, r0s, z0), rc, zc);
            int q2 = (int)quant_qm(fqvm(v.z, s0, r0s, z0), rc, zc);
            int q3 = (int)quant_qm(fqvm(v.w, s0, r0s, z0), rc, zc);
            uint32_t pk = (uint32_t)(q0 & 255) | ((uint32_t)(q1 & 255) << 8) |
                          ((uint32_t)(q2 & 255) << 16) | ((uint32_t)(q3 & 255) << 24);
            codes[lrow * CODE_STRW + lane] = pk;
            g_catq[row * 32 + lane] = pk;
        }
        __syncthreads();
        if (t < 128) {
            const uint32_t* cr = &codes[t * CODE_STRW];
            int sum = 0;
            #pragma unroll
            for (int k = 0; k < 32; k++) sum = __dp4a((int)cr[k], ONEB, sum);
            codes[t * CODE_STRW + 32] = (uint32_t)sum;
            g_rowsum[r0 + t] = sum;
        }
        __syncthreads();

        uint32_t a[16];
        #pragma unroll
        for (int kc = 0; kc < 4; kc++)
            ldsm_x4(a[kc * 4], a[kc * 4 + 1], a[kc * 4 + 2], a[kc * 4 + 3],
                    ldA_base + kc * 32);
        int rs_lo = (int)codes[(w * 16 + (lane >> 2)) * CODE_STRW + 32];
        int rs_hi = (int)codes[(w * 16 + (lane >> 2) + 8) * CODE_STRW + 32];

        #pragma unroll
        for (int g = 0; g < 4; g++) {
            float al = alsm[g];
            int   zw = zwsm[g];
            float mn = 1e30f, mx = -1e30f;
            #pragma unroll 2
            for (int ntg = 0; ntg < 8; ntg++) {
                int nt = g * 8 + ntg;
                int C[4] = {0, 0, 0, 0};
                #pragma unroll
                for (int kc = 0; kc < 4; kc++) {
                    uint32_t b0, b1;
                    ldsm_x2(b0, b1, ldB_base + nt * (8 * W_STRB) + kc * 32);
                    mma_s8(C, a[kc * 4], a[kc * 4 + 1], a[kc * 4 + 2], a[kc * 4 + 3],
                           b0, b1);
                }
                int col0 = nt * 8 + 2 * (lane & 3);
                int co0 = cosm[col0], co1 = cosm[col0 + 1];
                float bo0 = bosm[col0], bo1 = bosm[col0 + 1];
                float G0 = __fadd_rn(__fmul_rn((float)(C[0] - zw * rs_lo + co0), al), bo0);
                float G1 = __fadd_rn(__fmul_rn((float)(C[1] - zw * rs_lo + co1), al), bo1);
                float G2 = __fadd_rn(__fmul_rn((float)(C[2] - zw * rs_hi + co0), al), bo0);
                float G3 = __fadd_rn(__fmul_rn((float)(C[3] - zw * rs_hi + co1), al), bo1);
                mn = fminf(mn, fminf(fminf(G0, G1), fminf(G2, G3)));
                mx = fmaxf(mx, fmaxf(fmaxf(G0, G1), fmaxf(G2, G3)));
            }
            mnG[g] = fminf(mnG[g], mn);
            mxG[g] = fmaxf(mxG[g], mx);
        }
        __syncthreads();
    }
    #pragma unroll
    for (int g = 0; g < 4; g++) {
        float mn = mnG[g], mx = mxG[g];
        #pragma unroll
        for (int o = 16; o; o >>= 1) {
            mn = fminf(mn, __shfl_xor_sync(0xffffffffu, mn, o));
            mx = fmaxf(mx, __shfl_xor_sync(0xffffffffu, mx, o));
        }
        if (lane == 0) {
            atomicMin(&g_mm[6 + 2 * g], fenc(mn));
            atomicMax(&g_mm[7 + 2 * g], fenc(mx));
        }
    }
}

// ---------- K4: gate + activation params ----------
__global__ void k_p2() {
    for (int g = 0; g < 4; g++) {
        float mn = fdec(g_mm[6 + 2 * g]), mx = fdec(g_mm[7 + 2 * g]);
        mkparams(mn, mx, &g_p.sG[g], &g_p.zpG[g]);
        g_p.rG[g] = __fdiv_rn(1.f, g_p.sG[g]);
        float lo = fqvm(mn, g_p.sG[g], g_p.rG[g], g_p.zpG[g]);
        float hi = fqvm(mx, g_p.sG[g], g_p.rG[g], g_p.zpG[g]);
        float amin, amax;
        if (g < 3) { amin = hsig(lo); amax = hsig(hi); }
        else       { amin = htanh(lo); amax = htanh(hi); }
        mkparams(amin, amax, &g_p.sA[g], &g_p.zpA[g]);
        g_p.rA[g] = __fdiv_rn(1.f, g_p.sA[g]);
    }
}

// ---------- K3b: pass B — MMA from stored codes, activations, fc/ic minmax ----------
__global__ void __launch_bounds__(256) k_gemmB() {
    extern __shared__ uint8_t dyn[];
    uint32_t* codes = (uint32_t*)(dyn + W_BYTES);   // union with sact (disjoint lifetime)
    int8_t*   sact  = (int8_t*)(dyn + W_BYTES);
    __shared__ int   cosm[256];
    __shared__ float bosm[256];
    __shared__ float alsm[4], sGsm[4], zGsm[4], rGsm[4], sAsm[4], zAsm[4], rAsm[4];
    __shared__ int   zwsm[4];
    int t = threadIdx.x, lane = t & 31, w = t >> 5;

    {
        const uint4* wsrc = (const uint4*)&g_wq[t * 128];
        uint4* wdst = (uint4*)(dyn + t * W_STRB);
        #pragma unroll
        for (int i = 0; i < 8; i++) wdst[i] = wsrc[i];
    }
    cosm[t] = g_const[t];
    bosm[t] = g_p.bdq[t];
    if (t < 4) {
        alsm[t] = g_p.alpha[t]; zwsm[t] = g_p.zpw_i[t];
        sGsm[t] = g_p.sG[t];    zGsm[t] = g_p.zpG[t];  rGsm[t] = g_p.rG[t];
        sAsm[t] = g_p.sA[t];    zAsm[t] = g_p.zpA[t];  rAsm[t] = g_p.rA[t];
    }
    float sAi = g_p.sA[0], zAi = g_p.zpA[0], sAf = g_p.sA[1], zAf = g_p.zpA[1];
    float sAc = g_p.sA[3], zAc = g_p.zpA[3];
    float scc = g_p.s_c, zcc = g_p.zp_c;

    uint32_t Waddr = (uint32_t)__cvta_generic_to_shared(dyn);
    uint32_t Caddr = (uint32_t)__cvta_generic_to_shared(codes);
    uint32_t ldB_base = Waddr + (lane & 7) * W_STRB + ((lane >> 3) & 1) * 16;
    uint32_t ldA_base = Caddr + (w * 16 + (lane & 15)) * 144 + (lane >> 4) * 16;
    int rlo = w * 16 + (lane >> 2);
    const uint32_t* cq32 = (const uint32_t*)g_cq;

    float mn1 = 1e30f, mx1 = -1e30f, mn2 = 1e30f, mx2 = -1e30f;
    __syncthreads();

    for (int tile = blockIdx.x; tile < NT128; tile += gridDim.x) {
        long r0 = (long)tile * 128;
        // load codes (uint4) + rowsums into smem
        #pragma unroll
        for (int i = 0; i < 4; i++) {
            int u = t + i * 256;                   // 1024 uint4 = 4096 words
            int row = u >> 3, part = u & 7;
            *(uint4*)(dyn + W_BYTES + row * 144 + part * 16) =
                ((const uint4*)g_catq)[r0 * 8 + u];
        }
        if (t < 128) codes[t * CODE_STRW + 32] = (uint32_t)g_rowsum[r0 + t];
        __syncthreads();

        uint32_t a[16];
        #pragma unroll
        for (int kc = 0; kc < 4; kc++)
            ldsm_x4(a[kc * 4], a[kc * 4 + 1], a[kc * 4 + 2], a[kc * 4 + 3],
                    ldA_base + kc * 32);
        int rs_lo = (int)codes[(w * 16 + (lane >> 2)) * CODE_STRW + 32];
        int rs_hi = (int)codes[(w * 16 + (lane >> 2) + 8) * CODE_STRW + 32];
        __syncthreads();   // codes region now reused as sact

        #pragma unroll
        for (int g = 0; g < 4; g++) {
            float al = alsm[g];
            int   zw = zwsm[g];
            float sGg = sGsm[g], zGg = zGsm[g], rGg = rGsm[g];
            float sAg = sAsm[g], zAg = zAsm[g], rAg = rAsm[g];
            #pragma unroll 2
            for (int ntg = 0; ntg < 8; ntg++) {
                int nt = g * 8 + ntg;
                int C[4] = {0, 0, 0, 0};
                #pragma unroll
                for (int kc = 0; kc < 4; kc++) {
                    uint32_t b0, b1;
                    ldsm_x2(b0, b1, ldB_base + nt * (8 * W_STRB) + kc * 32);
                    mma_s8(C, a[kc * 4], a[kc * 4 + 1], a[kc * 4 + 2], a[kc * 4 + 3],
                           b0, b1);
                }
                int col0 = nt * 8 + 2 * (lane & 3);
                int co0 = cosm[col0], co1 = cosm[col0 + 1];
                float bo0 = bosm[col0], bo1 = bosm[col0 + 1];
                float G0 = __fadd_rn(__fmul_rn((float)(C[0] - zw * rs_lo + co0), al), bo0);
                float G1 = __fadd_rn(__fmul_rn((float)(C[1] - zw * rs_lo + co1), al), bo1);
                float G2 = __fadd_rn(__fmul_rn((float)(C[2] - zw * rs_hi + co0), al), bo0);
                float G3 = __fadd_rn(__fmul_rn((float)(C[3] - zw * rs_hi + co1), al), bo1);
                float v0 = fqvm(G0, sGg, rGg, zGg), v1 = fqvm(G1, sGg, rGg, zGg);
                float v2 = fqvm(G2, sGg, rGg, zGg), v3 = fqvm(G3, sGg, rGg, zGg);
                float a0, a1, a2, a3;
                if (g < 3) { a0 = hsig(v0); a1 = hsig(v1); a2 = hsig(v2); a3 = hsig(v3); }
                else       { a0 = htanh(v0); a1 = htanh(v1); a2 = htanh(v2); a3 = htanh(v3); }
                char2 lo2, hi2;
                lo2.x = (int8_t)(int)quant_qm(a0, rAg, zAg);
                lo2.y = (int8_t)(int)quant_qm(a1, rAg, zAg);
                hi2.x = (int8_t)(int)quant_qm(a2, rAg, zAg);
                hi2.y = (int8_t)(int)quant_qm(a3, rAg, zAg);
                *(char2*)&sact[rlo * SACT_STR + col0]       = lo2;
                *(char2*)&sact[(rlo + 8) * SACT_STR + col0] = hi2;
            }
        }
        __syncthreads();

        // coalesced store of act codes: 8192 words total
        #pragma unroll
        for (int i = 0; i < 32; i++) {
            int idx = t + i * 256;
            int g = idx >> 11, rem = idx & 2047, row = rem >> 4, w4 = rem & 15;
            uint32_t val = *(const uint32_t*)&sact[row * SACT_STR + g * 64 + w4 * 4];
            *(uint32_t*)&g_act[g][(r0 + row) * 64 + w4 * 4] = val;
        }
        // fc/ic minmax
        #pragma unroll
        for (int i = 0; i < 8; i++) {
            int idx = t + i * 256;
            int row = idx >> 4, w4 = idx & 15;
            uint32_t wi = *(const uint32_t*)&sact[row * SACT_STR + 0 * 64 + w4 * 4];
            uint32_t wf = *(const uint32_t*)&sact[row * SACT_STR + 1 * 64 + w4 * 4];
            uint32_t wg = *(const uint32_t*)&sact[row * SACT_STR + 3 * 64 + w4 * 4];
            uint32_t wc = cq32[r0 * 16 + idx];
            #pragma unroll
            for (int b = 0; b < 4; b++) {
                int qi = (int)(int8_t)(wi >> (8 * b));
                int qf = (int)(int8_t)(wf >> (8 * b));
                int qg = (int)(int8_t)(wg >> (8 * b));
                int qc = (int)(int8_t)(wc >> (8 * b));
                float fv = __fmul_rn((float)qf - zAf, sAf);
                float iv = __fmul_rn((float)qi - zAi, sAi);
                float gv = __fmul_rn((float)qg - zAc, sAc);
                float cd = __fmul_rn((float)qc - zcc, scc);
                float fc = __fmul_rn(fv, cd);
                float ic = __fmul_rn(iv, gv);
                mn1 = fminf(mn1, fc); mx1 = fmaxf(mx1, fc);
                mn2 = fminf(mn2, ic); mx2 = fmaxf(mx2, ic);
            }
        }
        __syncthreads();
    }
    block_minmax(mn1, mx1, &g_mm[14], &g_mm[15]);
    block_minmax(mn2, mx2, &g_mm[16], &g_mm[17]);
}

// ---------- K6 ----------
__global__ void k_p3() {
    mkparams(fdec(g_mm[14]), fdec(g_mm[15]), &g_p.s_fc, &g_p.zp_fc);
    mkparams(fdec(g_mm[16]), fdec(g_mm[17]), &g_p.s_ic, &g_p.zp_ic);
    g_p.r_fc = __fdiv_rn(1.f, g_p.s_fc);
    g_p.r_ic = __fdiv_rn(1.f, g_p.s_ic);
}

// ---------- K7: minmax of fq(fc)+fq(ic) ----------
__global__ void k_pre() {
    float sAi = g_p.sA[0], zAi = g_p.zpA[0], sAf = g_p.sA[1], zAf = g_p.zpA[1];
    float sAg = g_p.sA[3], zAg = g_p.zpA[3], scc = g_p.s_c, zcc = g_p.zp_c;
    float sfc = g_p.s_fc, rfc = g_p.r_fc, zfc = g_p.zp_fc;
    float sic = g_p.s_ic, ric = g_p.r_ic, zic = g_p.zp_ic;
    float mn = 1e30f, mx = -1e30f;
    for (long i = blockIdx.x * blockDim.x + threadIdx.x; i < NE / 4;
         i += (long)gridDim.x * blockDim.x) {
        char4 qi = ((const char4*)g_act[0])[i];
        char4 qf = ((const char4*)g_act[1])[i];
        char4 qg = ((const char4*)g_act[3])[i];
        char4 qc = ((const char4*)g_cq)[i];
        int ii[4] = {qi.x, qi.y, qi.z, qi.w}, ff[4] = {qf.x, qf.y, qf.z, qf.w};
        int gg[4] = {qg.x, qg.y, qg.z, qg.w}, cc[4] = {qc.x, qc.y, qc.z, qc.w};
        #pragma unroll
        for (int j = 0; j < 4; j++) {
            float fv = __fmul_rn((float)ff[j] - zAf, sAf);
            float iv = __fmul_rn((float)ii[j] - zAi, sAi);
            float gv = __fmul_rn((float)gg[j] - zAg, sAg);
            float cd = __fmul_rn((float)cc[j] - zcc, scc);
            float fcv = fqvm(__fmul_rn(fv, cd), sfc, rfc, zfc);
            float icv = fqvm(__fmul_rn(iv, gv), sic, ric, zic);
            float pre = __fadd_rn(fcv, icv);
            mn = fminf(mn, pre); mx = fmaxf(mx, pre);
        }
    }
    block_minmax(mn, mx, &g_mm[18], &g_mm[19]);
}

// ---------- K8 ----------
__global__ void k_p4() {
    float mn = fdec(g_mm[18]), mx = fdec(g_mm[19]);
    mkparams(mn, mx, &g_p.s_cn, &g_p.zp_cn);
    g_p.r_cn = __fdiv_rn(1.f, g_p.s_cn);
    float lo = htanh(fqvm(mn, g_p.s_cn, g_p.r_cn, g_p.zp_cn));
    float hi = htanh(fqvm(mx, g_p.s_cn, g_p.r_cn, g_p.zp_cn));
    mkparams(lo, hi, &g_p.s_t, &g_p.zp_t);
    g_p.r_t = __fdiv_rn(1.f, g_p.s_t);
}

// ---------- K9: write c_next, store t codes, minmax(o*t) ----------
__global__ void k_cnext(float* __restrict__ out_c) {
    float sAi = g_p.sA[0], zAi = g_p.zpA[0], sAf = g_p.sA[1], zAf = g_p.zpA[1];
    float sAo = g_p.sA[2], zAo = g_p.zpA[2], sAg = g_p.sA[3], zAg = g_p.zpA[3];
    float scc = g_p.s_c, zcc = g_p.zp_c;
    float sfc = g_p.s_fc, rfc = g_p.r_fc, zfc = g_p.zp_fc;
    float sic = g_p.s_ic, ric = g_p.r_ic, zic = g_p.zp_ic;
    float scn = g_p.s_cn, rcn = g_p.r_cn, zcn = g_p.zp_cn;
    float st = g_p.s_t, rt = g_p.r_t, zt = g_p.zp_t;
    float mn = 1e30f, mx = -1e30f;
    for (long i = blockIdx.x * blockDim.x + threadIdx.x; i < NE / 4;
         i += (long)gridDim.x * blockDim.x) {
        char4 qi = ((const char4*)g_act[0])[i];
        char4 qf = ((const char4*)g_act[1])[i];
        char4 qo = ((const char4*)g_act[2])[i];
        char4 qg = ((const char4*)g_act[3])[i];
        char4 qc = ((const char4*)g_cq)[i];
        int ii[4] = {qi.x, qi.y, qi.z, qi.w}, ff[4] = {qf.x, qf.y, qf.z, qf.w};
        int oo[4] = {qo.x, qo.y, qo.z, qo.w}, gg[4] = {qg.x, qg.y, qg.z, qg.w};
        int cc[4] = {qc.x, qc.y, qc.z, qc.w};
        float4 outc;
        float* oc = (float*)&outc;
        char4 tq4;
        int8_t* tqq = (int8_t*)&tq4;
        #pragma unroll
        for (int j = 0; j < 4; j++) {
            float fv = __fmul_rn((float)ff[j] - zAf, sAf);
            float iv = __fmul_rn((float)ii[j] - zAi, sAi);
            float gv = __fmul_rn((float)gg[j] - zAg, sAg);
            float cd = __fmul_rn((float)cc[j] - zcc, scc);
            float fcv = fqvm(__fmul_rn(fv, cd), sfc, rfc, zfc);
            float icv = fqvm(__fmul_rn(iv, gv), sic, ric, zic);
            float pre = __fadd_rn(fcv, icv);
            float cn = fqvm(pre, scn, rcn, zcn);
            oc[j] = cn;
            int tcode = (int)quant_qm(htanh(cn), rt, zt);
            tqq[j] = (int8_t)tcode;
            float tv = __fmul_rn((float)tcode - zt, st);
            float ov = __fmul_rn((float)oo[j] - zAo, sAo);
            float hp = __fmul_rn(ov, tv);
            mn = fminf(mn, hp); mx = fmaxf(mx, hp);
        }
        ((float4*)out_c)[i] = outc;
        ((char4*)g_tq)[i] = tq4;
    }
    block_minmax(mn, mx, &g_mm[20], &g_mm[21]);
}

// ---------- K10 ----------
__global__ void k_p5() {
    mkparams(fdec(g_mm[20]), fdec(g_mm[21]), &g_p.s_hn, &g_p.zp_hn);
    g_p.r_hn = __fdiv_rn(1.f, g_p.s_hn);
}

// ---------- K11: h_next ----------
__global__ void k_hnext(float* __restrict__ out_h) {
    float sAo = g_p.sA[2], zAo = g_p.zpA[2], st = g_p.s_t, zt = g_p.zp_t;
    float shn = g_p.s_hn, rhn = g_p.r_hn, zhn = g_p.zp_hn;
    for (long i = blockIdx.x * blockDim.x + threadIdx.x; i < NE / 4;
         i += (long)gridDim.x * blockDim.x) {
        char4 qo = ((const char4*)g_act[2])[i];
        char4 qt = ((const char4*)g_tq)[i];
        int oo[4] = {qo.x, qo.y, qo.z, qo.w}, tt[4] = {qt.x, qt.y, qt.z, qt.w};
        float4 outh;
        float* oh = (float*)&outh;
        #pragma unroll
        for (int j = 0; j < 4; j++) {
            float ov = __fmul_rn((float)oo[j] - zAo, sAo);
            float tv = __fmul_rn((float)tt[j] - zt, st);
            oh[j] = fqvm(__fmul_rn(ov, tv), shn, rhn, zhn);
        }
        ((float4*)out_h)[i] = outh;
    }
}

extern "C" void kernel_launch(void* const* d_in, const int* in_sizes, int n_in,
                              void* d_out, int out_size) {
    const float* x  = (const float*)d_in[0];
    const float* h  = (const float*)d_in[1];
    const float* c  = (const float*)d_in[2];
    const float* Wi = (const float*)d_in[3];
    const float* bi = (const float*)d_in[4];
    const float* Wf = (const float*)d_in[5];
    const float* bf = (const float*)d_in[6];
    const float* Wo = (const float*)d_in[7];
    const float* bo = (const float*)d_in[8];
    const float* Wc = (const float*)d_in[9];
    const float* bc = (const float*)d_in[10];
    float* out_h = (float*)d_out;
    float* out_c = (float*)d_out + NE;

    static int attr_done = 0;
    if (!attr_done) {
        cudaFuncSetAttribute(k_gemmA, cudaFuncAttributeMaxDynamicSharedMemorySize, DYN_A);
        cudaFuncSetAttribute(k_gemmB, cudaFuncAttributeMaxDynamicSharedMemorySize, DYN_B);
        attr_done = 1;
    }

    k_init<<<1, 32>>>();
    k_minmax3<<<2048, 256>>>(x, h, c);
    k_params<<<1, 256>>>(Wi, bi, Wf, bf, Wo, bo, Wc, bc);
    k_quantc<<<4096, 256>>>(c);
    k_gemmA<<<2048, 256, DYN_A>>>(x, h);
    k_p2<<<1, 1>>>();
    k_gemmB<<<2048, 256, DYN_B>>>();
    k_p3<<<1, 1>>>();
    k_pre<<<8192, 256>>>();
    k_p4<<<1, 1>>>();
    k_cnext<<<8192, 256>>>(out_c);
    k_p5<<<1, 1>>>();
    k_hnext<<<8192, 256>>>(out_h);
}

// round 8
// speedup vs baseline: 6.6315x; 1.0959x over previous
#include <cuda_runtime.h>
#include <stdint.h>

#define R_TOT 524288
#define NE    33554432
#define NT128 4096            // R_TOT / 128 rows per macro-tile
#define ONEB  0x01010101
#define FMG   12582912.0f     // 1.5 * 2^23 : magic rint constant

struct Params {
    float s_x, zp_x, s_h, zp_h, s_c, zp_c, s_cat, zp_cat;
    float r_x, r_h, r_c, r_cat;
    float alpha[4];
    float bdq[256];
    int   zpw_i[4], zpc_i;
    float sG[4], zpG[4], sA[4], zpA[4];
    float rG[4], rA[4];
    float kaG[4], c1G[4], c2G[4];
    float s_fc, zp_fc, s_ic, zp_ic, s_cn, zp_cn, s_t, zp_t, s_hn, zp_hn;
    float r_fc, r_ic, r_cn, r_t, r_hn;
};

__device__ Params   g_p;
__device__ unsigned g_mm[22];            // 11 (min,max) encoded-float slots
__device__ int8_t   g_wq[256 * 128];     // quantized weight codes [col][k]
__device__ int      g_const[256];        // per-output zero-point correction
__device__ float    g_kbq[256];          // per-col folded gate-quant offset
__device__ uint32_t g_catq[R_TOT * 32];  // packed cat codes (64 MB)
__device__ int      g_rowsum[R_TOT];     // per-row code sums (2 MB)
__device__ int8_t   g_act[4][NE];        // i,f,o,cg activation codes
__device__ int8_t   g_cq[NE];            // c_prev codes
__device__ int8_t   g_tq[NE];            // tanh(c_next) codes

// ---------- helpers ----------
__device__ __forceinline__ unsigned fenc(float f) {
    unsigned u = __float_as_uint(f);
    return (u & 0x80000000u) ? ~u : (u | 0x80000000u);
}
__device__ __forceinline__ float fdec(unsigned u) {
    return __uint_as_float((u & 0x80000000u) ? (u & 0x7fffffffu) : ~u);
}
__device__ __forceinline__ float clip128(float x) {
    return fminf(fmaxf(x, -128.f), 127.f);
}
// quantize code value as float: rint(clip(fma(v,rs,zp)))  [== clip(rint(v*rs)+zp)]
__device__ __forceinline__ float quant_qm(float v, float rs, float zp) {
    float x = clip128(__fmaf_rn(v, rs, zp));
    return __fadd_rn(__fadd_rn(x, FMG), -FMG);
}
// quantize to raw byte in bits[0:8]
__device__ __forceinline__ uint32_t quant_qb(float v, float rs, float zp) {
    float x = clip128(__fmaf_rn(v, rs, zp));
    return __float_as_uint(__fadd_rn(x, FMG));
}
__device__ __forceinline__ float fqvm(float v, float s, float rs, float zp) {
    return __fmul_rn(quant_qm(v, rs, zp) - zp, s);
}
__device__ __forceinline__ void mkparams(float mnr, float mxr, float* s, float* zp) {
    float mn = fminf(mnr, 0.f), mx = fmaxf(mxr, 0.f);
    float sc = fmaxf(__fdiv_rn(mx - mn, 255.f), 1e-8f);
    float z  = rintf(-128.f - __fdiv_rn(mn, sc));
    *s = sc; *zp = fminf(fmaxf(z, -128.f), 127.f);
}
#define HSIG_C 0.16666667f
__device__ __forceinline__ float hsig(float v) {
    return fminf(fmaxf(__fadd_rn(__fmul_rn(v, HSIG_C), 0.5f), 0.f), 1.f);
}
__device__ __forceinline__ float htanh(float v) { return fminf(fmaxf(v, -1.f), 1.f); }

__device__ __forceinline__ void block_minmax(float mn, float mx, unsigned* gmin, unsigned* gmax) {
    #pragma unroll
    for (int o = 16; o; o >>= 1) {
        mn = fminf(mn, __shfl_xor_sync(0xffffffffu, mn, o));
        mx = fmaxf(mx, __shfl_xor_sync(0xffffffffu, mx, o));
    }
    __shared__ float smn[8], smx[8];
    int w = threadIdx.x >> 5, nw = blockDim.x >> 5;
    __syncthreads();
    if ((threadIdx.x & 31) == 0) { smn[w] = mn; smx[w] = mx; }
    __syncthreads();
    if (threadIdx.x == 0) {
        for (int i = 1; i < nw; i++) { mn = fminf(mn, smn[i]); mx = fmaxf(mx, smx[i]); }
        atomicMin(gmin, fenc(mn));
        atomicMax(gmax, fenc(mx));
    }
    __syncthreads();
}

__device__ __forceinline__ float2 block_reduce_pair(float mn, float mx) {
    #pragma unroll
    for (int o = 16; o; o >>= 1) {
        mn = fminf(mn, __shfl_xor_sync(0xffffffffu, mn, o));
        mx = fmaxf(mx, __shfl_xor_sync(0xffffffffu, mx, o));
    }
    __shared__ float smn[8], smx[8];
    __shared__ float2 res;
    int w = threadIdx.x >> 5, nw = blockDim.x >> 5;
    __syncthreads();
    if ((threadIdx.x & 31) == 0) { smn[w] = mn; smx[w] = mx; }
    __syncthreads();
    if (threadIdx.x == 0) {
        for (int i = 1; i < nw; i++) { mn = fminf(mn, smn[i]); mx = fmaxf(mx, smx[i]); }
        res = make_float2(mn, mx);
    }
    __syncthreads();
    return res;
}

__device__ __forceinline__ void mma_s8(int* c, uint32_t a0, uint32_t a1, uint32_t a2,
                                       uint32_t a3, uint32_t b0, uint32_t b1) {
    asm volatile(
        "mma.sync.aligned.m16n8k32.row.col.s32.s8.s8.s32 "
        "{%0,%1,%2,%3}, {%4,%5,%6,%7}, {%8,%9}, {%0,%1,%2,%3};\n"
        : "+r"(c[0]), "+r"(c[1]), "+r"(c[2]), "+r"(c[3])
        : "r"(a0), "r"(a1), "r"(a2), "r"(a3), "r"(b0), "r"(b1));
}
__device__ __forceinline__ void ldsm_x4(uint32_t& r0, uint32_t& r1, uint32_t& r2,
                                        uint32_t& r3, uint32_t addr) {
    asm volatile("ldmatrix.sync.aligned.m8n8.x4.shared.b16 {%0,%1,%2,%3}, [%4];"
                 : "=r"(r0), "=r"(r1), "=r"(r2), "=r"(r3) : "r"(addr));
}
__device__ __forceinline__ void ldsm_x2(uint32_t& r0, uint32_t& r1, uint32_t addr) {
    asm volatile("ldmatrix.sync.aligned.m8n8.x2.shared.b16 {%0,%1}, [%2];"
                 : "=r"(r0), "=r"(r1) : "r"(addr));
}

// ---------- K0 ----------
__global__ void k_init() {
    int t = threadIdx.x;
    if (t < 11) { g_mm[2 * t] = fenc(1e30f); g_mm[2 * t + 1] = fenc(-1e30f); }
}

// ---------- K1: minmax of x, h, c ----------
__global__ void k_minmax3(const float* __restrict__ x, const float* __restrict__ h,
                          const float* __restrict__ c) {
    const float* arrs[3] = {x, h, c};
    for (int a = 0; a < 3; a++) {
        float mn = 1e30f, mx = -1e30f;
        const float4* p = (const float4*)arrs[a];
        for (long i = blockIdx.x * blockDim.x + threadIdx.x; i < NE / 4;
             i += (long)gridDim.x * blockDim.x) {
            float4 v = p[i];
            mn = fminf(fminf(fminf(mn, v.x), v.y), fminf(v.z, v.w));
            mx = fmaxf(fmaxf(fmaxf(mx, v.x), v.y), fmaxf(v.z, v.w));
        }
        block_minmax(mn, mx, &g_mm[2 * a], &g_mm[2 * a + 1]);
    }
}

// ---------- K2: scalar params + weight/bias quantization (1 block) ----------
__global__ void k_params(const float* __restrict__ Wi, const float* __restrict__ bi,
                         const float* __restrict__ Wf, const float* __restrict__ bf,
                         const float* __restrict__ Wo, const float* __restrict__ bo,
                         const float* __restrict__ Wc, const float* __restrict__ bc) {
    __shared__ float sw, zw, rw, sb, zb, rb_;
    int t = threadIdx.x;
    if (t == 0) {
        mkparams(fdec(g_mm[0]), fdec(g_mm[1]), &g_p.s_x, &g_p.zp_x);
        mkparams(fdec(g_mm[2]), fdec(g_mm[3]), &g_p.s_h, &g_p.zp_h);
        mkparams(fdec(g_mm[4]), fdec(g_mm[5]), &g_p.s_c, &g_p.zp_c);
        g_p.r_x = __fdiv_rn(1.f, g_p.s_x);
        g_p.r_h = __fdiv_rn(1.f, g_p.s_h);
        g_p.r_c = __fdiv_rn(1.f, g_p.s_c);
        float xlo = fqvm(fdec(g_mm[0]), g_p.s_x, g_p.r_x, g_p.zp_x);
        float xhi = fqvm(fdec(g_mm[1]), g_p.s_x, g_p.r_x, g_p.zp_x);
        float hlo = fqvm(fdec(g_mm[2]), g_p.s_h, g_p.r_h, g_p.zp_h);
        float hhi = fqvm(fdec(g_mm[3]), g_p.s_h, g_p.r_h, g_p.zp_h);
        mkparams(fminf(xlo, hlo), fmaxf(xhi, hhi), &g_p.s_cat, &g_p.zp_cat);
        g_p.r_cat = __fdiv_rn(1.f, g_p.s_cat);
        g_p.zpc_i = (int)g_p.zp_cat;
    }
    __syncthreads();
    const float* Wg[4] = {Wi, Wf, Wo, Wc};
    const float* bg[4] = {bi, bf, bo, bc};
    for (int g = 0; g < 4; g++) {
        float mn = 1e30f, mx = -1e30f;
        for (int i = t; i < 8192; i += 256) {
            float v = Wg[g][i];
            mn = fminf(mn, v); mx = fmaxf(mx, v);
        }
        float2 m = block_reduce_pair(mn, mx);
        if (t == 0) {
            mkparams(m.x, m.y, &sw, &zw);
            rw = __fdiv_rn(1.f, sw);
            g_p.alpha[g] = __fmul_rn(g_p.s_cat, sw);
            g_p.zpw_i[g] = (int)zw;
        }
        __syncthreads();
        for (int i = t; i < 8192; i += 256)
            g_wq[g * 8192 + i] = (int8_t)(int)quant_qm(Wg[g][i], rw, zw);
        mn = (t < 64) ? bg[g][t] : 1e30f;
        mx = (t < 64) ? bg[g][t] : -1e30f;
        m = block_reduce_pair(mn, mx);
        if (t == 0) { mkparams(m.x, m.y, &sb, &zb); rb_ = __fdiv_rn(1.f, sb); }
        __syncthreads();
        if (t < 64) g_p.bdq[g * 64 + t] = fqvm(bg[g][t], sb, rb_, zb);
        __syncthreads();
    }
    {
        int s = 0;
        const int8_t* wr = &g_wq[t * 128];
        for (int k = 0; k < 128; k++) s += wr[k];
        int g = t >> 6;
        g_const[t] = -g_p.zpc_i * s + 128 * g_p.zpc_i * g_p.zpw_i[g];
    }
}

// dyn smem layout (both gemm kernels):
//   [0, 36864)   W codes, 256 cols x 144B stride (conflict-free LDSM)
//   [36864, ...) codes staging: 128 rows x 36 words (144B stride); word 32 = rowsum
#define W_BYTES   36864
#define W_STRB    144
#define CODE_STRW 36
#define SACT_STR  264
#define DYN_A     (W_BYTES + 128 * CODE_STRW * 4)              // 55296
#define DYN_B     (W_BYTES + 128 * SACT_STR)                   // 70656

// ---------- K3a: pass A — quantize cat + c, store codes+rowsum, MMA, gate minmax ----------
__global__ void __launch_bounds__(256) k_gemmA(const float* __restrict__ X,
                                               const float* __restrict__ H,
                                               const float* __restrict__ Cp) {
    extern __shared__ uint8_t dyn[];
    uint32_t* codes = (uint32_t*)(dyn + W_BYTES);
    __shared__ int   cosm[256];
    __shared__ float bosm[256];
    __shared__ float alsm[4];
    __shared__ int   zwsm[4];
    int t = threadIdx.x, lane = t & 31, w = t >> 5;

    {   // W fill: one col per thread, uint4, padded stride
        const uint4* wsrc = (const uint4*)&g_wq[t * 128];
        uint4* wdst = (uint4*)(dyn + t * W_STRB);
        #pragma unroll
        for (int i = 0; i < 8; i++) wdst[i] = wsrc[i];
    }
    cosm[t] = g_const[t];
    bosm[t] = g_p.bdq[t];
    if (t < 4) { alsm[t] = g_p.alpha[t]; zwsm[t] = g_p.zpw_i[t]; }

    float sx = g_p.s_x, rx = g_p.r_x, zx = g_p.zp_x;
    float sh = g_p.s_h, rh = g_p.r_h, zh = g_p.zp_h;
    float nzx = -__fmul_rn(zx, sx), nzh = -__fmul_rn(zh, sh);
    float rc = g_p.r_cat, zc = g_p.zp_cat;
    float rcc = g_p.r_c, zcc = g_p.zp_c;
    const float4* X4 = (const float4*)X;
    const float4* H4 = (const float4*)H;
    const float4* C4 = (const float4*)Cp;

    uint32_t Waddr = (uint32_t)__cvta_generic_to_shared(dyn);
    uint32_t Caddr = (uint32_t)__cvta_generic_to_shared(codes);
    uint32_t ldB_base = Waddr + (lane & 7) * W_STRB + ((lane >> 3) & 1) * 16;
    uint32_t ldA_base = Caddr + (w * 16 + (lane & 15)) * 144 + (lane >> 4) * 16;

    float mnG[4], mxG[4];
    #pragma unroll
    for (int g = 0; g < 4; g++) { mnG[g] = 1e30f; mxG[g] = -1e30f; }
    __syncthreads();

    for (int tile = blockIdx.x; tile < NT128; tile += gridDim.x) {
        long r0 = (long)tile * 128;
        // quantize c slice of this tile (fused former k_quantc)
        #pragma unroll
        for (int i = 0; i < 8; i++) {
            int idx = t + i * 256;                 // 2048 float4 per tile
            float4 v = C4[r0 * 16 + idx];
            uint32_t b0 = quant_qb(v.x, rcc, zcc);
            uint32_t b1 = quant_qb(v.y, rcc, zcc);
            uint32_t b2 = quant_qb(v.z, rcc, zcc);
            uint32_t b3 = quant_qb(v.w, rcc, zcc);
            uint32_t pk = __byte_perm(__byte_perm(b0, b1, 0x0040),
                                      __byte_perm(b2, b3, 0x0040), 0x5410);
            ((uint32_t*)g_cq)[r0 * 16 + idx] = pk;
        }
        // quantize cat: 16 rows per warp
        #pragma unroll 4
        for (int rr = 0; rr < 16; rr++) {
            int lrow = w * 16 + rr;
            long row = r0 + lrow;
            float4 v = (lane < 16) ? X4[row * 16 + lane] : H4[row * 16 + lane - 16];
            float s0 = (lane < 16) ? sx : sh;
            float r0s = (lane < 16) ? rx : rh;
            float z0 = (lane < 16) ? zx : zh;
            float nz0 = (lane < 16) ? nzx : nzh;
            float c0 = quant_qm(v.x, r0s, z0), c1 = quant_qm(v.y, r0s, z0);
            float c2 = quant_qm(v.z, r0s, z0), c3 = quant_qm(v.w, r0s, z0);
            uint32_t b0 = quant_qb(__fmaf_rn(c0, s0, nz0), rc, zc);
            uint32_t b1 = quant_qb(__fmaf_rn(c1, s0, nz0), rc, zc);
            uint32_t b2 = quant_qb(__fmaf_rn(c2, s0, nz0), rc, zc);
            uint32_t b3 = quant_qb(__fmaf_rn(c3, s0, nz0), rc, zc);
            uint32_t pk = __byte_perm(__byte_perm(b0, b1, 0x0040),
                                      __byte_perm(b2, b3, 0x0040), 0x5410);
            codes[lrow * CODE_STRW + lane] = pk;
            g_catq[row * 32 + lane] = pk;
        }
        __syncthreads();
        if (t < 128) {
            const uint32_t* cr = &codes[t * CODE_STRW];
            int sum = 0;
            #pragma unroll
            for (int k = 0; k < 32; k++) sum = __dp4a((int)cr[k], ONEB, sum);
            codes[t * CODE_STRW + 32] = (uint32_t)sum;
            g_rowsum[r0 + t] = sum;
        }
        __syncthreads();

        uint32_t a[16];
        #pragma unroll
        for (int kc = 0; kc < 4; kc++)
            ldsm_x4(a[kc * 4], a[kc * 4 + 1], a[kc * 4 + 2], a[kc * 4 + 3],
                    ldA_base + kc * 32);
        int rs_lo = (int)codes[(w * 16 + (lane >> 2)) * CODE_STRW + 32];
        int rs_hi = (int)codes[(w * 16 + (lane >> 2) + 8) * CODE_STRW + 32];

        #pragma unroll
        for (int g = 0; g < 4; g++) {
            float al = alsm[g];
            int   zwrs_lo = zwsm[g] * rs_lo, zwrs_hi = zwsm[g] * rs_hi;
            float mn = 1e30f, mx = -1e30f;
            #pragma unroll 4
            for (int ntg = 0; ntg < 8; ntg++) {
                int nt = g * 8 + ntg;
                int C[4] = {0, 0, 0, 0};
                #pragma unroll
                for (int kc = 0; kc < 4; kc++) {
                    uint32_t b0, b1;
                    ldsm_x2(b0, b1, ldB_base + nt * (8 * W_STRB) + kc * 32);
                    mma_s8(C, a[kc * 4], a[kc * 4 + 1], a[kc * 4 + 2], a[kc * 4 + 3],
                           b0, b1);
                }
                int col0 = nt * 8 + 2 * (lane & 3);
                int co0 = cosm[col0], co1 = cosm[col0 + 1];
                float bo0 = bosm[col0], bo1 = bosm[col0 + 1];
                float G0 = __fmaf_rn(__int2float_rn(C[0] + co0 - zwrs_lo), al, bo0);
                float G1 = __fmaf_rn(__int2float_rn(C[1] + co1 - zwrs_lo), al, bo1);
                float G2 = __fmaf_rn(__int2float_rn(C[2] + co0 - zwrs_hi), al, bo0);
                float G3 = __fmaf_rn(__int2float_rn(C[3] + co1 - zwrs_hi), al, bo1);
                mn = fminf(mn, fminf(fminf(G0, G1), fminf(G2, G3)));
                mx = fmaxf(mx, fmaxf(fmaxf(G0, G1), fmaxf(G2, G3)));
            }
            mnG[g] = fminf(mnG[g], mn);
            mxG[g] = fmaxf(mxG[g], mx);
        }
        __syncthreads();
    }
    #pragma unroll
    for (int g = 0; g < 4; g++) {
        float mn = mnG[g], mx = mxG[g];
        #pragma unroll
        for (int o = 16; o; o >>= 1) {
            mn = fminf(mn, __shfl_xor_sync(0xffffffffu, mn, o));
            mx = fmaxf(mx, __shfl_xor_sync(0xffffffffu, mx, o));
        }
        if (lane == 0) {
            atomicMin(&g_mm[6 + 2 * g], fenc(mn));
            atomicMax(&g_mm[7 + 2 * g], fenc(mx));
        }
    }
}

// ---------- K4: gate + activation params + folded constants ----------
__global__ void k_p2() {
    int t = threadIdx.x;
    if (t == 0) {
        for (int g = 0; g < 4; g++) {
            float mn = fdec(g_mm[6 + 2 * g]), mx = fdec(g_mm[7 + 2 * g]);
            mkparams(mn, mx, &g_p.sG[g], &g_p.zpG[g]);
            g_p.rG[g] = __fdiv_rn(1.f, g_p.sG[g]);
            float lo = fqvm(mn, g_p.sG[g], g_p.rG[g], g_p.zpG[g]);
            float hi = fqvm(mx, g_p.sG[g], g_p.rG[g], g_p.zpG[g]);
            float amin, amax;
            if (g < 3) { amin = hsig(lo); amax = hsig(hi); }
            else       { amin = htanh(lo); amax = htanh(hi); }
            mkparams(amin, amax, &g_p.sA[g], &g_p.zpA[g]);
            g_p.rA[g] = __fdiv_rn(1.f, g_p.sA[g]);
            g_p.kaG[g] = __fmul_rn(g_p.alpha[g], g_p.rG[g]);
            if (g < 3) {
                g_p.c1G[g] = __fmul_rn(g_p.sG[g], HSIG_C);
                g_p.c2G[g] = __fadd_rn(0.5f, -__fmul_rn(g_p.zpG[g], g_p.c1G[g]));
            } else {
                g_p.c1G[g] = g_p.sG[g];
                g_p.c2G[g] = -__fmul_rn(g_p.zpG[g], g_p.sG[g]);
            }
        }
    }
    __syncthreads();
    int g = t >> 6;
    g_kbq[t] = __fadd_rn(__fmul_rn(g_p.bdq[t], g_p.rG[g]), g_p.zpG[g]);
}

// ---------- K3b: pass B — MMA from stored codes, activations, fc/ic minmax ----------
__global__ void __launch_bounds__(256) k_gemmB() {
    extern __shared__ uint8_t dyn[];
    uint32_t* codes = (uint32_t*)(dyn + W_BYTES);   // union with sact (disjoint lifetime)
    int8_t*   sact  = (int8_t*)(dyn + W_BYTES);
    __shared__ int   cosm[256];
    __shared__ float kbsm[256];
    __shared__ float kasm[4], c1sm[4], c2sm[4], rAsm[4], zAsm[4];
    __shared__ int   zwsm[4];
    int t = threadIdx.x, lane = t & 31, w = t >> 5;

    {
        const uint4* wsrc = (const uint4*)&g_wq[t * 128];
        uint4* wdst = (uint4*)(dyn + t * W_STRB);
        #pragma unroll
        for (int i = 0; i < 8; i++) wdst[i] = wsrc[i];
    }
    cosm[t] = g_const[t];
    kbsm[t] = g_kbq[t];
    if (t < 4) {
        kasm[t] = g_p.kaG[t]; zwsm[t] = g_p.zpw_i[t];
        c1sm[t] = g_p.c1G[t]; c2sm[t] = g_p.c2G[t];
        rAsm[t] = g_p.rA[t];  zAsm[t] = g_p.zpA[t];
    }
    float sAi = g_p.sA[0], zAi = g_p.zpA[0], sAf = g_p.sA[1], zAf = g_p.zpA[1];
    float sAc = g_p.sA[3], zAc = g_p.zpA[3];
    float scc = g_p.s_c, zcc = g_p.zp_c;

    uint32_t Waddr = (uint32_t)__cvta_generic_to_shared(dyn);
    uint32_t Caddr = (uint32_t)__cvta_generic_to_shared(codes);
    uint32_t ldB_base = Waddr + (lane & 7) * W_STRB + ((lane >> 3) & 1) * 16;
    uint32_t ldA_base = Caddr + (w * 16 + (lane & 15)) * 144 + (lane >> 4) * 16;
    int rlo = w * 16 + (lane >> 2);
    const uint32_t* cq32 = (const uint32_t*)g_cq;

    float mn1 = 1e30f, mx1 = -1e30f, mn2 = 1e30f, mx2 = -1e30f;
    __syncthreads();

    for (int tile = blockIdx.x; tile < NT128; tile += gridDim.x) {
        long r0 = (long)tile * 128;
        #pragma unroll
        for (int i = 0; i < 4; i++) {
            int u = t + i * 256;                   // 1024 uint4 = 4096 words
            int row = u >> 3, part = u & 7;
            *(uint4*)(dyn + W_BYTES + row * 144 + part * 16) =
                ((const uint4*)g_catq)[r0 * 8 + u];
        }
        if (t < 128) codes[t * CODE_STRW + 32] = (uint32_t)g_rowsum[r0 + t];
        __syncthreads();

        uint32_t a[16];
        #pragma unroll
        for (int kc = 0; kc < 4; kc++)
            ldsm_x4(a[kc * 4], a[kc * 4 + 1], a[kc * 4 + 2], a[kc * 4 + 3],
                    ldA_base + kc * 32);
        int rs_lo = (int)codes[(w * 16 + (lane >> 2)) * CODE_STRW + 32];
        int rs_hi = (int)codes[(w * 16 + (lane >> 2) + 8) * CODE_STRW + 32];
        __syncthreads();   // codes region now reused as sact

        #pragma unroll
        for (int g = 0; g < 4; g++) {
            float ka = kasm[g];
            int   zwrs_lo = zwsm[g] * rs_lo, zwrs_hi = zwsm[g] * rs_hi;
            float c1 = c1sm[g], c2 = c2sm[g];
            float rA = rAsm[g], zA = zAsm[g];
            float aLo = (g < 3) ? 0.f : -1.f, aHi = 1.f;
            #pragma unroll 4
            for (int ntg = 0; ntg < 8; ntg++) {
                int nt = g * 8 + ntg;
                int C[4] = {0, 0, 0, 0};
                #pragma unroll
                for (int kc = 0; kc < 4; kc++) {
                    uint32_t b0, b1;
                    ldsm_x2(b0, b1, ldB_base + nt * (8 * W_STRB) + kc * 32);
                    mma_s8(C, a[kc * 4], a[kc * 4 + 1], a[kc * 4 + 2], a[kc * 4 + 3],
                           b0, b1);
                }
                int col0 = nt * 8 + 2 * (lane & 3);
                int co0 = cosm[col0], co1 = cosm[col0 + 1];
                float kb0 = kbsm[col0], kb1 = kbsm[col0 + 1];
                float x0 = clip128(__fmaf_rn(__int2float_rn(C[0] + co0 - zwrs_lo), ka, kb0));
                float x1 = clip128(__fmaf_rn(__int2float_rn(C[1] + co1 - zwrs_lo), ka, kb1));
                float x2 = clip128(__fmaf_rn(__int2float_rn(C[2] + co0 - zwrs_hi), ka, kb0));
                float x3 = clip128(__fmaf_rn(__int2float_rn(C[3] + co1 - zwrs_hi), ka, kb1));
                float cf0 = __fadd_rn(__fadd_rn(x0, FMG), -FMG);
                float cf1 = __fadd_rn(__fadd_rn(x1, FMG), -FMG);
                float cf2 = __fadd_rn(__fadd_rn(x2, FMG), -FMG);
                float cf3 = __fadd_rn(__fadd_rn(x3, FMG), -FMG);
                float a0 = fminf(fmaxf(__fmaf_rn(cf0, c1, c2), aLo), aHi);
                float a1 = fminf(fmaxf(__fmaf_rn(cf1, c1, c2), aLo), aHi);
                float a2 = fminf(fmaxf(__fmaf_rn(cf2, c1, c2), aLo), aHi);
                float a3 = fminf(fmaxf(__fmaf_rn(cf3, c1, c2), aLo), aHi);
                uint32_t q0 = __float_as_uint(__fadd_rn(clip128(__fmaf_rn(a0, rA, zA)), FMG));
                uint32_t q1 = __float_as_uint(__fadd_rn(clip128(__fmaf_rn(a1, rA, zA)), FMG));
                uint32_t q2 = __float_as_uint(__fadd_rn(clip128(__fmaf_rn(a2, rA, zA)), FMG));
                uint32_t q3 = __float_as_uint(__fadd_rn(clip128(__fmaf_rn(a3, rA, zA)), FMG));
                *(uint16_t*)&sact[rlo * SACT_STR + col0] =
                    (uint16_t)__byte_perm(q0, q1, 0x0040);
                *(uint16_t*)&sact[(rlo + 8) * SACT_STR + col0] =
                    (uint16_t)__byte_perm(q2, q3, 0x0040);
            }
        }
        __syncthreads();

        // coalesced store of act codes: 8192 words total
        #pragma unroll
        for (int i = 0; i < 32; i++) {
            int idx = t + i * 256;
            int g = idx >> 11, rem = idx & 2047, row = rem >> 4, w4 = rem & 15;
            uint32_t val = *(const uint32_t*)&sact[row * SACT_STR + g * 64 + w4 * 4];
            *(uint32_t*)&g_act[g][(r0 + row) * 64 + w4 * 4] = val;
        }
        // fc/ic minmax
        #pragma unroll
        for (int i = 0; i < 8; i++) {
            int idx = t + i * 256;
            int row = idx >> 4, w4 = idx & 15;
            uint32_t wi = *(const uint32_t*)&sact[row * SACT_STR + 0 * 64 + w4 * 4];
            uint32_t wf = *(const uint32_t*)&sact[row * SACT_STR + 1 * 64 + w4 * 4];
            uint32_t wg = *(const uint32_t*)&sact[row * SACT_STR + 3 * 64 + w4 * 4];
            uint32_t wc = cq32[r0 * 16 + idx];
            #pragma unroll
            for (int b = 0; b < 4; b++) {
                int qi = (int)(int8_t)(wi >> (8 * b));
                int qf = (int)(int8_t)(wf >> (8 * b));
                int qg = (int)(int8_t)(wg >> (8 * b));
                int qc = (int)(int8_t)(wc >> (8 * b));
                float fv = __fmul_rn((float)qf - zAf, sAf);
                float iv = __fmul_rn((float)qi - zAi, sAi);
                float gv = __fmul_rn((float)qg - zAc, sAc);
                float cd = __fmul_rn((float)qc - zcc, scc);
                float fc = __fmul_rn(fv, cd);
                float ic = __fmul_rn(iv, gv);
                mn1 = fminf(mn1, fc); mx1 = fmaxf(mx1, fc);
                mn2 = fminf(mn2, ic); mx2 = fmaxf(mx2, ic);
            }
        }
        __syncthreads();
    }
    block_minmax(mn1, mx1, &g_mm[14], &g_mm[15]);
    block_minmax(mn2, mx2, &g_mm[16], &g_mm[17]);
}

// ---------- K6 ----------
__global__ void k_p3() {
    mkparams(fdec(g_mm[14]), fdec(g_mm[15]), &g_p.s_fc, &g_p.zp_fc);
    mkparams(fdec(g_mm[16]), fdec(g_mm[17]), &g_p.s_ic, &g_p.zp_ic);
    g_p.r_fc = __fdiv_rn(1.f, g_p.s_fc);
    g_p.r_ic = __fdiv_rn(1.f, g_p.s_ic);
}

// ---------- K7: minmax of fq(fc)+fq(ic) ----------
__global__ void k_pre() {
    float sAi = g_p.sA[0], zAi = g_p.zpA[0], sAf = g_p.sA[1], zAf = g_p.zpA[1];
    float sAg = g_p.sA[3], zAg = g_p.zpA[3], scc = g_p.s_c, zcc = g_p.zp_c;
    float sfc = g_p.s_fc, rfc = g_p.r_fc, zfc = g_p.zp_fc;
    float sic = g_p.s_ic, ric = g_p.r_ic, zic = g_p.zp_ic;
    float mn = 1e30f, mx = -1e30f;
    for (long i = blockIdx.x * blockDim.x + threadIdx.x; i < NE / 4;
         i += (long)gridDim.x * blockDim.x) {
        char4 qi = ((const char4*)g_act[0])[i];
        char4 qf = ((const char4*)g_act[1])[i];
        char4 qg = ((const char4*)g_act[3])[i];
        char4 qc = ((const char4*)g_cq)[i];
        int ii[4] = {qi.x, qi.y, qi.z, qi.w}, ff[4] = {qf.x, qf.y, qf.z, qf.w};
        int gg[4] = {qg.x, qg.y, qg.z, qg.w}, cc[4] = {qc.x, qc.y, qc.z, qc.w};
        #pragma unroll
        for (int j = 0; j < 4; j++) {
            float fv = __fmul_rn((float)ff[j] - zAf, sAf);
            float iv = __fmul_rn((float)ii[j] - zAi, sAi);
            float gv = __fmul_rn((float)gg[j] - zAg, sAg);
            float cd = __fmul_rn((float)cc[j] - zcc, scc);
            float fcv = fqvm(__fmul_rn(fv, cd), sfc, rfc, zfc);
            float icv = fqvm(__fmul_rn(iv, gv), sic, ric, zic);
            float pre = __fadd_rn(fcv, icv);
            mn = fminf(mn, pre); mx = fmaxf(mx, pre);
        }
    }
    block_minmax(mn, mx, &g_mm[18], &g_mm[19]);
}

// ---------- K8 ----------
__global__ void k_p4() {
    float mn = fdec(g_mm[18]), mx = fdec(g_mm[19]);
    mkparams(mn, mx, &g_p.s_cn, &g_p.zp_cn);
    g_p.r_cn = __fdiv_rn(1.f, g_p.s_cn);
    float lo = htanh(fqvm(mn, g_p.s_cn, g_p.r_cn, g_p.zp_cn));
    float hi = htanh(fqvm(mx, g_p.s_cn, g_p.r_cn, g_p.zp_cn));
    mkparams(lo, hi, &g_p.s_t, &g_p.zp_t);
    g_p.r_t = __fdiv_rn(1.f, g_p.s_t);
}

// ---------- K9: write c_next, store t codes, minmax(o*t) ----------
__global__ void k_cnext(float* __restrict__ out_c) {
    float sAi = g_p.sA[0], zAi = g_p.zpA[0], sAf = g_p.sA[1], zAf = g_p.zpA[1];
    float sAo = g_p.sA[2], zAo = g_p.zpA[2], sAg = g_p.sA[3], zAg = g_p.zpA[3];
    float scc = g_p.s_c, zcc = g_p.zp_c;
    float sfc = g_p.s_fc, rfc = g_p.r_fc, zfc = g_p.zp_fc;
    float sic = g_p.s_ic, ric = g_p.r_ic, zic = g_p.zp_ic;
    float scn = g_p.s_cn, rcn = g_p.r_cn, zcn = g_p.zp_cn;
    float st = g_p.s_t, rt = g_p.r_t, zt = g_p.zp_t;
    float mn = 1e30f, mx = -1e30f;
    for (long i = blockIdx.x * blockDim.x + threadIdx.x; i < NE / 4;
         i += (long)gridDim.x * blockDim.x) {
        char4 qi = ((const char4*)g_act[0])[i];
        char4 qf = ((const char4*)g_act[1])[i];
        char4 qo = ((const char4*)g_act[2])[i];
        char4 qg = ((const char4*)g_act[3])[i];
        char4 qc = ((const char4*)g_cq)[i];
        int ii[4] = {qi.x, qi.y, qi.z, qi.w}, ff[4] = {qf.x, qf.y, qf.z, qf.w};
        int oo[4] = {qo.x, qo.y, qo.z, qo.w}, gg[4] = {qg.x, qg.y, qg.z, qg.w};
        int cc[4] = {qc.x, qc.y, qc.z, qc.w};
        float4 outc;
        float* oc = (float*)&outc;
        char4 tq4;
        int8_t* tqq = (int8_t*)&tq4;
        #pragma unroll
        for (int j = 0; j < 4; j++) {
            float fv = __fmul_rn((float)ff[j] - zAf, sAf);
            float iv = __fmul_rn((float)ii[j] - zAi, sAi);
            float gv = __fmul_rn((float)gg[j] - zAg, sAg);
            float cd = __fmul_rn((float)cc[j] - zcc, scc);
            float fcv = fqvm(__fmul_rn(fv, cd), sfc, rfc, zfc);
            float icv = fqvm(__fmul_rn(iv, gv), sic, ric, zic);
            float pre = __fadd_rn(fcv, icv);
            float cn = fqvm(pre, scn, rcn, zcn);
            oc[j] = cn;
            float tcodef = quant_qm(htanh(cn), rt, zt);
            int tcode = (int)tcodef;
            tqq[j] = (int8_t)tcode;
            float tv = __fmul_rn(tcodef - zt, st);
            float ov = __fmul_rn((float)oo[j] - zAo, sAo);
            float hp = __fmul_rn(ov, tv);
            mn = fminf(mn, hp); mx = fmaxf(mx, hp);
        }
        ((float4*)out_c)[i] = outc;
        ((char4*)g_tq)[i] = tq4;
    }
    block_minmax(mn, mx, &g_mm[20], &g_mm[21]);
}

// ---------- K10 ----------
__global__ void k_p5() {
    mkparams(fdec(g_mm[20]), fdec(g_mm[21]), &g_p.s_hn, &g_p.zp_hn);
    g_p.r_hn = __fdiv_rn(1.f, g_p.s_hn);
}

// ---------- K11: h_next ----------
__global__ void k_hnext(float* __restrict__ out_h) {
    float sAo = g_p.sA[2], zAo = g_p.zpA[2], st = g_p.s_t, zt = g_p.zp_t;
    float shn = g_p.s_hn, rhn = g_p.r_hn, zhn = g_p.zp_hn;
    for (long i = blockIdx.x * blockDim.x + threadIdx.x; i < NE / 4;
         i += (long)gridDim.x * blockDim.x) {
        char4 qo = ((const char4*)g_act[2])[i];
        char4 qt = ((const char4*)g_tq)[i];
        int oo[4] = {qo.x, qo.y, qo.z, qo.w}, tt[4] = {qt.x, qt.y, qt.z, qt.w};
        float4 outh;
        float* oh = (float*)&outh;
        #pragma unroll
        for (int j = 0; j < 4; j++) {
            float ov = __fmul_rn((float)oo[j] - zAo, sAo);
            float tv = __fmul_rn((float)tt[j] - zt, st);
            oh[j] = fqvm(__fmul_rn(ov, tv), shn, rhn, zhn);
        }
        ((float4*)out_h)[i] = outh;
    }
}

extern "C" void kernel_launch(void* const* d_in, const int* in_sizes, int n_in,
                              void* d_out, int out_size) {
    const float* x  = (const float*)d_in[0];
    const float* h  = (const float*)d_in[1];
    const float* c  = (const float*)d_in[2];
    const float* Wi = (const float*)d_in[3];
    const float* bi = (const float*)d_in[4];
    const float* Wf = (const float*)d_in[5];
    const float* bf = (const float*)d_in[6];
    const float* Wo = (const float*)d_in[7];
    const float* bo = (const float*)d_in[8];
    const float* Wc = (const float*)d_in[9];
    const float* bc = (const float*)d_in[10];
    float* out_h = (float*)d_out;
    float* out_c = (float*)d_out + NE;

    static int attr_done = 0;
    if (!attr_done) {
        cudaFuncSetAttribute(k_gemmA, cudaFuncAttributeMaxDynamicSharedMemorySize, DYN_A);
        cudaFuncSetAttribute(k_gemmB, cudaFuncAttributeMaxDynamicSharedMemorySize, DYN_B);
        attr_done = 1;
    }

    k_init<<<1, 32>>>();
    k_minmax3<<<2048, 256>>>(x, h, c);
    k_params<<<1, 256>>>(Wi, bi, Wf, bf, Wo, bo, Wc, bc);
    k_gemmA<<<2048, 256, DYN_A>>>(x, h, c);
    k_p2<<<1, 256>>>();
    k_gemmB<<<2048, 256, DYN_B>>>();
    k_p3<<<1, 1>>>();
    k_pre<<<8192, 256>>>();
    k_p4<<<1, 1>>>();
    k_cnext<<<8192, 256>>>(out_c);
    k_p5<<<1, 1>>>();
    k_hnext<<<8192, 256>>>(out_h);
}

// round 9
// speedup vs baseline: 6.6332x; 1.0003x over previous
#include <cuda_runtime.h>
#include <stdint.h>

#define R_TOT 524288
#define NE    33554432
#define NT128 4096            // R_TOT / 128 rows per macro-tile
#define ONEB  0x01010101
#define FMG   12582912.0f     // 1.5 * 2^23 : magic rint constant

struct Params {
    float s_x, zp_x, s_h, zp_h, s_c, zp_c, s_cat, zp_cat;
    float r_x, r_h, r_c, r_cat;
    float alpha[4];
    float bdq[256];
    int   zpw_i[4], zpc_i;
    float sG[4], zpG[4], sA[4], zpA[4];
    float rG[4], rA[4];
    float kaG[4], c1G[4], c2G[4];
    float s_fc, zp_fc, s_ic, zp_ic, s_cn, zp_cn, s_t, zp_t, s_hn, zp_hn;
    float r_fc, r_ic, r_cn, r_t, r_hn;
};

__device__ Params   g_p;
__device__ unsigned g_mm[22];            // 11 (min,max) encoded-float slots
__device__ int8_t   g_wq[256 * 128];     // quantized weight codes [col][k]
__device__ int      g_const[256];        // per-output zero-point correction
__device__ float    g_kbq[256];          // per-col folded gate-quant offset
__device__ uint32_t g_catq[R_TOT * 32];  // packed cat codes (64 MB)
__device__ int      g_rowsum[R_TOT];     // per-row code sums (2 MB)
__device__ int8_t   g_act[4][NE];        // i,f,o,cg activation codes
__device__ int8_t   g_cq[NE];            // c_prev codes
__device__ int8_t   g_tq[NE];            // tanh(c_next) codes

// ---------- helpers ----------
__device__ __forceinline__ unsigned fenc(float f) {
    unsigned u = __float_as_uint(f);
    return (u & 0x80000000u) ? ~u : (u | 0x80000000u);
}
__device__ __forceinline__ float fdec(unsigned u) {
    return __uint_as_float((u & 0x80000000u) ? (u & 0x7fffffffu) : ~u);
}
__device__ __forceinline__ float clip128(float x) {
    return fminf(fmaxf(x, -128.f), 127.f);
}
// quantize code value as float: rint(clip(fma(v,rs,zp)))  [== clip(rint(v*rs)+zp)]
__device__ __forceinline__ float quant_qm(float v, float rs, float zp) {
    float x = clip128(__fmaf_rn(v, rs, zp));
    return __fadd_rn(__fadd_rn(x, FMG), -FMG);
}
// quantize to raw byte in bits[0:8]
__device__ __forceinline__ uint32_t quant_qb(float v, float rs, float zp) {
    float x = clip128(__fmaf_rn(v, rs, zp));
    return __float_as_uint(__fadd_rn(x, FMG));
}
__device__ __forceinline__ float fqvm(float v, float s, float rs, float zp) {
    return __fmul_rn(quant_qm(v, rs, zp) - zp, s);
}
__device__ __forceinline__ void mkparams(float mnr, float mxr, float* s, float* zp) {
    float mn = fminf(mnr, 0.f), mx = fmaxf(mxr, 0.f);
    float sc = fmaxf(__fdiv_rn(mx - mn, 255.f), 1e-8f);
    float z  = rintf(-128.f - __fdiv_rn(mn, sc));
    *s = sc; *zp = fminf(fmaxf(z, -128.f), 127.f);
}
#define HSIG_C 0.16666667f
__device__ __forceinline__ float hsig(float v) {
    return fminf(fmaxf(__fadd_rn(__fmul_rn(v, HSIG_C), 0.5f), 0.f), 1.f);
}
__device__ __forceinline__ float htanh(float v) { return fminf(fmaxf(v, -1.f), 1.f); }

__device__ __forceinline__ void block_minmax(float mn, float mx, unsigned* gmin, unsigned* gmax) {
    #pragma unroll
    for (int o = 16; o; o >>= 1) {
        mn = fminf(mn, __shfl_xor_sync(0xffffffffu, mn, o));
        mx = fmaxf(mx, __shfl_xor_sync(0xffffffffu, mx, o));
    }
    __shared__ float smn[8], smx[8];
    int w = threadIdx.x >> 5, nw = blockDim.x >> 5;
    __syncthreads();
    if ((threadIdx.x & 31) == 0) { smn[w] = mn; smx[w] = mx; }
    __syncthreads();
    if (threadIdx.x == 0) {
        for (int i = 1; i < nw; i++) { mn = fminf(mn, smn[i]); mx = fmaxf(mx, smx[i]); }
        atomicMin(gmin, fenc(mn));
        atomicMax(gmax, fenc(mx));
    }
    __syncthreads();
}

__device__ __forceinline__ float2 block_reduce_pair(float mn, float mx) {
    #pragma unroll
    for (int o = 16; o; o >>= 1) {
        mn = fminf(mn, __shfl_xor_sync(0xffffffffu, mn, o));
        mx = fmaxf(mx, __shfl_xor_sync(0xffffffffu, mx, o));
    }
    __shared__ float smn[8], smx[8];
    __shared__ float2 res;
    int w = threadIdx.x >> 5, nw = blockDim.x >> 5;
    __syncthreads();
    if ((threadIdx.x & 31) == 0) { smn[w] = mn; smx[w] = mx; }
    __syncthreads();
    if (threadIdx.x == 0) {
        for (int i = 1; i < nw; i++) { mn = fminf(mn, smn[i]); mx = fmaxf(mx, smx[i]); }
        res = make_float2(mn, mx);
    }
    __syncthreads();
    return res;
}

__device__ __forceinline__ void mma_s8(int* c, uint32_t a0, uint32_t a1, uint32_t a2,
                                       uint32_t a3, uint32_t b0, uint32_t b1) {
    asm volatile(
        "mma.sync.aligned.m16n8k32.row.col.s32.s8.s8.s32 "
        "{%0,%1,%2,%3}, {%4,%5,%6,%7}, {%8,%9}, {%0,%1,%2,%3};\n"
        : "+r"(c[0]), "+r"(c[1]), "+r"(c[2]), "+r"(c[3])
        : "r"(a0), "r"(a1), "r"(a2), "r"(a3), "r"(b0), "r"(b1));
}
__device__ __forceinline__ void ldsm_x4(uint32_t& r0, uint32_t& r1, uint32_t& r2,
                                        uint32_t& r3, uint32_t addr) {
    asm volatile("ldmatrix.sync.aligned.m8n8.x4.shared.b16 {%0,%1,%2,%3}, [%4];"
                 : "=r"(r0), "=r"(r1), "=r"(r2), "=r"(r3) : "r"(addr));
}
__device__ __forceinline__ void ldsm_x2(uint32_t& r0, uint32_t& r1, uint32_t addr) {
    asm volatile("ldmatrix.sync.aligned.m8n8.x2.shared.b16 {%0,%1}, [%2];"
                 : "=r"(r0), "=r"(r1) : "r"(addr));
}

// ---------- K0 ----------
__global__ void k_init() {
    int t = threadIdx.x;
    if (t < 11) { g_mm[2 * t] = fenc(1e30f); g_mm[2 * t + 1] = fenc(-1e30f); }
}

// ---------- K1: minmax of x, h, c ----------
__global__ void k_minmax3(const float* __restrict__ x, const float* __restrict__ h,
                          const float* __restrict__ c) {
    const float* arrs[3] = {x, h, c};
    for (int a = 0; a < 3; a++) {
        float mn = 1e30f, mx = -1e30f;
        const float4* p = (const float4*)arrs[a];
        for (long i = blockIdx.x * blockDim.x + threadIdx.x; i < NE / 4;
             i += (long)gridDim.x * blockDim.x) {
            float4 v = p[i];
            mn = fminf(fminf(fminf(mn, v.x), v.y), fminf(v.z, v.w));
            mx = fmaxf(fmaxf(fmaxf(mx, v.x), v.y), fmaxf(v.z, v.w));
        }
        block_minmax(mn, mx, &g_mm[2 * a], &g_mm[2 * a + 1]);
    }
}

// ---------- K2: scalar params + weight/bias quantization (1 block) ----------
__global__ void k_params(const float* __restrict__ Wi, const float* __restrict__ bi,
                         const float* __restrict__ Wf, const float* __restrict__ bf,
                         const float* __restrict__ Wo, const float* __restrict__ bo,
                         const float* __restrict__ Wc, const float* __restrict__ bc) {
    __shared__ float sw, zw, rw, sb, zb, rb_;
    int t = threadIdx.x;
    if (t == 0) {
        mkparams(fdec(g_mm[0]), fdec(g_mm[1]), &g_p.s_x, &g_p.zp_x);
        mkparams(fdec(g_mm[2]), fdec(g_mm[3]), &g_p.s_h, &g_p.zp_h);
        mkparams(fdec(g_mm[4]), fdec(g_mm[5]), &g_p.s_c, &g_p.zp_c);
        g_p.r_x = __fdiv_rn(1.f, g_p.s_x);
        g_p.r_h = __fdiv_rn(1.f, g_p.s_h);
        g_p.r_c = __fdiv_rn(1.f, g_p.s_c);
        float xlo = fqvm(fdec(g_mm[0]), g_p.s_x, g_p.r_x, g_p.zp_x);
        float xhi = fqvm(fdec(g_mm[1]), g_p.s_x, g_p.r_x, g_p.zp_x);
        float hlo = fqvm(fdec(g_mm[2]), g_p.s_h, g_p.r_h, g_p.zp_h);
        float hhi = fqvm(fdec(g_mm[3]), g_p.s_h, g_p.r_h, g_p.zp_h);
        mkparams(fminf(xlo, hlo), fmaxf(xhi, hhi), &g_p.s_cat, &g_p.zp_cat);
        g_p.r_cat = __fdiv_rn(1.f, g_p.s_cat);
        g_p.zpc_i = (int)g_p.zp_cat;
    }
    __syncthreads();
    const float* Wg[4] = {Wi, Wf, Wo, Wc};
    const float* bg[4] = {bi, bf, bo, bc};
    for (int g = 0; g < 4; g++) {
        float mn = 1e30f, mx = -1e30f;
        for (int i = t; i < 8192; i += 256) {
            float v = Wg[g][i];
            mn = fminf(mn, v); mx = fmaxf(mx, v);
        }
        float2 m = block_reduce_pair(mn, mx);
        if (t == 0) {
            mkparams(m.x, m.y, &sw, &zw);
            rw = __fdiv_rn(1.f, sw);
            g_p.alpha[g] = __fmul_rn(g_p.s_cat, sw);
            g_p.zpw_i[g] = (int)zw;
        }
        __syncthreads();
        for (int i = t; i < 8192; i += 256)
            g_wq[g * 8192 + i] = (int8_t)(int)quant_qm(Wg[g][i], rw, zw);
        mn = (t < 64) ? bg[g][t] : 1e30f;
        mx = (t < 64) ? bg[g][t] : -1e30f;
        m = block_reduce_pair(mn, mx);
        if (t == 0) { mkparams(m.x, m.y, &sb, &zb); rb_ = __fdiv_rn(1.f, sb); }
        __syncthreads();
        if (t < 64) g_p.bdq[g * 64 + t] = fqvm(bg[g][t], sb, rb_, zb);
        __syncthreads();
    }
    {
        int s = 0;
        const int8_t* wr = &g_wq[t * 128];
        for (int k = 0; k < 128; k++) s += wr[k];
        int g = t >> 6;
        g_const[t] = -g_p.zpc_i * s + 128 * g_p.zpc_i * g_p.zpw_i[g];
    }
}

// dyn smem layout (both gemm kernels):
//   [0, 36864)   W codes, 256 cols x 144B stride (conflict-free LDSM)
//   [36864, ...) codes staging: 128 rows x 36 words (144B stride); word 32 = rowsum
#define W_BYTES   36864
#define W_STRB    144
#define CODE_STRW 36
#define SACT_STR  264
#define DYN_A     (W_BYTES + 128 * CODE_STRW * 4)              // 55296
#define DYN_B     (W_BYTES + 128 * SACT_STR)                   // 70656

// ---------- K3a: pass A — quantize cat + c, store codes+rowsum, MMA, gate minmax ----------
__global__ void __launch_bounds__(256) k_gemmA(const float* __restrict__ X,
                                               const float* __restrict__ H,
                                               const float* __restrict__ Cp) {
    extern __shared__ uint8_t dyn[];
    uint32_t* codes = (uint32_t*)(dyn + W_BYTES);
    __shared__ int   cosm[256];
    __shared__ float bosm[256];
    __shared__ float alsm[4];
    __shared__ int   zwsm[4];
    int t = threadIdx.x, lane = t & 31, w = t >> 5;

    {   // W fill: one col per thread, uint4, padded stride
        const uint4* wsrc = (const uint4*)&g_wq[t * 128];
        uint4* wdst = (uint4*)(dyn + t * W_STRB);
        #pragma unroll
        for (int i = 0; i < 8; i++) wdst[i] = wsrc[i];
    }
    cosm[t] = g_const[t];
    bosm[t] = g_p.bdq[t];
    if (t < 4) { alsm[t] = g_p.alpha[t]; zwsm[t] = g_p.zpw_i[t]; }

    float sx = g_p.s_x, rx = g_p.r_x, zx = g_p.zp_x;
    float sh = g_p.s_h, rh = g_p.r_h, zh = g_p.zp_h;
    float nzx = -__fmul_rn(zx, sx), nzh = -__fmul_rn(zh, sh);
    float rc = g_p.r_cat, zc = g_p.zp_cat;
    float rcc = g_p.r_c, zcc = g_p.zp_c;
    const float4* X4 = (const float4*)X;
    const float4* H4 = (const float4*)H;
    const float4* C4 = (const float4*)Cp;

    uint32_t Waddr = (uint32_t)__cvta_generic_to_shared(dyn);
    uint32_t Caddr = (uint32_t)__cvta_generic_to_shared(codes);
    uint32_t ldB_base = Waddr + (lane & 7) * W_STRB + ((lane >> 3) & 1) * 16;
    uint32_t ldA_base = Caddr + (w * 16 + (lane & 15)) * 144 + (lane >> 4) * 16;

    float mnG[4], mxG[4];
    #pragma unroll
    for (int g = 0; g < 4; g++) { mnG[g] = 1e30f; mxG[g] = -1e30f; }
    __syncthreads();

    for (int tile = blockIdx.x; tile < NT128; tile += gridDim.x) {
        long r0 = (long)tile * 128;
        // quantize c slice of this tile (fused former k_quantc)
        #pragma unroll
        for (int i = 0; i < 8; i++) {
            int idx = t + i * 256;                 // 2048 float4 per tile
            float4 v = C4[r0 * 16 + idx];
            uint32_t b0 = quant_qb(v.x, rcc, zcc);
            uint32_t b1 = quant_qb(v.y, rcc, zcc);
            uint32_t b2 = quant_qb(v.z, rcc, zcc);
            uint32_t b3 = quant_qb(v.w, rcc, zcc);
            uint32_t pk = __byte_perm(__byte_perm(b0, b1, 0x0040),
                                      __byte_perm(b2, b3, 0x0040), 0x5410);
            ((uint32_t*)g_cq)[r0 * 16 + idx] = pk;
        }
        // quantize cat: 16 rows per warp
        #pragma unroll 4
        for (int rr = 0; rr < 16; rr++) {
            int lrow = w * 16 + rr;
            long row = r0 + lrow;
            float4 v = (lane < 16) ? X4[row * 16 + lane] : H4[row * 16 + lane - 16];
            float s0 = (lane < 16) ? sx : sh;
            float r0s = (lane < 16) ? rx : rh;
            float z0 = (lane < 16) ? zx : zh;
            float nz0 = (lane < 16) ? nzx : nzh;
            float c0 = quant_qm(v.x, r0s, z0), c1 = quant_qm(v.y, r0s, z0);
            float c2 = quant_qm(v.z, r0s, z0), c3 = quant_qm(v.w, r0s, z0);
            uint32_t b0 = quant_qb(__fmaf_rn(c0, s0, nz0), rc, zc);
            uint32_t b1 = quant_qb(__fmaf_rn(c1, s0, nz0), rc, zc);
            uint32_t b2 = quant_qb(__fmaf_rn(c2, s0, nz0), rc, zc);
            uint32_t b3 = quant_qb(__fmaf_rn(c3, s0, nz0), rc, zc);
            uint32_t pk = __byte_perm(__byte_perm(b0, b1, 0x0040),
                                      __byte_perm(b2, b3, 0x0040), 0x5410);
            codes[lrow * CODE_STRW + lane] = pk;
            g_catq[row * 32 + lane] = pk;
        }
        __syncthreads();
        if (t < 128) {
            const uint32_t* cr = &codes[t * CODE_STRW];
            int sum = 0;
            #pragma unroll
            for (int k = 0; k < 32; k++) sum = __dp4a((int)cr[k], ONEB, sum);
            codes[t * CODE_STRW + 32] = (uint32_t)sum;
            g_rowsum[r0 + t] = sum;
        }
        __syncthreads();

        uint32_t a[16];
        #pragma unroll
        for (int kc = 0; kc < 4; kc++)
            ldsm_x4(a[kc * 4], a[kc * 4 + 1], a[kc * 4 + 2], a[kc * 4 + 3],
                    ldA_base + kc * 32);
        int rs_lo = (int)codes[(w * 16 + (lane >> 2)) * CODE_STRW + 32];
        int rs_hi = (int)codes[(w * 16 + (lane >> 2) + 8) * CODE_STRW + 32];

        #pragma unroll
        for (int g = 0; g < 4; g++) {
            float al = alsm[g];
            int   zwrs_lo = zwsm[g] * rs_lo, zwrs_hi = zwsm[g] * rs_hi;
            float mn = 1e30f, mx = -1e30f;
            #pragma unroll 4
            for (int ntg = 0; ntg < 8; ntg++) {
                int nt = g * 8 + ntg;
                int C[4] = {0, 0, 0, 0};
                #pragma unroll
                for (int kc = 0; kc < 4; kc++) {
                    uint32_t b0, b1;
                    ldsm_x2(b0, b1, ldB_base + nt * (8 * W_STRB) + kc * 32);
                    mma_s8(C, a[kc * 4], a[kc * 4 + 1], a[kc * 4 + 2], a[kc * 4 + 3],
                           b0, b1);
                }
                int col0 = nt * 8 + 2 * (lane & 3);
                int co0 = cosm[col0], co1 = cosm[col0 + 1];
                float bo0 = bosm[col0], bo1 = bosm[col0 + 1];
                float G0 = __fmaf_rn(__int2float_rn(C[0] + co0 - zwrs_lo), al, bo0);
                float G1 = __fmaf_rn(__int2float_rn(C[1] + co1 - zwrs_lo), al, bo1);
                float G2 = __fmaf_rn(__int2float_rn(C[2] + co0 - zwrs_hi), al, bo0);
                float G3 = __fmaf_rn(__int2float_rn(C[3] + co1 - zwrs_hi), al, bo1);
                mn = fminf(mn, fminf(fminf(G0, G1), fminf(G2, G3)));
                mx = fmaxf(mx, fmaxf(fmaxf(G0, G1), fmaxf(G2, G3)));
            }
            mnG[g] = fminf(mnG[g], mn);
            mxG[g] = fmaxf(mxG[g], mx);
        }
        __syncthreads();
    }
    #pragma unroll
    for (int g = 0; g < 4; g++) {
        float mn = mnG[g], mx = mxG[g];
        #pragma unroll
        for (int o = 16; o; o >>= 1) {
            mn = fminf(mn, __shfl_xor_sync(0xffffffffu, mn, o));
            mx = fmaxf(mx, __shfl_xor_sync(0xffffffffu, mx, o));
        }
        if (lane == 0) {
            atomicMin(&g_mm[6 + 2 * g], fenc(mn));
            atomicMax(&g_mm[7 + 2 * g], fenc(mx));
        }
    }
}

// ---------- K4: gate + activation params + folded constants ----------
__global__ void k_p2() {
    int t = threadIdx.x;
    if (t == 0) {
        for (int g = 0; g < 4; g++) {
            float mn = fdec(g_mm[6 + 2 * g]), mx = fdec(g_mm[7 + 2 * g]);
            mkparams(mn, mx, &g_p.sG[g], &g_p.zpG[g]);
            g_p.rG[g] = __fdiv_rn(1.f, g_p.sG[g]);
            float lo = fqvm(mn, g_p.sG[g], g_p.rG[g], g_p.zpG[g]);
            float hi = fqvm(mx, g_p.sG[g], g_p.rG[g], g_p.zpG[g]);
            float amin, amax;
            if (g < 3) { amin = hsig(lo); amax = hsig(hi); }
            else       { amin = htanh(lo); amax = htanh(hi); }
            mkparams(amin, amax, &g_p.sA[g], &g_p.zpA[g]);
            g_p.rA[g] = __fdiv_rn(1.f, g_p.sA[g]);
            g_p.kaG[g] = __fmul_rn(g_p.alpha[g], g_p.rG[g]);
            if (g < 3) {
                g_p.c1G[g] = __fmul_rn(g_p.sG[g], HSIG_C);
                g_p.c2G[g] = __fadd_rn(0.5f, -__fmul_rn(g_p.zpG[g], g_p.c1G[g]));
            } else {
                g_p.c1G[g] = g_p.sG[g];
                g_p.c2G[g] = -__fmul_rn(g_p.zpG[g], g_p.sG[g]);
            }
        }
    }
    __syncthreads();
    int g = t >> 6;
    g_kbq[t] = __fadd_rn(__fmul_rn(g_p.bdq[t], g_p.rG[g]), g_p.zpG[g]);
}

// ---------- K3b: pass B — MMA from stored codes, activations, fc/ic minmax ----------
__global__ void __launch_bounds__(256) k_gemmB() {
    extern __shared__ uint8_t dyn[];
    uint32_t* codes = (uint32_t*)(dyn + W_BYTES);   // union with sact (disjoint lifetime)
    int8_t*   sact  = (int8_t*)(dyn + W_BYTES);
    __shared__ int   cosm[256];
    __shared__ float kbsm[256];
    __shared__ float kasm[4], c1sm[4], c2sm[4], rAsm[4], zAsm[4];
    __shared__ int   zwsm[4];
    int t = threadIdx.x, lane = t & 31, w = t >> 5;

    {
        const uint4* wsrc = (const uint4*)&g_wq[t * 128];
        uint4* wdst = (uint4*)(dyn + t * W_STRB);
        #pragma unroll
        for (int i = 0; i < 8; i++) wdst[i] = wsrc[i];
    }
    cosm[t] = g_const[t];
    kbsm[t] = g_kbq[t];
    if (t < 4) {
        kasm[t] = g_p.kaG[t]; zwsm[t] = g_p.zpw_i[t];
        c1sm[t] = g_p.c1G[t]; c2sm[t] = g_p.c2G[t];
        rAsm[t] = g_p.rA[t];  zAsm[t] = g_p.zpA[t];
    }
    float sAi = g_p.sA[0], zAi = g_p.zpA[0], sAf = g_p.sA[1], zAf = g_p.zpA[1];
    float sAc = g_p.sA[3], zAc = g_p.zpA[3];
    float scc = g_p.s_c, zcc = g_p.zp_c;

    uint32_t Waddr = (uint32_t)__cvta_generic_to_shared(dyn);
    uint32_t Caddr = (uint32_t)__cvta_generic_to_shared(codes);
    uint32_t ldB_base = Waddr + (lane & 7) * W_STRB + ((lane >> 3) & 1) * 16;
    uint32_t ldA_base = Caddr + (w * 16 + (lane & 15)) * 144 + (lane >> 4) * 16;
    int rlo = w * 16 + (lane >> 2);
    const uint32_t* cq32 = (const uint32_t*)g_cq;

    float mn1 = 1e30f, mx1 = -1e30f, mn2 = 1e30f, mx2 = -1e30f;
    __syncthreads();

    for (int tile = blockIdx.x; tile < NT128; tile += gridDim.x) {
        long r0 = (long)tile * 128;
        #pragma unroll
        for (int i = 0; i < 4; i++) {
            int u = t + i * 256;                   // 1024 uint4 = 4096 words
            int row = u >> 3, part = u & 7;
            *(uint4*)(dyn + W_BYTES + row * 144 + part * 16) =
                ((const uint4*)g_catq)[r0 * 8 + u];
        }
        if (t < 128) codes[t * CODE_STRW + 32] = (uint32_t)g_rowsum[r0 + t];
        __syncthreads();

        uint32_t a[16];
        #pragma unroll
        for (int kc = 0; kc < 4; kc++)
            ldsm_x4(a[kc * 4], a[kc * 4 + 1], a[kc * 4 + 2], a[kc * 4 + 3],
                    ldA_base + kc * 32);
        int rs_lo = (int)codes[(w * 16 + (lane >> 2)) * CODE_STRW + 32];
        int rs_hi = (int)codes[(w * 16 + (lane >> 2) + 8) * CODE_STRW + 32];
        __syncthreads();   // codes region now reused as sact

        #pragma unroll
        for (int g = 0; g < 4; g++) {
            float ka = kasm[g];
            int   zwrs_lo = zwsm[g] * rs_lo, zwrs_hi = zwsm[g] * rs_hi;
            float c1 = c1sm[g], c2 = c2sm[g];
            float rA = rAsm[g], zA = zAsm[g];
            float aLo = (g < 3) ? 0.f : -1.f, aHi = 1.f;
            #pragma unroll 4
            for (int ntg = 0; ntg < 8; ntg++) {
                int nt = g * 8 + ntg;
                int C[4] = {0, 0, 0, 0};
                #pragma unroll
                for (int kc = 0; kc < 4; kc++) {
                    uint32_t b0, b1;
                    ldsm_x2(b0, b1, ldB_base + nt * (8 * W_STRB) + kc * 32);
                    mma_s8(C, a[kc * 4], a[kc * 4 + 1], a[kc * 4 + 2], a[kc * 4 + 3],
                           b0, b1);
                }
                int col0 = nt * 8 + 2 * (lane & 3);
                int co0 = cosm[col0], co1 = cosm[col0 + 1];
                float kb0 = kbsm[col0], kb1 = kbsm[col0 + 1];
                float x0 = clip128(__fmaf_rn(__int2float_rn(C[0] + co0 - zwrs_lo), ka, kb0));
                float x1 = clip128(__fmaf_rn(__int2float_rn(C[1] + co1 - zwrs_lo), ka, kb1));
                float x2 = clip128(__fmaf_rn(__int2float_rn(C[2] + co0 - zwrs_hi), ka, kb0));
                float x3 = clip128(__fmaf_rn(__int2float_rn(C[3] + co1 - zwrs_hi), ka, kb1));
                float cf0 = __fadd_rn(__fadd_rn(x0, FMG), -FMG);
                float cf1 = __fadd_rn(__fadd_rn(x1, FMG), -FMG);
                float cf2 = __fadd_rn(__fadd_rn(x2, FMG), -FMG);
                float cf3 = __fadd_rn(__fadd_rn(x3, FMG), -FMG);
                float a0 = fminf(fmaxf(__fmaf_rn(cf0, c1, c2), aLo), aHi);
                float a1 = fminf(fmaxf(__fmaf_rn(cf1, c1, c2), aLo), aHi);
                float a2 = fminf(fmaxf(__fmaf_rn(cf2, c1, c2), aLo), aHi);
                float a3 = fminf(fmaxf(__fmaf_rn(cf3, c1, c2), aLo), aHi);
                uint32_t q0 = __float_as_uint(__fadd_rn(clip128(__fmaf_rn(a0, rA, zA)), FMG));
                uint32_t q1 = __float_as_uint(__fadd_rn(clip128(__fmaf_rn(a1, rA, zA)), FMG));
                uint32_t q2 = __float_as_uint(__fadd_rn(clip128(__fmaf_rn(a2, rA, zA)), FMG));
                uint32_t q3 = __float_as_uint(__fadd_rn(clip128(__fmaf_rn(a3, rA, zA)), FMG));
                *(uint16_t*)&sact[rlo * SACT_STR + col0] =
                    (uint16_t)__byte_perm(q0, q1, 0x0040);
                *(uint16_t*)&sact[(rlo + 8) * SACT_STR + col0] =
                    (uint16_t)__byte_perm(q2, q3, 0x0040);
            }
        }
        __syncthreads();

        // coalesced store of act codes: 8192 words total
        #pragma unroll
        for (int i = 0; i < 32; i++) {
            int idx = t + i * 256;
            int g = idx >> 11, rem = idx & 2047, row = rem >> 4, w4 = rem & 15;
            uint32_t val = *(const uint32_t*)&sact[row * SACT_STR + g * 64 + w4 * 4];
            *(uint32_t*)&g_act[g][(r0 + row) * 64 + w4 * 4] = val;
        }
        // fc/ic minmax
        #pragma unroll
        for (int i = 0; i < 8; i++) {
            int idx = t + i * 256;
            int row = idx >> 4, w4 = idx & 15;
            uint32_t wi = *(const uint32_t*)&sact[row * SACT_STR + 0 * 64 + w4 * 4];
            uint32_t wf = *(const uint32_t*)&sact[row * SACT_STR + 1 * 64 + w4 * 4];
            uint32_t wg = *(const uint32_t*)&sact[row * SACT_STR + 3 * 64 + w4 * 4];
            uint32_t wc = cq32[r0 * 16 + idx];
            #pragma unroll
            for (int b = 0; b < 4; b++) {
                int qi = (int)(int8_t)(wi >> (8 * b));
                int qf = (int)(int8_t)(wf >> (8 * b));
                int qg = (int)(int8_t)(wg >> (8 * b));
                int qc = (int)(int8_t)(wc >> (8 * b));
                float fv = __fmul_rn((float)qf - zAf, sAf);
                float iv = __fmul_rn((float)qi - zAi, sAi);
                float gv = __fmul_rn((float)qg - zAc, sAc);
                float cd = __fmul_rn((float)qc - zcc, scc);
                float fc = __fmul_rn(fv, cd);
                float ic = __fmul_rn(iv, gv);
                mn1 = fminf(mn1, fc); mx1 = fmaxf(mx1, fc);
                mn2 = fminf(mn2, ic); mx2 = fmaxf(mx2, ic);
            }
        }
        __syncthreads();
    }
    block_minmax(mn1, mx1, &g_mm[14], &g_mm[15]);
    block_minmax(mn2, mx2, &g_mm[16], &g_mm[17]);
}

// ---------- K6 ----------
__global__ void k_p3() {
    mkparams(fdec(g_mm[14]), fdec(g_mm[15]), &g_p.s_fc, &g_p.zp_fc);
    mkparams(fdec(g_mm[16]), fdec(g_mm[17]), &g_p.s_ic, &g_p.zp_ic);
    g_p.r_fc = __fdiv_rn(1.f, g_p.s_fc);
    g_p.r_ic = __fdiv_rn(1.f, g_p.s_ic);
}

// ---------- K7: minmax of fq(fc)+fq(ic) ----------
__global__ void k_pre() {
    float sAi = g_p.sA[0], zAi = g_p.zpA[0], sAf = g_p.sA[1], zAf = g_p.zpA[1];
    float sAg = g_p.sA[3], zAg = g_p.zpA[3], scc = g_p.s_c, zcc = g_p.zp_c;
    float sfc = g_p.s_fc, rfc = g_p.r_fc, zfc = g_p.zp_fc;
    float sic = g_p.s_ic, ric = g_p.r_ic, zic = g_p.zp_ic;
    float mn = 1e30f, mx = -1e30f;
    for (long i = blockIdx.x * blockDim.x + threadIdx.x; i < NE / 4;
         i += (long)gridDim.x * blockDim.x) {
        char4 qi = ((const char4*)g_act[0])[i];
        char4 qf = ((const char4*)g_act[1])[i];
        char4 qg = ((const char4*)g_act[3])[i];
        char4 qc = ((const char4*)g_cq)[i];
        int ii[4] = {qi.x, qi.y, qi.z, qi.w}, ff[4] = {qf.x, qf.y, qf.z, qf.w};
        int gg[4] = {qg.x, qg.y, qg.z, qg.w}, cc[4] = {qc.x, qc.y, qc.z, qc.w};
        #pragma unroll
        for (int j = 0; j < 4; j++) {
            float fv = __fmul_rn((float)ff[j] - zAf, sAf);
            float iv = __fmul_rn((float)ii[j] - zAi, sAi);
            float gv = __fmul_rn((float)gg[j] - zAg, sAg);
            float cd = __fmul_rn((float)cc[j] - zcc, scc);
            float fcv = fqvm(__fmul_rn(fv, cd), sfc, rfc, zfc);
            float icv = fqvm(__fmul_rn(iv, gv), sic, ric, zic);
            float pre = __fadd_rn(fcv, icv);
            mn = fminf(mn, pre); mx = fmaxf(mx, pre);
        }
    }
    block_minmax(mn, mx, &g_mm[18], &g_mm[19]);
}

// ---------- K8 ----------
__global__ void k_p4() {
    float mn = fdec(g_mm[18]), mx = fdec(g_mm[19]);
    mkparams(mn, mx, &g_p.s_cn, &g_p.zp_cn);
    g_p.r_cn = __fdiv_rn(1.f, g_p.s_cn);
    float lo = htanh(fqvm(mn, g_p.s_cn, g_p.r_cn, g_p.zp_cn));
    float hi = htanh(fqvm(mx, g_p.s_cn, g_p.r_cn, g_p.zp_cn));
    mkparams(lo, hi, &g_p.s_t, &g_p.zp_t);
    g_p.r_t = __fdiv_rn(1.f, g_p.s_t);
}

// ---------- K9: write c_next, store t codes, minmax(o*t) ----------
__global__ void k_cnext(float* __restrict__ out_c) {
    float sAi = g_p.sA[0], zAi = g_p.zpA[0], sAf = g_p.sA[1], zAf = g_p.zpA[1];
    float sAo = g_p.sA[2], zAo = g_p.zpA[2], sAg = g_p.sA[3], zAg = g_p.zpA[3];
    float scc = g_p.s_c, zcc = g_p.zp_c;
    float sfc = g_p.s_fc, rfc = g_p.r_fc, zfc = g_p.zp_fc;
    float sic = g_p.s_ic, ric = g_p.r_ic, zic = g_p.zp_ic;
    float scn = g_p.s_cn, rcn = g_p.r_cn, zcn = g_p.zp_cn;
    float st = g_p.s_t, rt = g_p.r_t, zt = g_p.zp_t;
    float mn = 1e30f, mx = -1e30f;
    for (long i = blockIdx.x * blockDim.x + threadIdx.x; i < NE / 4;
         i += (long)gridDim.x * blockDim.x) {
        char4 qi = ((const char4*)g_act[0])[i];
        char4 qf = ((const char4*)g_act[1])[i];
        char4 qo = ((const char4*)g_act[2])[i];
        char4 qg = ((const char4*)g_act[3])[i];
        char4 qc = ((const char4*)g_cq)[i];
        int ii[4] = {qi.x, qi.y, qi.z, qi.w}, ff[4] = {qf.x, qf.y, qf.z, qf.w};
        int oo[4] = {qo.x, qo.y, qo.z, qo.w}, gg[4] = {qg.x, qg.y, qg.z, qg.w};
        int cc[4] = {qc.x, qc.y, qc.z, qc.w};
        float4 outc;
        float* oc = (float*)&outc;
        char4 tq4;
        int8_t* tqq = (int8_t*)&tq4;
        #pragma unroll
        for (int j = 0; j < 4; j++) {
            float fv = __fmul_rn((float)ff[j] - zAf, sAf);
            float iv = __fmul_rn((float)ii[j] - zAi, sAi);
            float gv = __fmul_rn((float)gg[j] - zAg, sAg);
            float cd = __fmul_rn((float)cc[j] - zcc, scc);
            float fcv = fqvm(__fmul_rn(fv, cd), sfc, rfc, zfc);
            float icv = fqvm(__fmul_rn(iv, gv), sic, ric, zic);
            float pre = __fadd_rn(fcv, icv);
            float cn = fqvm(pre, scn, rcn, zcn);
            oc[j] = cn;
            float tcodef = quant_qm(htanh(cn), rt, zt);
            int tcode = (int)tcodef;
            tqq[j] = (int8_t)tcode;
            float tv = __fmul_rn(tcodef - zt, st);
            float ov = __fmul_rn((float)oo[j] - zAo, sAo);
            float hp = __fmul_rn(ov, tv);
            mn = fminf(mn, hp); mx = fmaxf(mx, hp);
        }
        ((float4*)out_c)[i] = outc;
        ((char4*)g_tq)[i] = tq4;
    }
    block_minmax(mn, mx, &g_mm[20], &g_mm[21]);
}

// ---------- K10 ----------
__global__ void k_p5() {
    mkparams(fdec(g_mm[20]), fdec(g_mm[21]), &g_p.s_hn, &g_p.zp_hn);
    g_p.r_hn = __fdiv_rn(1.f, g_p.s_hn);
}

// ---------- K11: h_next ----------
__global__ void k_hnext(float* __restrict__ out_h) {
    float sAo = g_p.sA[2], zAo = g_p.zpA[2], st = g_p.s_t, zt = g_p.zp_t;
    float shn = g_p.s_hn, rhn = g_p.r_hn, zhn = g_p.zp_hn;
    for (long i = blockIdx.x * blockDim.x + threadIdx.x; i < NE / 4;
         i += (long)gridDim.x * blockDim.x) {
        char4 qo = ((const char4*)g_act[2])[i];
        char4 qt = ((const char4*)g_tq)[i];
        int oo[4] = {qo.x, qo.y, qo.z, qo.w}, tt[4] = {qt.x, qt.y, qt.z, qt.w};
        float4 outh;
        float* oh = (float*)&outh;
        #pragma unroll
        for (int j = 0; j < 4; j++) {
            float ov = __fmul_rn((float)oo[j] - zAo, sAo);
            float tv = __fmul_rn((float)tt[j] - zt, st);
            oh[j] = fqvm(__fmul_rn(ov, tv), shn, rhn, zhn);
        }
        ((float4*)out_h)[i] = outh;
    }
}

extern "C" void kernel_launch(void* const* d_in, const int* in_sizes, int n_in,
                              void* d_out, int out_size) {
    const float* x  = (const float*)d_in[0];
    const float* h  = (const float*)d_in[1];
    const float* c  = (const float*)d_in[2];
    const float* Wi = (const float*)d_in[3];
    const float* bi = (const float*)d_in[4];
    const float* Wf = (const float*)d_in[5];
    const float* bf = (const float*)d_in[6];
    const float* Wo = (const float*)d_in[7];
    const float* bo = (const float*)d_in[8];
    const float* Wc = (const float*)d_in[9];
    const float* bc = (const float*)d_in[10];
    float* out_h = (float*)d_out;
    float* out_c = (float*)d_out + NE;

    static int attr_done = 0;
    if (!attr_done) {
        cudaFuncSetAttribute(k_gemmA, cudaFuncAttributeMaxDynamicSharedMemorySize, DYN_A);
        cudaFuncSetAttribute(k_gemmB, cudaFuncAttributeMaxDynamicSharedMemorySize, DYN_B);
        attr_done = 1;
    }

    k_init<<<1, 32>>>();
    k_minmax3<<<2048, 256>>>(x, h, c);
    k_params<<<1, 256>>>(Wi, bi, Wf, bf, Wo, bo, Wc, bc);
    k_gemmA<<<2048, 256, DYN_A>>>(x, h, c);
    k_p2<<<1, 256>>>();
    k_gemmB<<<2048, 256, DYN_B>>>();
    k_p3<<<1, 1>>>();
    k_pre<<<8192, 256>>>();
    k_p4<<<1, 1>>>();
    k_cnext<<<8192, 256>>>(out_c);
    k_p5<<<1, 1>>>();
    k_hnext<<<8192, 256>>>(out_h);
}

// round 11
// speedup vs baseline: 7.5282x; 1.1349x over previous
#include <cuda_runtime.h>
#include <stdint.h>

#define R_TOT 524288
#define NE    33554432
#define ONEB  0x01010101
#define FMG   12582912.0f

struct Params {
    float s_x, zp_x, s_h, zp_h, s_c, zp_c, s_cat, zp_cat;
    float r_x, r_h, r_c, r_cat;
    float alpha[4];
    float bdq[256];
    int   zpw_i[4], zpc_i;
    float sG[4], zpG[4], sA[4], zpA[4];
    float rG[4], rA[4];
    float c1G[4], c2G[4];
    float s_fc, zp_fc, s_ic, zp_ic, s_cn, zp_cn, s_t, zp_t, s_hn, zp_hn;
    float r_fc, r_ic, r_cn, r_t, r_hn;
};

__device__ Params   g_p;
__device__ unsigned g_mm[22];
__device__ int8_t   g_wq[256 * 128];
__device__ int      g_const[256];
__device__ float    g_G[134217728];      // gate pre-activations [row][256] (512 MB)
__device__ int8_t   g_act[4][NE];
__device__ int8_t   g_cq[NE];
__device__ int8_t   g_tq[NE];

// ---------- helpers ----------
__device__ __forceinline__ unsigned fenc(float f) {
    unsigned u = __float_as_uint(f);
    return (u & 0x80000000u) ? ~u : (u | 0x80000000u);
}
__device__ __forceinline__ float fdec(unsigned u) {
    return __uint_as_float((u & 0x80000000u) ? (u & 0x7fffffffu) : ~u);
}
__device__ __forceinline__ float clip128(float x) { return fminf(fmaxf(x, -128.f), 127.f); }
__device__ __forceinline__ float quant_qm(float v, float rs, float zp) {
    float x = clip128(__fmaf_rn(v, rs, zp));
    return __fadd_rn(__fadd_rn(x, FMG), -FMG);
}
__device__ __forceinline__ uint32_t quant_qb(float v, float rs, float zp) {
    float x = clip128(__fmaf_rn(v, rs, zp));
    return __float_as_uint(__fadd_rn(x, FMG));
}
__device__ __forceinline__ float fqvm(float v, float s, float rs, float zp) {
    return __fmul_rn(quant_qm(v, rs, zp) - zp, s);
}
__device__ __forceinline__ void mkparams(float mnr, float mxr, float* s, float* zp) {
    float mn = fminf(mnr, 0.f), mx = fmaxf(mxr, 0.f);
    float sc = fmaxf(__fdiv_rn(mx - mn, 255.f), 1e-8f);
    float z  = rintf(-128.f - __fdiv_rn(mn, sc));
    *s = sc; *zp = fminf(fmaxf(z, -128.f), 127.f);
}
#define HSIG_C 0.16666667f
__device__ __forceinline__ float hsig(float v) {
    return fminf(fmaxf(__fadd_rn(__fmul_rn(v, HSIG_C), 0.5f), 0.f), 1.f);
}
__device__ __forceinline__ float htanh(float v) { return fminf(fmaxf(v, -1.f), 1.f); }

__device__ __forceinline__ void block_minmax(float mn, float mx, unsigned* gmin, unsigned* gmax) {
    #pragma unroll
    for (int o = 16; o; o >>= 1) {
        mn = fminf(mn, __shfl_xor_sync(0xffffffffu, mn, o));
        mx = fmaxf(mx, __shfl_xor_sync(0xffffffffu, mx, o));
    }
    __shared__ float smn[8], smx[8];
    int w = threadIdx.x >> 5, nw = blockDim.x >> 5;
    __syncthreads();
    if ((threadIdx.x & 31) == 0) { smn[w] = mn; smx[w] = mx; }
    __syncthreads();
    if (threadIdx.x == 0) {
        for (int i = 1; i < nw; i++) { mn = fminf(mn, smn[i]); mx = fmaxf(mx, smx[i]); }
        atomicMin(gmin, fenc(mn)); atomicMax(gmax, fenc(mx));
    }
    __syncthreads();
}
__device__ __forceinline__ float2 block_reduce_pair(float mn, float mx) {
    #pragma unroll
    for (int o = 16; o; o >>= 1) {
        mn = fminf(mn, __shfl_xor_sync(0xffffffffu, mn, o));
        mx = fmaxf(mx, __shfl_xor_sync(0xffffffffu, mx, o));
    }
    __shared__ float smn[8], smx[8];
    __shared__ float2 res;
    int w = threadIdx.x >> 5, nw = blockDim.x >> 5;
    __syncthreads();
    if ((threadIdx.x & 31) == 0) { smn[w] = mn; smx[w] = mx; }
    __syncthreads();
    if (threadIdx.x == 0) {
        for (int i = 1; i < nw; i++) { mn = fminf(mn, smn[i]); mx = fmaxf(mx, smx[i]); }
        res = make_float2(mn, mx);
    }
    __syncthreads();
    return res;
}

__device__ __forceinline__ void mma_s8(int* c, uint32_t a0, uint32_t a1, uint32_t a2,
                                       uint32_t a3, uint32_t b0, uint32_t b1) {
    asm volatile(
        "mma.sync.aligned.m16n8k32.row.col.s32.s8.s8.s32 "
        "{%0,%1,%2,%3}, {%4,%5,%6,%7}, {%8,%9}, {%0,%1,%2,%3};\n"
        : "+r"(c[0]), "+r"(c[1]), "+r"(c[2]), "+r"(c[3])
        : "r"(a0), "r"(a1), "r"(a2), "r"(a3), "r"(b0), "r"(b1));
}
__device__ __forceinline__ void ldsm_x4(uint32_t& r0, uint32_t& r1, uint32_t& r2,
                                        uint32_t& r3, uint32_t addr) {
    asm volatile("ldmatrix.sync.aligned.m8n8.x4.shared.b16 {%0,%1,%2,%3}, [%4];"
                 : "=r"(r0), "=r"(r1), "=r"(r2), "=r"(r3) : "r"(addr));
}
__device__ __forceinline__ void ldsm_x2(uint32_t& r0, uint32_t& r1, uint32_t addr) {
    asm volatile("ldmatrix.sync.aligned.m8n8.x2.shared.b16 {%0,%1}, [%2];"
                 : "=r"(r0), "=r"(r1) : "r"(addr));
}

// ---------- K0 ----------
__global__ void k_init() {
    int t = threadIdx.x;
    if (t < 11) { g_mm[2 * t] = fenc(1e30f); g_mm[2 * t + 1] = fenc(-1e30f); }
}

// ---------- K1 ----------
__global__ void k_minmax3(const float* __restrict__ x, const float* __restrict__ h,
                          const float* __restrict__ c) {
    const float* arrs[3] = {x, h, c};
    for (int a = 0; a < 3; a++) {
        float mn = 1e30f, mx = -1e30f;
        const float4* p = (const float4*)arrs[a];
        for (long i = blockIdx.x * blockDim.x + threadIdx.x; i < NE / 4;
             i += (long)gridDim.x * blockDim.x) {
            float4 v = p[i];
            mn = fminf(fminf(fminf(mn, v.x), v.y), fminf(v.z, v.w));
            mx = fmaxf(fmaxf(fmaxf(mx, v.x), v.y), fmaxf(v.z, v.w));
        }
        block_minmax(mn, mx, &g_mm[2 * a], &g_mm[2 * a + 1]);
    }
}

// ---------- K2 ----------
__global__ void k_params(const float* __restrict__ Wi, const float* __restrict__ bi,
                         const float* __restrict__ Wf, const float* __restrict__ bf,
                         const float* __restrict__ Wo, const float* __restrict__ bo,
                         const float* __restrict__ Wc, const float* __restrict__ bc) {
    __shared__ float sw, zw, rw, sb, zb, rb_;
    int t = threadIdx.x;
    if (t == 0) {
        mkparams(fdec(g_mm[0]), fdec(g_mm[1]), &g_p.s_x, &g_p.zp_x);
        mkparams(fdec(g_mm[2]), fdec(g_mm[3]), &g_p.s_h, &g_p.zp_h);
        mkparams(fdec(g_mm[4]), fdec(g_mm[5]), &g_p.s_c, &g_p.zp_c);
        g_p.r_x = __fdiv_rn(1.f, g_p.s_x);
        g_p.r_h = __fdiv_rn(1.f, g_p.s_h);
        g_p.r_c = __fdiv_rn(1.f, g_p.s_c);
        float xlo = fqvm(fdec(g_mm[0]), g_p.s_x, g_p.r_x, g_p.zp_x);
        float xhi = fqvm(fdec(g_mm[1]), g_p.s_x, g_p.r_x, g_p.zp_x);
        float hlo = fqvm(fdec(g_mm[2]), g_p.s_h, g_p.r_h, g_p.zp_h);
        float hhi = fqvm(fdec(g_mm[3]), g_p.s_h, g_p.r_h, g_p.zp_h);
        mkparams(fminf(xlo, hlo), fmaxf(xhi, hhi), &g_p.s_cat, &g_p.zp_cat);
        g_p.r_cat = __fdiv_rn(1.f, g_p.s_cat);
        g_p.zpc_i = (int)g_p.zp_cat;
    }
    __syncthreads();
    const float* Wg[4] = {Wi, Wf, Wo, Wc};
    const float* bg[4] = {bi, bf, bo, bc};
    for (int g = 0; g < 4; g++) {
        float mn = 1e30f, mx = -1e30f;
        for (int i = t; i < 8192; i += 256) {
            float v = Wg[g][i];
            mn = fminf(mn, v); mx = fmaxf(mx, v);
        }
        float2 m = block_reduce_pair(mn, mx);
        if (t == 0) {
            mkparams(m.x, m.y, &sw, &zw);
            rw = __fdiv_rn(1.f, sw);
            g_p.alpha[g] = __fmul_rn(g_p.s_cat, sw);
            g_p.zpw_i[g] = (int)zw;
        }
        __syncthreads();
        for (int i = t; i < 8192; i += 256)
            g_wq[g * 8192 + i] = (int8_t)(int)quant_qm(Wg[g][i], rw, zw);
        mn = (t < 64) ? bg[g][t] : 1e30f;
        mx = (t < 64) ? bg[g][t] : -1e30f;
        m = block_reduce_pair(mn, mx);
        if (t == 0) { mkparams(m.x, m.y, &sb, &zb); rb_ = __fdiv_rn(1.f, sb); }
        __syncthreads();
        if (t < 64) g_p.bdq[g * 64 + t] = fqvm(bg[g][t], sb, rb_, zb);
        __syncthreads();
    }
    {
        int s = 0;
        const int8_t* wr = &g_wq[t * 128];
        for (int k = 0; k < 128; k++) s += wr[k];
        int g = t >> 6;
        g_const[t] = -g_p.zpc_i * s + 128 * g_p.zpc_i * g_p.zpw_i[g];
    }
}

#define W_BYTES   36864
#define W_STRB    144
#define CODE_STRW 36
#define DYN_A     (W_BYTES + 128 * CODE_STRW * 4)

// ---------- K3: single GEMM pass — quantize cat + c, IMMA, G store, gate minmax ----------
__global__ void __launch_bounds__(256) k_gemmA(const float* __restrict__ X,
                                               const float* __restrict__ H,
                                               const float* __restrict__ Cp) {
    extern __shared__ uint8_t dyn[];
    uint32_t* codes = (uint32_t*)(dyn + W_BYTES);
    __shared__ int   cosm[256];
    __shared__ float bosm[256];
    __shared__ float alsm[4];
    __shared__ int   zwsm[4];
    int t = threadIdx.x, lane = t & 31, w = t >> 5;

    {
        const uint4* wsrc = (const uint4*)&g_wq[t * 128];
        uint4* wdst = (uint4*)(dyn + t * W_STRB);
        #pragma unroll
        for (int i = 0; i < 8; i++) wdst[i] = wsrc[i];
    }
    cosm[t] = g_const[t];
    bosm[t] = g_p.bdq[t];
    if (t < 4) { alsm[t] = g_p.alpha[t]; zwsm[t] = g_p.zpw_i[t]; }

    float sx = g_p.s_x, rx = g_p.r_x, zx = g_p.zp_x;
    float sh = g_p.s_h, rh = g_p.r_h, zh = g_p.zp_h;
    float nzx = -__fmul_rn(zx, sx), nzh = -__fmul_rn(zh, sh);
    float rc = g_p.r_cat, zc = g_p.zp_cat;
    float rcc = g_p.r_c, zcc = g_p.zp_c;
    const float4* X4 = (const float4*)X;
    const float4* H4 = (const float4*)H;
    const float4* C4 = (const float4*)Cp;

    uint32_t Waddr = (uint32_t)__cvta_generic_to_shared(dyn);
    uint32_t Caddr = (uint32_t)__cvta_generic_to_shared(codes);
    uint32_t ldB_base = Waddr + (lane & 7) * W_STRB + ((lane >> 3) & 1) * 16;
    uint32_t ldA_base = Caddr + (w * 16 + (lane & 15)) * 144 + (lane >> 4) * 16;
    int rlo = w * 16 + (lane >> 2);

    float mnG[4], mxG[4];
    #pragma unroll
    for (int g = 0; g < 4; g++) { mnG[g] = 1e30f; mxG[g] = -1e30f; }
    __syncthreads();

    for (int tile = blockIdx.x; tile < R_TOT / 128; tile += gridDim.x) {
        long r0 = (long)tile * 128;
        #pragma unroll
        for (int i = 0; i < 8; i++) {
            int idx = t + i * 256;
            float4 v = C4[r0 * 16 + idx];
            uint32_t b0 = quant_qb(v.x, rcc, zcc);
            uint32_t b1 = quant_qb(v.y, rcc, zcc);
            uint32_t b2 = quant_qb(v.z, rcc, zcc);
            uint32_t b3 = quant_qb(v.w, rcc, zcc);
            ((uint32_t*)g_cq)[r0 * 16 + idx] =
                __byte_perm(__byte_perm(b0, b1, 0x0040),
                            __byte_perm(b2, b3, 0x0040), 0x5410);
        }
        #pragma unroll 4
        for (int rr = 0; rr < 16; rr++) {
            int lrow = w * 16 + rr;
            long row = r0 + lrow;
            float4 v = (lane < 16) ? X4[row * 16 + lane] : H4[row * 16 + lane - 16];
            float s0 = (lane < 16) ? sx : sh;
            float r0s = (lane < 16) ? rx : rh;
            float z0 = (lane < 16) ? zx : zh;
            float nz0 = (lane < 16) ? nzx : nzh;
            float c0 = quant_qm(v.x, r0s, z0), c1 = quant_qm(v.y, r0s, z0);
            float c2 = quant_qm(v.z, r0s, z0), c3 = quant_qm(v.w, r0s, z0);
            uint32_t b0 = quant_qb(__fmaf_rn(c0, s0, nz0), rc, zc);
            uint32_t b1 = quant_qb(__fmaf_rn(c1, s0, nz0), rc, zc);
            uint32_t b2 = quant_qb(__fmaf_rn(c2, s0, nz0), rc, zc);
            uint32_t b3 = quant_qb(__fmaf_rn(c3, s0, nz0), rc, zc);
            codes[lrow * CODE_STRW + lane] =
                __byte_perm(__byte_perm(b0, b1, 0x0040),
                            __byte_perm(b2, b3, 0x0040), 0x5410);
        }
        __syncthreads();
        if (t < 128) {
            const uint32_t* cr = &codes[t * CODE_STRW];
            int sum = 0;
            #pragma unroll
            for (int k = 0; k < 32; k++) sum = __dp4a((int)cr[k], ONEB, sum);
            codes[t * CODE_STRW + 32] = (uint32_t)sum;
        }
        __syncthreads();

        uint32_t a[16];
        #pragma unroll
        for (int kc = 0; kc < 4; kc++)
            ldsm_x4(a[kc * 4], a[kc * 4 + 1], a[kc * 4 + 2], a[kc * 4 + 3],
                    ldA_base + kc * 32);
        int rs_lo = (int)codes[rlo * CODE_STRW + 32];
        int rs_hi = (int)codes[(rlo + 8) * CODE_STRW + 32];
        long growL = (r0 + rlo) * 256, growH = (r0 + rlo + 8) * 256;

        #pragma unroll
        for (int g = 0; g < 4; g++) {
            float al = alsm[g];
            int   zwrs_lo = zwsm[g] * rs_lo, zwrs_hi = zwsm[g] * rs_hi;
            float mn = 1e30f, mx = -1e30f;
            #pragma unroll 4
            for (int ntg = 0; ntg < 8; ntg++) {
                int nt = g * 8 + ntg;
                int C[4] = {0, 0, 0, 0};
                #pragma unroll
                for (int kc = 0; kc < 4; kc++) {
                    uint32_t b0, b1;
                    ldsm_x2(b0, b1, ldB_base + nt * (8 * W_STRB) + kc * 32);
                    mma_s8(C, a[kc * 4], a[kc * 4 + 1], a[kc * 4 + 2], a[kc * 4 + 3],
                           b0, b1);
                }
                int col0 = nt * 8 + 2 * (lane & 3);
                int co0 = cosm[col0], co1 = cosm[col0 + 1];
                float bo0 = bosm[col0], bo1 = bosm[col0 + 1];
                float G0 = __fmaf_rn(__int2float_rn(C[0] + co0 - zwrs_lo), al, bo0);
                float G1 = __fmaf_rn(__int2float_rn(C[1] + co1 - zwrs_lo), al, bo1);
                float G2 = __fmaf_rn(__int2float_rn(C[2] + co0 - zwrs_hi), al, bo0);
                float G3 = __fmaf_rn(__int2float_rn(C[3] + co1 - zwrs_hi), al, bo1);
                *(float2*)&g_G[growL + col0] = make_float2(G0, G1);
                *(float2*)&g_G[growH + col0] = make_float2(G2, G3);
                mn = fminf(mn, fminf(fminf(G0, G1), fminf(G2, G3)));
                mx = fmaxf(mx, fmaxf(fmaxf(G0, G1), fmaxf(G2, G3)));
            }
            mnG[g] = fminf(mnG[g], mn);
            mxG[g] = fmaxf(mxG[g], mx);
        }
        __syncthreads();
    }
    #pragma unroll
    for (int g = 0; g < 4; g++) {
        float mn = mnG[g], mx = mxG[g];
        #pragma unroll
        for (int o = 16; o; o >>= 1) {
            mn = fminf(mn, __shfl_xor_sync(0xffffffffu, mn, o));
            mx = fmaxf(mx, __shfl_xor_sync(0xffffffffu, mx, o));
        }
        if (lane == 0) {
            atomicMin(&g_mm[6 + 2 * g], fenc(mn));
            atomicMax(&g_mm[7 + 2 * g], fenc(mx));
        }
    }
}

// ---------- K4: gate + activation params ----------
__global__ void k_p2() {
    if (threadIdx.x == 0) {
        for (int g = 0; g < 4; g++) {
            float mn = fdec(g_mm[6 + 2 * g]), mx = fdec(g_mm[7 + 2 * g]);
            mkparams(mn, mx, &g_p.sG[g], &g_p.zpG[g]);
            g_p.rG[g] = __fdiv_rn(1.f, g_p.sG[g]);
            float lo = fqvm(mn, g_p.sG[g], g_p.rG[g], g_p.zpG[g]);
            float hi = fqvm(mx, g_p.sG[g], g_p.rG[g], g_p.zpG[g]);
            float amin, amax;
            if (g < 3) { amin = hsig(lo); amax = hsig(hi); }
            else       { amin = htanh(lo); amax = htanh(hi); }
            mkparams(amin, amax, &g_p.sA[g], &g_p.zpA[g]);
            g_p.rA[g] = __fdiv_rn(1.f, g_p.sA[g]);
            if (g < 3) {
                g_p.c1G[g] = __fmul_rn(g_p.sG[g], HSIG_C);
                g_p.c2G[g] = __fadd_rn(0.5f, -__fmul_rn(g_p.zpG[g], g_p.c1G[g]));
            } else {
                g_p.c1G[g] = g_p.sG[g];
                g_p.c2G[g] = -__fmul_rn(g_p.zpG[g], g_p.sG[g]);
            }
        }
    }
}

// ---------- K5: activations from stored G; fc/ic minmax ----------
__global__ void k_act() {
    float rG[4], zG[4], c1[4], c2[4], rA[4], zA[4], sA[4], zAv[4];
    #pragma unroll
    for (int g = 0; g < 4; g++) {
        rG[g] = g_p.rG[g]; zG[g] = g_p.zpG[g];
        c1[g] = g_p.c1G[g]; c2[g] = g_p.c2G[g];
        rA[g] = g_p.rA[g]; zA[g] = g_p.zpA[g];
        sA[g] = g_p.sA[g]; zAv[g] = g_p.zpA[g];
    }
    float scc = g_p.s_c, zcc = g_p.zp_c;
    float mn1 = 1e30f, mx1 = -1e30f, mn2 = 1e30f, mx2 = -1e30f;
    for (long i = blockIdx.x * blockDim.x + threadIdx.x; i < NE / 4;
         i += (long)gridDim.x * blockDim.x) {
        long row = i >> 4;
        int h0 = (int)(i & 15) * 4;
        char4 qc = ((const char4*)g_cq)[i];
        int ccode[4] = {qc.x, qc.y, qc.z, qc.w};
        float acode[4][4];
        #pragma unroll
        for (int g = 0; g < 4; g++) {
            float4 G4 = *(const float4*)&g_G[row * 256 + g * 64 + h0];
            float gv[4] = {G4.x, G4.y, G4.z, G4.w};
            float aLo = (g == 3) ? -1.f : 0.f;
            uint32_t q[4];
            #pragma unroll
            for (int j = 0; j < 4; j++) {
                float cf = quant_qm(gv[j], rG[g], zG[g]);
                float a = fminf(fmaxf(__fmaf_rn(cf, c1[g], c2[g]), aLo), 1.f);
                float code = quant_qm(a, rA[g], zA[g]);
                acode[g][j] = code;
                q[j] = __float_as_uint(__fadd_rn(code, FMG));
            }
            ((uint32_t*)g_act[g])[i] =
                __byte_perm(__byte_perm(q[0], q[1], 0x0040),
                            __byte_perm(q[2], q[3], 0x0040), 0x5410);
        }
        #pragma unroll
        for (int j = 0; j < 4; j++) {
            float fv = __fmul_rn(acode[1][j] - zAv[1], sA[1]);
            float iv = __fmul_rn(acode[0][j] - zAv[0], sA[0]);
            float gv = __fmul_rn(acode[3][j] - zAv[3], sA[3]);
            float cd = __fmul_rn((float)ccode[j] - zcc, scc);
            float fc = __fmul_rn(fv, cd);
            float ic = __fmul_rn(iv, gv);
            mn1 = fminf(mn1, fc); mx1 = fmaxf(mx1, fc);
            mn2 = fminf(mn2, ic); mx2 = fmaxf(mx2, ic);
        }
    }
    block_minmax(mn1, mx1, &g_mm[14], &g_mm[15]);
    block_minmax(mn2, mx2, &g_mm[16], &g_mm[17]);
}

// ---------- K6 ----------
__global__ void k_p3() {
    mkparams(fdec(g_mm[14]), fdec(g_mm[15]), &g_p.s_fc, &g_p.zp_fc);
    mkparams(fdec(g_mm[16]), fdec(g_mm[17]), &g_p.s_ic, &g_p.zp_ic);
    g_p.r_fc = __fdiv_rn(1.f, g_p.s_fc);
    g_p.r_ic = __fdiv_rn(1.f, g_p.s_ic);
}

// ---------- K7 ----------
__global__ void k_pre() {
    float sAi = g_p.sA[0], zAi = g_p.zpA[0], sAf = g_p.sA[1], zAf = g_p.zpA[1];
    float sAg = g_p.sA[3], zAg = g_p.zpA[3], scc = g_p.s_c, zcc = g_p.zp_c;
    float sfc = g_p.s_fc, rfc = g_p.r_fc, zfc = g_p.zp_fc;
    float sic = g_p.s_ic, ric = g_p.r_ic, zic = g_p.zp_ic;
    float mn = 1e30f, mx = -1e30f;
    for (long i = blockIdx.x * blockDim.x + threadIdx.x; i < NE / 4;
         i += (long)gridDim.x * blockDim.x) {
        char4 qi = ((const char4*)g_act[0])[i];
        char4 qf = ((const char4*)g_act[1])[i];
        char4 qg = ((const char4*)g_act[3])[i];
        char4 qc = ((const char4*)g_cq)[i];
        int ii[4] = {qi.x, qi.y, qi.z, qi.w}, ff[4] = {qf.x, qf.y, qf.z, qf.w};
        int gg[4] = {qg.x, qg.y, qg.z, qg.w}, cc[4] = {qc.x, qc.y, qc.z, qc.w};
        #pragma unroll
        for (int j = 0; j < 4; j++) {
            float fv = __fmul_rn((float)ff[j] - zAf, sAf);
            float iv = __fmul_rn((float)ii[j] - zAi, sAi);
            float gv = __fmul_rn((float)gg[j] - zAg, sAg);
            float cd = __fmul_rn((float)cc[j] - zcc, scc);
            float fcv = fqvm(__fmul_rn(fv, cd), sfc, rfc, zfc);
            float icv = fqvm(__fmul_rn(iv, gv), sic, ric, zic);
            float pre = __fadd_rn(fcv, icv);
            mn = fminf(mn, pre); mx = fmaxf(mx, pre);
        }
    }
    block_minmax(mn, mx, &g_mm[18], &g_mm[19]);
}

// ---------- K8 ----------
__global__ void k_p4() {
    float mn = fdec(g_mm[18]), mx = fdec(g_mm[19]);
    mkparams(mn, mx, &g_p.s_cn, &g_p.zp_cn);
    g_p.r_cn = __fdiv_rn(1.f, g_p.s_cn);
    float lo = htanh(fqvm(mn, g_p.s_cn, g_p.r_cn, g_p.zp_cn));
    float hi = htanh(fqvm(mx, g_p.s_cn, g_p.r_cn, g_p.zp_cn));
    mkparams(lo, hi, &g_p.s_t, &g_p.zp_t);
    g_p.r_t = __fdiv_rn(1.f, g_p.s_t);
}

// ---------- K9 ----------
__global__ void k_cnext(float* __restrict__ out_c) {
    float sAi = g_p.sA[0], zAi = g_p.zpA[0], sAf = g_p.sA[1], zAf = g_p.zpA[1];
    float sAo = g_p.sA[2], zAo = g_p.zpA[2], sAg = g_p.sA[3], zAg = g_p.zpA[3];
    float scc = g_p.s_c, zcc = g_p.zp_c;
    float sfc = g_p.s_fc, rfc = g_p.r_fc, zfc = g_p.zp_fc;
    float sic = g_p.s_ic, ric = g_p.r_ic, zic = g_p.zp_ic;
    float scn = g_p.s_cn, rcn = g_p.r_cn, zcn = g_p.zp_cn;
    float st = g_p.s_t, rt = g_p.r_t, zt = g_p.zp_t;
    float mn = 1e30f, mx = -1e30f;
    for (long i = blockIdx.x * blockDim.x + threadIdx.x; i < NE / 4;
         i += (long)gridDim.x * blockDim.x) {
        char4 qi = ((const char4*)g_act[0])[i];
        char4 qf = ((const char4*)g_act[1])[i];
        char4 qo = ((const char4*)g_act[2])[i];
        char4 qg = ((const char4*)g_act[3])[i];
        char4 qc = ((const char4*)g_cq)[i];
        int ii[4] = {qi.x, qi.y, qi.z, qi.w}, ff[4] = {qf.x, qf.y, qf.z, qf.w};
        int oo[4] = {qo.x, qo.y, qo.z, qo.w}, gg[4] = {qg.x, qg.y, qg.z, qg.w};
        int cc[4] = {qc.x, qc.y, qc.z, qc.w};
        float4 outc;
        float* oc = (float*)&outc;
        char4 tq4;
        int8_t* tqq = (int8_t*)&tq4;
        #pragma unroll
        for (int j = 0; j < 4; j++) {
            float fv = __fmul_rn((float)ff[j] - zAf, sAf);
            float iv = __fmul_rn((float)ii[j] - zAi, sAi);
            float gv = __fmul_rn((float)gg[j] - zAg, sAg);
            float cd = __fmul_rn((float)cc[j] - zcc, scc);
            float fcv = fqvm(__fmul_rn(fv, cd), sfc, rfc, zfc);
            float icv = fqvm(__fmul_rn(iv, gv), sic, ric, zic);
            float pre = __fadd_rn(fcv, icv);
            float cn = fqvm(pre, scn, rcn, zcn);
            oc[j] = cn;
            float tcodef = quant_qm(htanh(cn), rt, zt);
            tqq[j] = (int8_t)(int)tcodef;
            float tv = __fmul_rn(tcodef - zt, st);
            float ov = __fmul_rn((float)oo[j] - zAo, sAo);
            float hp = __fmul_rn(ov, tv);
            mn = fminf(mn, hp); mx = fmaxf(mx, hp);
        }
        ((float4*)out_c)[i] = outc;
        ((char4*)g_tq)[i] = tq4;
    }
    block_minmax(mn, mx, &g_mm[20], &g_mm[21]);
}

// ---------- K10 ----------
__global__ void k_p5() {
    mkparams(fdec(g_mm[20]), fdec(g_mm[21]), &g_p.s_hn, &g_p.zp_hn);
    g_p.r_hn = __fdiv_rn(1.f, g_p.s_hn);
}

// ---------- K11 ----------
__global__ void k_hnext(float* __restrict__ out_h) {
    float sAo = g_p.sA[2], zAo = g_p.zpA[2], st = g_p.s_t, zt = g_p.zp_t;
    float shn = g_p.s_hn, rhn = g_p.r_hn, zhn = g_p.zp_hn;
    for (long i = blockIdx.x * blockDim.x + threadIdx.x; i < NE / 4;
         i += (long)gridDim.x * blockDim.x) {
        char4 qo = ((const char4*)g_act[2])[i];
        char4 qt = ((const char4*)g_tq)[i];
        int oo[4] = {qo.x, qo.y, qo.z, qo.w}, tt[4] = {qt.x, qt.y, qt.z, qt.w};
        float4 outh;
        float* oh = (float*)&outh;
        #pragma unroll
        for (int j = 0; j < 4; j++) {
            float ov = __fmul_rn((float)oo[j] - zAo, sAo);
            float tv = __fmul_rn((float)tt[j] - zt, st);
            oh[j] = fqvm(__fmul_rn(ov, tv), shn, rhn, zhn);
        }
        ((float4*)out_h)[i] = outh;
    }
}

extern "C" void kernel_launch(void* const* d_in, const int* in_sizes, int n_in,
                              void* d_out, int out_size) {
    const float* x  = (const float*)d_in[0];
    const float* h  = (const float*)d_in[1];
    const float* c  = (const float*)d_in[2];
    const float* Wi = (const float*)d_in[3];
    const float* bi = (const float*)d_in[4];
    const float* Wf = (const float*)d_in[5];
    const float* bf = (const float*)d_in[6];
    const float* Wo = (const float*)d_in[7];
    const float* bo = (const float*)d_in[8];
    const float* Wc = (const float*)d_in[9];
    const float* bc = (const float*)d_in[10];
    float* out_h = (float*)d_out;
    float* out_c = (float*)d_out + NE;

    static int attr_done = 0;
    if (!attr_done) {
        cudaFuncSetAttribute(k_gemmA, cudaFuncAttributeMaxDynamicSharedMemorySize, DYN_A);
        attr_done = 1;
    }

    k_init<<<1, 32>>>();
    k_minmax3<<<2048, 256>>>(x, h, c);
    k_params<<<1, 256>>>(Wi, bi, Wf, bf, Wo, bo, Wc, bc);
    k_gemmA<<<2048, 256, DYN_A>>>(x, h, c);
    k_p2<<<1, 32>>>();
    k_act<<<8192, 256>>>();
    k_p3<<<1, 1>>>();
    k_pre<<<8192, 256>>>();
    k_p4<<<1, 1>>>();
    k_cnext<<<8192, 256>>>(out_c);
    k_p5<<<1, 1>>>();
    k_hnext<<<8192, 256>>>(out_h);
}

// round 12
// speedup vs baseline: 7.6740x; 1.0194x over previous
#include <cuda_runtime.h>
#include <stdint.h>

#define R_TOT 524288
#define NE    33554432
#define ONEB  0x01010101
#define FMG   12582912.0f
#define EW_GRID 2368

struct Params {
    float s_x, zp_x, s_h, zp_h, s_c, zp_c, s_cat, zp_cat;
    float r_x, r_h, r_c, r_cat;
    float alpha[4];
    float bdq[256];
    int   zpw_i[4], zpc_i;
    float sG[4], zpG[4], sA[4], zpA[4];
    float rG[4], rA[4];
    float c1G[4], c2G[4];
    float s_fc, zp_fc, s_ic, zp_ic, s_cn, zp_cn, s_t, zp_t, s_hn, zp_hn;
    float r_fc, r_ic, r_cn, r_t, r_hn;
};

__device__ Params   g_p;
__device__ unsigned g_mm[22];
__device__ unsigned g_ctr[5];
__device__ int8_t   g_wq[256 * 128];
__device__ int      g_const[256];
__device__ float    g_G[134217728];      // gate pre-activations [row][256] (512 MB)
__device__ int8_t   g_act[4][NE];
__device__ int8_t   g_cq[NE];
__device__ int8_t   g_tq[NE];

// ---------- helpers ----------
__device__ __forceinline__ unsigned fenc(float f) {
    unsigned u = __float_as_uint(f);
    return (u & 0x80000000u) ? ~u : (u | 0x80000000u);
}
__device__ __forceinline__ float fdec(unsigned u) {
    return __uint_as_float((u & 0x80000000u) ? (u & 0x7fffffffu) : ~u);
}
__device__ __forceinline__ float clip128(float x) { return fminf(fmaxf(x, -128.f), 127.f); }
__device__ __forceinline__ float quant_qm(float v, float rs, float zp) {
    float x = clip128(__fmaf_rn(v, rs, zp));
    return __fadd_rn(__fadd_rn(x, FMG), -FMG);
}
__device__ __forceinline__ uint32_t quant_qb(float v, float rs, float zp) {
    float x = clip128(__fmaf_rn(v, rs, zp));
    return __float_as_uint(__fadd_rn(x, FMG));
}
__device__ __forceinline__ float fqvm(float v, float s, float rs, float zp) {
    return __fmul_rn(quant_qm(v, rs, zp) - zp, s);
}
__device__ __forceinline__ void mkparams(float mnr, float mxr, float* s, float* zp) {
    float mn = fminf(mnr, 0.f), mx = fmaxf(mxr, 0.f);
    float sc = fmaxf(__fdiv_rn(mx - mn, 255.f), 1e-8f);
    float z  = rintf(-128.f - __fdiv_rn(mn, sc));
    *s = sc; *zp = fminf(fmaxf(z, -128.f), 127.f);
}
#define HSIG_C 0.16666667f
__device__ __forceinline__ float hsig(float v) {
    return fminf(fmaxf(__fadd_rn(__fmul_rn(v, HSIG_C), 0.5f), 0.f), 1.f);
}
__device__ __forceinline__ float htanh(float v) { return fminf(fmaxf(v, -1.f), 1.f); }

__device__ __forceinline__ void block_minmax(float mn, float mx, unsigned* gmin, unsigned* gmax) {
    #pragma unroll
    for (int o = 16; o; o >>= 1) {
        mn = fminf(mn, __shfl_xor_sync(0xffffffffu, mn, o));
        mx = fmaxf(mx, __shfl_xor_sync(0xffffffffu, mx, o));
    }
    __shared__ float smn[8], smx[8];
    int w = threadIdx.x >> 5, nw = blockDim.x >> 5;
    __syncthreads();
    if ((threadIdx.x & 31) == 0) { smn[w] = mn; smx[w] = mx; }
    __syncthreads();
    if (threadIdx.x == 0) {
        for (int i = 1; i < nw; i++) { mn = fminf(mn, smn[i]); mx = fmaxf(mx, smx[i]); }
        atomicMin(gmin, fenc(mn)); atomicMax(gmax, fenc(mx));
    }
    __syncthreads();
}
__device__ __forceinline__ float2 block_reduce_pair(float mn, float mx) {
    #pragma unroll
    for (int o = 16; o; o >>= 1) {
        mn = fminf(mn, __shfl_xor_sync(0xffffffffu, mn, o));
        mx = fmaxf(mx, __shfl_xor_sync(0xffffffffu, mx, o));
    }
    __shared__ float smn[8], smx[8];
    __shared__ float2 res;
    int w = threadIdx.x >> 5, nw = blockDim.x >> 5;
    __syncthreads();
    if ((threadIdx.x & 31) == 0) { smn[w] = mn; smx[w] = mx; }
    __syncthreads();
    if (threadIdx.x == 0) {
        for (int i = 1; i < nw; i++) { mn = fminf(mn, smn[i]); mx = fmaxf(mx, smx[i]); }
        res = make_float2(mn, mx);
    }
    __syncthreads();
    return res;
}
// last-block election: returns true for every thread of the final block
__device__ __forceinline__ bool last_block(unsigned* ctr) {
    __shared__ int amLast;
    __threadfence();
    if (threadIdx.x == 0)
        amLast = (atomicAdd(ctr, 1u) == gridDim.x - 1u);
    __syncthreads();
    return amLast != 0;
}

__device__ __forceinline__ void mma_s8(int* c, uint32_t a0, uint32_t a1, uint32_t a2,
                                       uint32_t a3, uint32_t b0, uint32_t b1) {
    asm volatile(
        "mma.sync.aligned.m16n8k32.row.col.s32.s8.s8.s32 "
        "{%0,%1,%2,%3}, {%4,%5,%6,%7}, {%8,%9}, {%0,%1,%2,%3};\n"
        : "+r"(c[0]), "+r"(c[1]), "+r"(c[2]), "+r"(c[3])
        : "r"(a0), "r"(a1), "r"(a2), "r"(a3), "r"(b0), "r"(b1));
}
__device__ __forceinline__ void ldsm_x4(uint32_t& r0, uint32_t& r1, uint32_t& r2,
                                        uint32_t& r3, uint32_t addr) {
    asm volatile("ldmatrix.sync.aligned.m8n8.x4.shared.b16 {%0,%1,%2,%3}, [%4];"
                 : "=r"(r0), "=r"(r1), "=r"(r2), "=r"(r3) : "r"(addr));
}
__device__ __forceinline__ void ldsm_x2(uint32_t& r0, uint32_t& r1, uint32_t addr) {
    asm volatile("ldmatrix.sync.aligned.m8n8.x2.shared.b16 {%0,%1}, [%2];"
                 : "=r"(r0), "=r"(r1) : "r"(addr));
}

// ---------- scalar param bodies ----------
__device__ void p2_body() {
    for (int g = 0; g < 4; g++) {
        float mn = fdec(g_mm[6 + 2 * g]), mx = fdec(g_mm[7 + 2 * g]);
        mkparams(mn, mx, &g_p.sG[g], &g_p.zpG[g]);
        g_p.rG[g] = __fdiv_rn(1.f, g_p.sG[g]);
        float lo = fqvm(mn, g_p.sG[g], g_p.rG[g], g_p.zpG[g]);
        float hi = fqvm(mx, g_p.sG[g], g_p.rG[g], g_p.zpG[g]);
        float amin, amax;
        if (g < 3) { amin = hsig(lo); amax = hsig(hi); }
        else       { amin = htanh(lo); amax = htanh(hi); }
        mkparams(amin, amax, &g_p.sA[g], &g_p.zpA[g]);
        g_p.rA[g] = __fdiv_rn(1.f, g_p.sA[g]);
        if (g < 3) {
            g_p.c1G[g] = __fmul_rn(g_p.sG[g], HSIG_C);
            g_p.c2G[g] = __fadd_rn(0.5f, -__fmul_rn(g_p.zpG[g], g_p.c1G[g]));
        } else {
            g_p.c1G[g] = g_p.sG[g];
            g_p.c2G[g] = -__fmul_rn(g_p.zpG[g], g_p.sG[g]);
        }
    }
}
__device__ void p3_body() {
    mkparams(fdec(g_mm[14]), fdec(g_mm[15]), &g_p.s_fc, &g_p.zp_fc);
    mkparams(fdec(g_mm[16]), fdec(g_mm[17]), &g_p.s_ic, &g_p.zp_ic);
    g_p.r_fc = __fdiv_rn(1.f, g_p.s_fc);
    g_p.r_ic = __fdiv_rn(1.f, g_p.s_ic);
}
__device__ void p4_body() {
    float mn = fdec(g_mm[18]), mx = fdec(g_mm[19]);
    mkparams(mn, mx, &g_p.s_cn, &g_p.zp_cn);
    g_p.r_cn = __fdiv_rn(1.f, g_p.s_cn);
    float lo = htanh(fqvm(mn, g_p.s_cn, g_p.r_cn, g_p.zp_cn));
    float hi = htanh(fqvm(mx, g_p.s_cn, g_p.r_cn, g_p.zp_cn));
    mkparams(lo, hi, &g_p.s_t, &g_p.zp_t);
    g_p.r_t = __fdiv_rn(1.f, g_p.s_t);
}
__device__ void p5_body() {
    mkparams(fdec(g_mm[20]), fdec(g_mm[21]), &g_p.s_hn, &g_p.zp_hn);
    g_p.r_hn = __fdiv_rn(1.f, g_p.s_hn);
}

// ---------- K0 ----------
__global__ void k_init() {
    int t = threadIdx.x;
    if (t < 11) { g_mm[2 * t] = fenc(1e30f); g_mm[2 * t + 1] = fenc(-1e30f); }
    if (t < 5) g_ctr[t] = 0u;
}

// ---------- K1: minmax of x,h,c ; last block runs the params body ----------
__global__ void k_minmax3(const float* __restrict__ x, const float* __restrict__ h,
                          const float* __restrict__ c,
                          const float* __restrict__ Wi, const float* __restrict__ bi,
                          const float* __restrict__ Wf, const float* __restrict__ bf,
                          const float* __restrict__ Wo, const float* __restrict__ bo,
                          const float* __restrict__ Wc, const float* __restrict__ bc) {
    const float* arrs[3] = {x, h, c};
    for (int a = 0; a < 3; a++) {
        float mn = 1e30f, mx = -1e30f;
        const float4* p = (const float4*)arrs[a];
        for (long i = blockIdx.x * blockDim.x + threadIdx.x; i < NE / 4;
             i += (long)gridDim.x * blockDim.x) {
            float4 v = p[i];
            mn = fminf(fminf(fminf(mn, v.x), v.y), fminf(v.z, v.w));
            mx = fmaxf(fmaxf(fmaxf(mx, v.x), v.y), fmaxf(v.z, v.w));
        }
        block_minmax(mn, mx, &g_mm[2 * a], &g_mm[2 * a + 1]);
    }
    if (!last_block(&g_ctr[0])) return;
    // ----- former k_params (256 threads) -----
    __shared__ float sw, zw, rw, sb, zb, rb_;
    int t = threadIdx.x;
    if (t == 0) {
        g_ctr[0] = 0u;
        mkparams(fdec(g_mm[0]), fdec(g_mm[1]), &g_p.s_x, &g_p.zp_x);
        mkparams(fdec(g_mm[2]), fdec(g_mm[3]), &g_p.s_h, &g_p.zp_h);
        mkparams(fdec(g_mm[4]), fdec(g_mm[5]), &g_p.s_c, &g_p.zp_c);
        g_p.r_x = __fdiv_rn(1.f, g_p.s_x);
        g_p.r_h = __fdiv_rn(1.f, g_p.s_h);
        g_p.r_c = __fdiv_rn(1.f, g_p.s_c);
        float xlo = fqvm(fdec(g_mm[0]), g_p.s_x, g_p.r_x, g_p.zp_x);
        float xhi = fqvm(fdec(g_mm[1]), g_p.s_x, g_p.r_x, g_p.zp_x);
        float hlo = fqvm(fdec(g_mm[2]), g_p.s_h, g_p.r_h, g_p.zp_h);
        float hhi = fqvm(fdec(g_mm[3]), g_p.s_h, g_p.r_h, g_p.zp_h);
        mkparams(fminf(xlo, hlo), fmaxf(xhi, hhi), &g_p.s_cat, &g_p.zp_cat);
        g_p.r_cat = __fdiv_rn(1.f, g_p.s_cat);
        g_p.zpc_i = (int)g_p.zp_cat;
    }
    __syncthreads();
    const float* Wg[4] = {Wi, Wf, Wo, Wc};
    const float* bg[4] = {bi, bf, bo, bc};
    for (int g = 0; g < 4; g++) {
        float mn = 1e30f, mx = -1e30f;
        for (int i = t; i < 8192; i += 256) {
            float v = Wg[g][i];
            mn = fminf(mn, v); mx = fmaxf(mx, v);
        }
        float2 m = block_reduce_pair(mn, mx);
        if (t == 0) {
            mkparams(m.x, m.y, &sw, &zw);
            rw = __fdiv_rn(1.f, sw);
            g_p.alpha[g] = __fmul_rn(g_p.s_cat, sw);
            g_p.zpw_i[g] = (int)zw;
        }
        __syncthreads();
        for (int i = t; i < 8192; i += 256)
            g_wq[g * 8192 + i] = (int8_t)(int)quant_qm(Wg[g][i], rw, zw);
        mn = (t < 64) ? bg[g][t] : 1e30f;
        mx = (t < 64) ? bg[g][t] : -1e30f;
        m = block_reduce_pair(mn, mx);
        if (t == 0) { mkparams(m.x, m.y, &sb, &zb); rb_ = __fdiv_rn(1.f, sb); }
        __syncthreads();
        if (t < 64) g_p.bdq[g * 64 + t] = fqvm(bg[g][t], sb, rb_, zb);
        __syncthreads();
    }
    {
        int s = 0;
        const int8_t* wr = &g_wq[t * 128];
        for (int k = 0; k < 128; k++) s += wr[k];
        int g = t >> 6;
        g_const[t] = -g_p.zpc_i * s + 128 * g_p.zpc_i * g_p.zpw_i[g];
    }
}

#define W_BYTES   36864
#define W_STRB    144
#define CODE_STRW 36
#define DYN_A     (W_BYTES + 128 * CODE_STRW * 4)

// ---------- K3: single GEMM pass; last block runs p2 ----------
__global__ void __launch_bounds__(256) k_gemmA(const float* __restrict__ X,
                                               const float* __restrict__ H,
                                               const float* __restrict__ Cp) {
    extern __shared__ uint8_t dyn[];
    uint32_t* codes = (uint32_t*)(dyn + W_BYTES);
    __shared__ int   cosm[256];
    __shared__ float bosm[256];
    __shared__ float alsm[4];
    __shared__ int   zwsm[4];
    int t = threadIdx.x, lane = t & 31, w = t >> 5;

    {
        const uint4* wsrc = (const uint4*)&g_wq[t * 128];
        uint4* wdst = (uint4*)(dyn + t * W_STRB);
        #pragma unroll
        for (int i = 0; i < 8; i++) wdst[i] = wsrc[i];
    }
    cosm[t] = g_const[t];
    bosm[t] = g_p.bdq[t];
    if (t < 4) { alsm[t] = g_p.alpha[t]; zwsm[t] = g_p.zpw_i[t]; }

    float sx = g_p.s_x, rx = g_p.r_x, zx = g_p.zp_x;
    float sh = g_p.s_h, rh = g_p.r_h, zh = g_p.zp_h;
    float nzx = -__fmul_rn(zx, sx), nzh = -__fmul_rn(zh, sh);
    float rc = g_p.r_cat, zc = g_p.zp_cat;
    float rcc = g_p.r_c, zcc = g_p.zp_c;
    const float4* X4 = (const float4*)X;
    const float4* H4 = (const float4*)H;
    const float4* C4 = (const float4*)Cp;

    uint32_t Waddr = (uint32_t)__cvta_generic_to_shared(dyn);
    uint32_t Caddr = (uint32_t)__cvta_generic_to_shared(codes);
    uint32_t ldB_base = Waddr + (lane & 7) * W_STRB + ((lane >> 3) & 1) * 16;
    uint32_t ldA_base = Caddr + (w * 16 + (lane & 15)) * 144 + (lane >> 4) * 16;
    int rlo = w * 16 + (lane >> 2);

    float mnG[4], mxG[4];
    #pragma unroll
    for (int g = 0; g < 4; g++) { mnG[g] = 1e30f; mxG[g] = -1e30f; }
    __syncthreads();

    for (int tile = blockIdx.x; tile < R_TOT / 128; tile += gridDim.x) {
        long r0 = (long)tile * 128;
        #pragma unroll
        for (int i = 0; i < 8; i++) {
            int idx = t + i * 256;
            float4 v = C4[r0 * 16 + idx];
            uint32_t b0 = quant_qb(v.x, rcc, zcc);
            uint32_t b1 = quant_qb(v.y, rcc, zcc);
            uint32_t b2 = quant_qb(v.z, rcc, zcc);
            uint32_t b3 = quant_qb(v.w, rcc, zcc);
            ((uint32_t*)g_cq)[r0 * 16 + idx] =
                __byte_perm(__byte_perm(b0, b1, 0x0040),
                            __byte_perm(b2, b3, 0x0040), 0x5410);
        }
        #pragma unroll 4
        for (int rr = 0; rr < 16; rr++) {
            int lrow = w * 16 + rr;
            long row = r0 + lrow;
            float4 v = (lane < 16) ? X4[row * 16 + lane] : H4[row * 16 + lane - 16];
            float s0 = (lane < 16) ? sx : sh;
            float r0s = (lane < 16) ? rx : rh;
            float z0 = (lane < 16) ? zx : zh;
            float nz0 = (lane < 16) ? nzx : nzh;
            float c0 = quant_qm(v.x, r0s, z0), c1 = quant_qm(v.y, r0s, z0);
            float c2 = quant_qm(v.z, r0s, z0), c3 = quant_qm(v.w, r0s, z0);
            uint32_t b0 = quant_qb(__fmaf_rn(c0, s0, nz0), rc, zc);
            uint32_t b1 = quant_qb(__fmaf_rn(c1, s0, nz0), rc, zc);
            uint32_t b2 = quant_qb(__fmaf_rn(c2, s0, nz0), rc, zc);
            uint32_t b3 = quant_qb(__fmaf_rn(c3, s0, nz0), rc, zc);
            codes[lrow * CODE_STRW + lane] =
                __byte_perm(__byte_perm(b0, b1, 0x0040),
                            __byte_perm(b2, b3, 0x0040), 0x5410);
        }
        __syncthreads();
        if (t < 128) {
            const uint32_t* cr = &codes[t * CODE_STRW];
            int sum = 0;
            #pragma unroll
            for (int k = 0; k < 32; k++) sum = __dp4a((int)cr[k], ONEB, sum);
            codes[t * CODE_STRW + 32] = (uint32_t)sum;
        }
        __syncthreads();

        uint32_t a[16];
        #pragma unroll
        for (int kc = 0; kc < 4; kc++)
            ldsm_x4(a[kc * 4], a[kc * 4 + 1], a[kc * 4 + 2], a[kc * 4 + 3],
                    ldA_base + kc * 32);
        int rs_lo = (int)codes[rlo * CODE_STRW + 32];
        int rs_hi = (int)codes[(rlo + 8) * CODE_STRW + 32];
        long growL = (r0 + rlo) * 256, growH = (r0 + rlo + 8) * 256;

        #pragma unroll
        for (int g = 0; g < 4; g++) {
            float al = alsm[g];
            int   zwrs_lo = zwsm[g] * rs_lo, zwrs_hi = zwsm[g] * rs_hi;
            float mn = 1e30f, mx = -1e30f;
            #pragma unroll 4
            for (int ntg = 0; ntg < 8; ntg++) {
                int nt = g * 8 + ntg;
                int C[4] = {0, 0, 0, 0};
                #pragma unroll
                for (int kc = 0; kc < 4; kc++) {
                    uint32_t b0, b1;
                    ldsm_x2(b0, b1, ldB_base + nt * (8 * W_STRB) + kc * 32);
                    mma_s8(C, a[kc * 4], a[kc * 4 + 1], a[kc * 4 + 2], a[kc * 4 + 3],
                           b0, b1);
                }
                int col0 = nt * 8 + 2 * (lane & 3);
                int co0 = cosm[col0], co1 = cosm[col0 + 1];
                float bo0 = bosm[col0], bo1 = bosm[col0 + 1];
                float G0 = __fmaf_rn(__int2float_rn(C[0] + co0 - zwrs_lo), al, bo0);
                float G1 = __fmaf_rn(__int2float_rn(C[1] + co1 - zwrs_lo), al, bo1);
                float G2 = __fmaf_rn(__int2float_rn(C[2] + co0 - zwrs_hi), al, bo0);
                float G3 = __fmaf_rn(__int2float_rn(C[3] + co1 - zwrs_hi), al, bo1);
                *(float2*)&g_G[growL + col0] = make_float2(G0, G1);
                *(float2*)&g_G[growH + col0] = make_float2(G2, G3);
                mn = fminf(mn, fminf(fminf(G0, G1), fminf(G2, G3)));
                mx = fmaxf(mx, fmaxf(fmaxf(G0, G1), fmaxf(G2, G3)));
            }
            mnG[g] = fminf(mnG[g], mn);
            mxG[g] = fmaxf(mxG[g], mx);
        }
        __syncthreads();
    }
    #pragma unroll
    for (int g = 0; g < 4; g++) {
        float mn = mnG[g], mx = mxG[g];
        #pragma unroll
        for (int o = 16; o; o >>= 1) {
            mn = fminf(mn, __shfl_xor_sync(0xffffffffu, mn, o));
            mx = fmaxf(mx, __shfl_xor_sync(0xffffffffu, mx, o));
        }
        if (lane == 0) {
            atomicMin(&g_mm[6 + 2 * g], fenc(mn));
            atomicMax(&g_mm[7 + 2 * g], fenc(mx));
        }
    }
    if (last_block(&g_ctr[1]) && t == 0) { g_ctr[1] = 0u; p2_body(); }
}

// ---------- K5: activations from stored G; fc/ic minmax; last block runs p3 ----------
__global__ void k_act() {
    float rG[4], zG[4], c1[4], c2[4], rA[4], zA[4], sA[4];
    #pragma unroll
    for (int g = 0; g < 4; g++) {
        rG[g] = g_p.rG[g]; zG[g] = g_p.zpG[g];
        c1[g] = g_p.c1G[g]; c2[g] = g_p.c2G[g];
        rA[g] = g_p.rA[g]; zA[g] = g_p.zpA[g];
        sA[g] = g_p.sA[g];
    }
    float scc = g_p.s_c, zcc = g_p.zp_c;
    float mn1 = 1e30f, mx1 = -1e30f, mn2 = 1e30f, mx2 = -1e30f;
    for (long i = blockIdx.x * blockDim.x + threadIdx.x; i < NE / 4;
         i += (long)gridDim.x * blockDim.x) {
        long row = i >> 4;
        int h0 = (int)(i & 15) * 4;
        char4 qc = ((const char4*)g_cq)[i];
        int ccode[4] = {qc.x, qc.y, qc.z, qc.w};
        float acode[4][4];
        #pragma unroll
        for (int g = 0; g < 4; g++) {
            float4 G4 = *(const float4*)&g_G[row * 256 + g * 64 + h0];
            float gv[4] = {G4.x, G4.y, G4.z, G4.w};
            float aLo = (g == 3) ? -1.f : 0.f;
            uint32_t q[4];
            #pragma unroll
            for (int j = 0; j < 4; j++) {
                float cf = quant_qm(gv[j], rG[g], zG[g]);
                float a = fminf(fmaxf(__fmaf_rn(cf, c1[g], c2[g]), aLo), 1.f);
                float code = quant_qm(a, rA[g], zA[g]);
                acode[g][j] = code;
                q[j] = __float_as_uint(__fadd_rn(code, FMG));
            }
            ((uint32_t*)g_act[g])[i] =
                __byte_perm(__byte_perm(q[0], q[1], 0x0040),
                            __byte_perm(q[2], q[3], 0x0040), 0x5410);
        }
        #pragma unroll
        for (int j = 0; j < 4; j++) {
            float fv = __fmul_rn(acode[1][j] - zA[1], sA[1]);
            float iv = __fmul_rn(acode[0][j] - zA[0], sA[0]);
            float gv = __fmul_rn(acode[3][j] - zA[3], sA[3]);
            float cd = __fmul_rn((float)ccode[j] - zcc, scc);
            float fc = __fmul_rn(fv, cd);
            float ic = __fmul_rn(iv, gv);
            mn1 = fminf(mn1, fc); mx1 = fmaxf(mx1, fc);
            mn2 = fminf(mn2, ic); mx2 = fmaxf(mx2, ic);
        }
    }
    block_minmax(mn1, mx1, &g_mm[14], &g_mm[15]);
    block_minmax(mn2, mx2, &g_mm[16], &g_mm[17]);
    if (last_block(&g_ctr[2]) && threadIdx.x == 0) { g_ctr[2] = 0u; p3_body(); }
}

// ---------- K7: minmax of fq(fc)+fq(ic); last block runs p4 ----------
__global__ void k_pre() {
    float sAi = g_p.sA[0], zAi = g_p.zpA[0], sAf = g_p.sA[1], zAf = g_p.zpA[1];
    float sAg = g_p.sA[3], zAg = g_p.zpA[3], scc = g_p.s_c, zcc = g_p.zp_c;
    float sfc = g_p.s_fc, rfc = g_p.r_fc, zfc = g_p.zp_fc;
    float sic = g_p.s_ic, ric = g_p.r_ic, zic = g_p.zp_ic;
    float mn = 1e30f, mx = -1e30f;
    for (long i = blockIdx.x * blockDim.x + threadIdx.x; i < NE / 4;
         i += (long)gridDim.x * blockDim.x) {
        char4 qi = ((const char4*)g_act[0])[i];
        char4 qf = ((const char4*)g_act[1])[i];
        char4 qg = ((const char4*)g_act[3])[i];
        char4 qc = ((const char4*)g_cq)[i];
        int ii[4] = {qi.x, qi.y, qi.z, qi.w}, ff[4] = {qf.x, qf.y, qf.z, qf.w};
        int gg[4] = {qg.x, qg.y, qg.z, qg.w}, cc[4] = {qc.x, qc.y, qc.z, qc.w};
        #pragma unroll
        for (int j = 0; j < 4; j++) {
            float fv = __fmul_rn((float)ff[j] - zAf, sAf);
            float iv = __fmul_rn((float)ii[j] - zAi, sAi);
            float gv = __fmul_rn((float)gg[j] - zAg, sAg);
            float cd = __fmul_rn((float)cc[j] - zcc, scc);
            float fcv = fqvm(__fmul_rn(fv, cd), sfc, rfc, zfc);
            float icv = fqvm(__fmul_rn(iv, gv), sic, ric, zic);
            float pre = __fadd_rn(fcv, icv);
            mn = fminf(mn, pre); mx = fmaxf(mx, pre);
        }
    }
    block_minmax(mn, mx, &g_mm[18], &g_mm[19]);
    if (last_block(&g_ctr[3]) && threadIdx.x == 0) { g_ctr[3] = 0u; p4_body(); }
}

// ---------- K9: c_next + t codes + o*t minmax; last block runs p5 ----------
__global__ void k_cnext(float* __restrict__ out_c) {
    float sAi = g_p.sA[0], zAi = g_p.zpA[0], sAf = g_p.sA[1], zAf = g_p.zpA[1];
    float sAo = g_p.sA[2], zAo = g_p.zpA[2], sAg = g_p.sA[3], zAg = g_p.zpA[3];
    float scc = g_p.s_c, zcc = g_p.zp_c;
    float sfc = g_p.s_fc, rfc = g_p.r_fc, zfc = g_p.zp_fc;
    float sic = g_p.s_ic, ric = g_p.r_ic, zic = g_p.zp_ic;
    float scn = g_p.s_cn, rcn = g_p.r_cn, zcn = g_p.zp_cn;
    float st = g_p.s_t, rt = g_p.r_t, zt = g_p.zp_t;
    float mn = 1e30f, mx = -1e30f;
    for (long i = blockIdx.x * blockDim.x + threadIdx.x; i < NE / 4;
         i += (long)gridDim.x * blockDim.x) {
        char4 qi = ((const char4*)g_act[0])[i];
        char4 qf = ((const char4*)g_act[1])[i];
        char4 qo = ((const char4*)g_act[2])[i];
        char4 qg = ((const char4*)g_act[3])[i];
        char4 qc = ((const char4*)g_cq)[i];
        int ii[4] = {qi.x, qi.y, qi.z, qi.w}, ff[4] = {qf.x, qf.y, qf.z, qf.w};
        int oo[4] = {qo.x, qo.y, qo.z, qo.w}, gg[4] = {qg.x, qg.y, qg.z, qg.w};
        int cc[4] = {qc.x, qc.y, qc.z, qc.w};
        float4 outc;
        float* oc = (float*)&outc;
        char4 tq4;
        int8_t* tqq = (int8_t*)&tq4;
        #pragma unroll
        for (int j = 0; j < 4; j++) {
            float fv = __fmul_rn((float)ff[j] - zAf, sAf);
            float iv = __fmul_rn((float)ii[j] - zAi, sAi);
            float gv = __fmul_rn((float)gg[j] - zAg, sAg);
            float cd = __fmul_rn((float)cc[j] - zcc, scc);
            float fcv = fqvm(__fmul_rn(fv, cd), sfc, rfc, zfc);
            float icv = fqvm(__fmul_rn(iv, gv), sic, ric, zic);
            float pre = __fadd_rn(fcv, icv);
            float cn = fqvm(pre, scn, rcn, zcn);
            oc[j] = cn;
            float tcodef = quant_qm(htanh(cn), rt, zt);
            tqq[j] = (int8_t)(int)tcodef;
            float tv = __fmul_rn(tcodef - zt, st);
            float ov = __fmul_rn((float)oo[j] - zAo, sAo);
            float hp = __fmul_rn(ov, tv);
            mn = fminf(mn, hp); mx = fmaxf(mx, hp);
        }
        ((float4*)out_c)[i] = outc;
        ((char4*)g_tq)[i] = tq4;
    }
    block_minmax(mn, mx, &g_mm[20], &g_mm[21]);
    if (last_block(&g_ctr[4]) && threadIdx.x == 0) { g_ctr[4] = 0u; p5_body(); }
}

// ---------- K11 ----------
__global__ void k_hnext(float* __restrict__ out_h) {
    float sAo = g_p.sA[2], zAo = g_p.zpA[2], st = g_p.s_t, zt = g_p.zp_t;
    float shn = g_p.s_hn, rhn = g_p.r_hn, zhn = g_p.zp_hn;
    for (long i = blockIdx.x * blockDim.x + threadIdx.x; i < NE / 4;
         i += (long)gridDim.x * blockDim.x) {
        char4 qo = ((const char4*)g_act[2])[i];
        char4 qt = ((const char4*)g_tq)[i];
        int oo[4] = {qo.x, qo.y, qo.z, qo.w}, tt[4] = {qt.x, qt.y, qt.z, qt.w};
        float4 outh;
        float* oh = (float*)&outh;
        #pragma unroll
        for (int j = 0; j < 4; j++) {
            float ov = __fmul_rn((float)oo[j] - zAo, sAo);
            float tv = __fmul_rn((float)tt[j] - zt, st);
            oh[j] = fqvm(__fmul_rn(ov, tv), shn, rhn, zhn);
        }
        ((float4*)out_h)[i] = outh;
    }
}

extern "C" void kernel_launch(void* const* d_in, const int* in_sizes, int n_in,
                              void* d_out, int out_size) {
    const float* x  = (const float*)d_in[0];
    const float* h  = (const float*)d_in[1];
    const float* c  = (const float*)d_in[2];
    const float* Wi = (const float*)d_in[3];
    const float* bi = (const float*)d_in[4];
    const float* Wf = (const float*)d_in[5];
    const float* bf = (const float*)d_in[6];
    const float* Wo = (const float*)d_in[7];
    const float* bo = (const float*)d_in[8];
    const float* Wc = (const float*)d_in[9];
    const float* bc = (const float*)d_in[10];
    float* out_h = (float*)d_out;
    float* out_c = (float*)d_out + NE;

    static int attr_done = 0;
    if (!attr_done) {
        cudaFuncSetAttribute(k_gemmA, cudaFuncAttributeMaxDynamicSharedMemorySize, DYN_A);
        attr_done = 1;
    }

    k_init<<<1, 32>>>();
    k_minmax3<<<2048, 256>>>(x, h, c, Wi, bi, Wf, bf, Wo, bo, Wc, bc);
    k_gemmA<<<2048, 256, DYN_A>>>(x, h, c);
    k_act<<<EW_GRID, 256>>>();
    k_pre<<<EW_GRID, 256>>>();
    k_cnext<<<EW_GRID, 256>>>(out_c);
    k_hnext<<<EW_GRID, 256>>>(out_h);
}